// round 1
// baseline (speedup 1.0000x reference)
#include <cuda_runtime.h>
#include <math.h>

// Problem constants
#define Bn   8
#define Ln   4096
#define Cn   128
#define BL   32768            // B*L rows
#define NHn  4
#define HDn  32

// ---------------- scratch (device globals; no allocs allowed) ----------------
__device__ float d_x  [BL * Cn];     // running stream value (g / x)
__device__ float d_xw [BL * Cn];     // LN output (window layout or identity)
__device__ float d_big[BL * 512];    // qkv (384) and MLP hidden (512)
__device__ float d_att[BL * Cn];     // attention out (window layout); reused for fusion tmp A
__device__ float d_t  [BL * Cn];     // fusion tmp
__device__ float d_loc[BL * Cn];     // deform-conv output, stored (B,C,L) flat
__device__ int   d_fp [Bn * 3 * Ln];
__device__ float d_a0 [Bn * 3 * Ln];
__device__ float d_a1 [Bn * 3 * Ln];

// window-layout row m  <->  token index (b*L + ho*64 + wo), shared by partition & reverse
__device__ __forceinline__ int win_to_token(int m, int shift) {
    int n    = m & 63;
    int bw   = m >> 6;
    int widx = bw & 63;
    int b    = bw >> 6;
    int wh = widx >> 3, ww = widx & 7;
    int r = n >> 3, s = n & 7;
    int ho = (wh * 8 + r + shift) & 63;
    int wo = (ww * 8 + s + shift) & 63;
    return (b << 12) + (ho << 6) + wo;
}

// ---------------- GEMM: 128x128 tile, BK=16, 8x8 micro-tile ----------------
enum { M_PLAIN = 0, M_CONCAT, M_GELU, M_RES, M_PERMRES, M_MULRELU, M_GATE };

template <int MODE>
__global__ void __launch_bounds__(256) gemm_k(
    const float* __restrict__ A, const float* __restrict__ A2,
    const float* __restrict__ Bm, const float* __restrict__ bias,
    const float* extra, float* C,
    int M, int N, int K, int shift)
{
    __shared__ float As[16][132];
    __shared__ float Bs[16][128];
    int tid = threadIdx.x;
    int tx = tid & 15, ty = tid >> 4;
    int n0 = blockIdx.x << 7;
    int m0 = blockIdx.y << 7;

    float acc[8][8];
#pragma unroll
    for (int i = 0; i < 8; i++)
#pragma unroll
        for (int j = 0; j < 8; j++) acc[i][j] = 0.f;

    for (int k0 = 0; k0 < K; k0 += 16) {
#pragma unroll
        for (int r = 0; r < 2; r++) {
            int idx = tid + (r << 8);           // 0..511
            // A tile: 128 rows x 16 cols (store transposed)
            int m  = idx >> 2;
            int k4 = (idx & 3) << 2;
            float4 av;
            if (MODE == M_CONCAT) {
                int gk = k0 + k4;
                const float* src = (gk < 128) ? (A  + (size_t)(m0 + m) * 128 + gk)
                                              : (A2 + (size_t)(m0 + m) * 128 + gk - 128);
                av = *(const float4*)src;
            } else {
                av = *(const float4*)(A + (size_t)(m0 + m) * K + k0 + k4);
            }
            As[k4 + 0][m] = av.x; As[k4 + 1][m] = av.y;
            As[k4 + 2][m] = av.z; As[k4 + 3][m] = av.w;
            // B tile: 16 rows x 128 cols
            int kk = idx >> 5;
            int n4 = (idx & 31) << 2;
            *(float4*)&Bs[kk][n4] = *(const float4*)(Bm + (size_t)(k0 + kk) * N + n0 + n4);
        }
        __syncthreads();
#pragma unroll
        for (int kk = 0; kk < 16; kk++) {
            float4 a0v = *(const float4*)&As[kk][(ty << 3)];
            float4 a1v = *(const float4*)&As[kk][(ty << 3) + 4];
            float4 b0v = *(const float4*)&Bs[kk][(tx << 3)];
            float4 b1v = *(const float4*)&Bs[kk][(tx << 3) + 4];
            float aa[8] = {a0v.x, a0v.y, a0v.z, a0v.w, a1v.x, a1v.y, a1v.z, a1v.w};
            float bb[8] = {b0v.x, b0v.y, b0v.z, b0v.w, b1v.x, b1v.y, b1v.z, b1v.w};
#pragma unroll
            for (int i = 0; i < 8; i++)
#pragma unroll
                for (int j = 0; j < 8; j++) acc[i][j] += aa[i] * bb[j];
        }
        __syncthreads();
    }

#pragma unroll
    for (int i = 0; i < 8; i++) {
        int row = m0 + (ty << 3) + i;
        int dst = row;
        if (MODE == M_PERMRES) dst = win_to_token(row, shift);
#pragma unroll
        for (int j = 0; j < 8; j++) {
            int col = n0 + (tx << 3) + j;
            float v = acc[i][j] + bias[col];
            size_t off = (size_t)dst * N + col;
            if (MODE == M_GELU) {
                C[off] = 0.5f * v * (1.f + erff(v * 0.70710678118654752f));
            } else if (MODE == M_RES || MODE == M_PERMRES) {
                C[off] = extra[off] + v;
            } else if (MODE == M_MULRELU) {
                float t = extra[off] * v;
                C[off] = t > 0.f ? t : 0.f;
            } else if (MODE == M_GATE) {
                float gate = 1.f / (1.f + expf(-v));
                float cell = tanhf(v);
                float cy = gate * (extra[off] + cell);
                C[off] = gate * tanhf(cy);
            } else {
                C[off] = v;
            }
        }
    }
}

// ---------------- LayerNorm (warp per row) with optional window gather ----------------
__global__ void __launch_bounds__(256) ln_k(
    const float* __restrict__ x, const float* __restrict__ gamma,
    const float* __restrict__ beta, float* __restrict__ y,
    int permute, int shift)
{
    int warp = threadIdx.x >> 5, lane = threadIdx.x & 31;
    int row = (blockIdx.x << 3) + warp;
    int src = permute ? win_to_token(row, shift) : row;
    float4 v = *((const float4*)(x + (size_t)src * 128) + lane);
    float s  = v.x + v.y + v.z + v.w;
    float ss = v.x * v.x + v.y * v.y + v.z * v.z + v.w * v.w;
#pragma unroll
    for (int o = 16; o > 0; o >>= 1) {
        s  += __shfl_xor_sync(0xffffffffu, s,  o);
        ss += __shfl_xor_sync(0xffffffffu, ss, o);
    }
    float mu  = s * 0.0078125f;
    float var = ss * 0.0078125f - mu * mu;
    float rs  = rsqrtf(var + 1e-5f);
    float4 g4 = *((const float4*)gamma + lane);
    float4 b4 = *((const float4*)beta  + lane);
    float4 o4;
    o4.x = (v.x - mu) * rs * g4.x + b4.x;
    o4.y = (v.y - mu) * rs * g4.y + b4.y;
    o4.z = (v.z - mu) * rs * g4.z + b4.z;
    o4.w = (v.w - mu) * rs * g4.w + b4.w;
    *((float4*)(y + (size_t)row * 128) + lane) = o4;
}

// ---------------- Window attention: one block per (window, head) ----------------
__global__ void __launch_bounds__(256) attn_k(
    const float* __restrict__ qkv, const float* __restrict__ rp,
    float* __restrict__ out, int shift)
{
    __shared__ float qs[64][33], ks[64][33], vs[64][33];
    __shared__ float p[64][65];
    int tid = threadIdx.x;
    int bw = blockIdx.x >> 2;
    int h  = blockIdx.x & 3;
    const float SCALE = 0.17677669529663687f;   // 1/sqrt(32)
    const float* base = qkv + (size_t)bw * 64 * 384 + h * 32;

    for (int i = tid; i < 512; i += 256) {
        int n = i >> 3, d4 = (i & 7) << 2;
        float4 qv = *(const float4*)(base + n * 384 + d4);
        float4 kv = *(const float4*)(base + n * 384 + 128 + d4);
        float4 vv = *(const float4*)(base + n * 384 + 256 + d4);
        qs[n][d4] = qv.x * SCALE; qs[n][d4 + 1] = qv.y * SCALE;
        qs[n][d4 + 2] = qv.z * SCALE; qs[n][d4 + 3] = qv.w * SCALE;
        ks[n][d4] = kv.x; ks[n][d4 + 1] = kv.y; ks[n][d4 + 2] = kv.z; ks[n][d4 + 3] = kv.w;
        vs[n][d4] = vv.x; vs[n][d4 + 1] = vv.y; vs[n][d4 + 2] = vv.z; vs[n][d4 + 3] = vv.w;
    }
    __syncthreads();

    int n = tid >> 2, quad = tid & 3;
    float qreg[32];
#pragma unroll
    for (int d = 0; d < 32; d++) qreg[d] = qs[n][d];

    int r1 = n >> 3, s1 = n & 7;
    int widx = bw & 63;
    int wh = widx >> 3, ww = widx & 7;
    int h1 = wh * 8 + r1, w1 = ww * 8 + s1;
    int img1 = (h1 < 56 ? 0 : (h1 < 60 ? 1 : 2)) * 3 + (w1 < 56 ? 0 : (w1 < 60 ? 1 : 2));

    for (int mm = 0; mm < 16; mm++) {
        int m = (quad << 4) + mm;
        float s = 0.f;
#pragma unroll
        for (int d = 0; d < 32; d++) s += qreg[d] * ks[m][d];
        int r2 = m >> 3, s2 = m & 7;
        s += rp[((r1 - r2 + 7) * 15 + (s1 - s2 + 7)) * 4 + h];
        if (shift) {
            int h2 = wh * 8 + r2, w2 = ww * 8 + s2;
            int img2 = (h2 < 56 ? 0 : (h2 < 60 ? 1 : 2)) * 3 + (w2 < 56 ? 0 : (w2 < 60 ? 1 : 2));
            if (img1 != img2) s -= 100.f;
        }
        p[n][m] = s;
    }
    // quad-cooperative softmax over this thread's row (quads are lane groups within a warp)
    float mx = -1e30f;
#pragma unroll
    for (int mm = 0; mm < 16; mm++) mx = fmaxf(mx, p[n][(quad << 4) + mm]);
    mx = fmaxf(mx, __shfl_xor_sync(0xffffffffu, mx, 1));
    mx = fmaxf(mx, __shfl_xor_sync(0xffffffffu, mx, 2));
    float sum = 0.f;
#pragma unroll
    for (int mm = 0; mm < 16; mm++) {
        int m = (quad << 4) + mm;
        float e = expf(p[n][m] - mx);
        p[n][m] = e; sum += e;
    }
    sum += __shfl_xor_sync(0xffffffffu, sum, 1);
    sum += __shfl_xor_sync(0xffffffffu, sum, 2);
    float inv = 1.f / sum;
#pragma unroll
    for (int mm = 0; mm < 16; mm++) p[n][(quad << 4) + mm] *= inv;
    __syncthreads();

    float acc[8];
#pragma unroll
    for (int j = 0; j < 8; j++) acc[j] = 0.f;
    int db = quad << 3;
    for (int m = 0; m < 64; m++) {
        float pm = p[n][m];
#pragma unroll
        for (int j = 0; j < 8; j++) acc[j] += pm * vs[m][db + j];
    }
    float* op = out + ((size_t)(bw * 64 + n)) * 128 + h * 32 + db;
#pragma unroll
    for (int j = 0; j < 8; j++) op[j] = acc[j];
}

// ---------------- deformable-conv branch ----------------
__global__ void __launch_bounds__(128) offmask_k(
    const float* __restrict__ xt,
    const float* __restrict__ ow, const float* __restrict__ ob,
    const float* __restrict__ mw, const float* __restrict__ mb,
    int* __restrict__ fp, float* __restrict__ a0, float* __restrict__ a1)
{
    int idx = blockIdx.x * 128 + threadIdx.x;   // (b, k, l)
    int l = idx & 4095;
    int k = (idx >> 12) % 3;
    int b = idx / (3 * 4096);
    float off = ob[k], mk = mb[k];
#pragma unroll
    for (int j = 0; j < 3; j++) {
        int ll = l + j - 1;
        if (ll < 0 || ll >= 4096) continue;
        const float* xr  = xt + ((size_t)b * 4096 + ll) * 128;
        const float* owr = ow + k * 384 + j;    // (K,C,K): stride 3 over c
        const float* mwr = mw + k * 384 + j;
        float so = 0.f, sm = 0.f;
        for (int c = 0; c < 128; c++) {
            float xv = xr[c];
            so += xv * owr[c * 3];
            sm += xv * mwr[c * 3];
        }
        off += so; mk += sm;
    }
    float mask = 1.f / (1.f + expf(-mk));
    float pos = fminf(fmaxf((float)l + off, 0.f), 4095.f);
    float fpf = floorf(pos);
    int f = (int)fpf;
    float alpha = pos - fpf;
    fp[idx] = f;
    a0[idx] = (1.f - alpha) * mask;
    a1[idx] = alpha * mask;
}

__global__ void __launch_bounds__(128) deform_k(
    const float* __restrict__ xt, const int* __restrict__ fp,
    const float* __restrict__ a0, const float* __restrict__ a1,
    float* __restrict__ outp)
{
    int bl = blockIdx.x;                 // (b, l)
    int b = bl >> 12, l = bl & 4095;
    int c = threadIdx.x;
    float o = 0.f;
#pragma unroll
    for (int k = 0; k < 3; k++) {
        int base = (b * 3 + k) * 4096 + l;
        int f  = fp[base];
        int cp = min(f + 1, 4095);
        o += xt[((size_t)b * 4096 + f)  * 128 + c] * a0[base]
           + xt[((size_t)b * 4096 + cp) * 128 + c] * a1[base];
    }
    // torch .view: output stays in (B, C, L) memory order
    outp[(size_t)b * 524288 + (size_t)c * 4096 + l] = o;
}

// ---------------- host launcher ----------------
extern "C" void kernel_launch(void* const* d_in, const int* in_sizes, int n_in,
                              void* d_out, int out_size)
{
    const float* xt    = (const float*)d_in[0];
    const float* hx    = (const float*)d_in[1];
    const float* cx    = (const float*)d_in[2];
    const float* red_w = (const float*)d_in[3];
    const float* red_b = (const float*)d_in[4];
    const float* n1g   = (const float*)d_in[5];
    const float* n1b   = (const float*)d_in[6];
    const float* qkvw  = (const float*)d_in[7];
    const float* qkvb  = (const float*)d_in[8];
    const float* rp    = (const float*)d_in[9];
    const float* pw    = (const float*)d_in[10];
    const float* pb    = (const float*)d_in[11];
    const float* n2g   = (const float*)d_in[12];
    const float* n2b   = (const float*)d_in[13];
    const float* f1w   = (const float*)d_in[14];
    const float* f1b   = (const float*)d_in[15];
    const float* f2w   = (const float*)d_in[16];
    const float* f2b   = (const float*)d_in[17];
    const float* off_w = (const float*)d_in[18];
    const float* off_b = (const float*)d_in[19];
    const float* msk_w = (const float*)d_in[20];
    const float* msk_b = (const float*)d_in[21];
    const float* lf_w  = (const float*)d_in[22];
    const float* lf_b  = (const float*)d_in[23];
    const float* gf_w  = (const float*)d_in[24];
    const float* gf_b  = (const float*)d_in[25];
    const float* ff_w  = (const float*)d_in[26];
    const float* ff_b  = (const float*)d_in[27];

    float *px, *pxw, *pbig, *patt, *pt, *ploc, *pa0, *pa1;
    int* pfp;
    cudaGetSymbolAddress((void**)&px,   d_x);
    cudaGetSymbolAddress((void**)&pxw,  d_xw);
    cudaGetSymbolAddress((void**)&pbig, d_big);
    cudaGetSymbolAddress((void**)&patt, d_att);
    cudaGetSymbolAddress((void**)&pt,   d_t);
    cudaGetSymbolAddress((void**)&ploc, d_loc);
    cudaGetSymbolAddress((void**)&pfp,  d_fp);
    cudaGetSymbolAddress((void**)&pa0,  d_a0);
    cudaGetSymbolAddress((void**)&pa1,  d_a1);

    // local (deformable) branch — independent of global branch
    offmask_k<<<Bn * 3 * Ln / 128, 128>>>(xt, off_w, off_b, msk_w, msk_b, pfp, pa0, pa1);
    deform_k<<<BL, 128>>>(xt, pfp, pa0, pa1, ploc);

    // global branch: reduce (concat GEMM)
    gemm_k<M_CONCAT><<<dim3(1, 256), 256>>>(xt, hx, red_w, red_b, nullptr, px,
                                            BL, 128, 256, 0);

    for (int i = 0; i < 2; i++) {
        int shift = i ? 4 : 0;
        // LN1 + shift/window-partition gather
        ln_k<<<BL / 8, 256>>>(px, n1g + i * 128, n1b + i * 128, pxw, 1, shift);
        // QKV GEMM (window layout rows)
        gemm_k<M_PLAIN><<<dim3(3, 256), 256>>>(pxw, nullptr, qkvw + i * 49152,
                                               qkvb + i * 384, nullptr, pbig,
                                               BL, 384, 128, 0);
        // windowed attention + rel-pos bias + (shifted) mask + softmax
        attn_k<<<2048, 256>>>(pbig, rp + i * 900, patt, shift);
        // proj GEMM + window-reverse/roll permute + residual (in-place on d_x)
        gemm_k<M_PERMRES><<<dim3(1, 256), 256>>>(patt, nullptr, pw + i * 16384,
                                                 pb + i * 128, px, px,
                                                 BL, 128, 128, shift);
        // LN2
        ln_k<<<BL / 8, 256>>>(px, n2g + i * 128, n2b + i * 128, pxw, 0, 0);
        // MLP fc1 + exact GELU
        gemm_k<M_GELU><<<dim3(4, 256), 256>>>(pxw, nullptr, f1w + i * 65536,
                                              f1b + i * 512, nullptr, pbig,
                                              BL, 512, 128, 0);
        // MLP fc2 + residual (in-place on d_x)
        gemm_k<M_RES><<<dim3(1, 256), 256>>>(pbig, nullptr, f2w + i * 65536,
                                             f2b + i * 128, px, px,
                                             BL, 128, 512, 0);
    }

    // fusion: relu((local@lf + lf_b) * (g@gf + gf_b)) @ ff + ff_b, then LSTM gate
    gemm_k<M_PLAIN><<<dim3(1, 256), 256>>>(ploc, nullptr, lf_w, lf_b, nullptr, patt,
                                           BL, 128, 128, 0);
    gemm_k<M_MULRELU><<<dim3(1, 256), 256>>>(px, nullptr, gf_w, gf_b, patt, pt,
                                             BL, 128, 128, 0);
    gemm_k<M_GATE><<<dim3(1, 256), 256>>>(pt, nullptr, ff_w, ff_b, cx, (float*)d_out,
                                          BL, 128, 128, 0);
}

// round 3
// speedup vs baseline: 1.0463x; 1.0463x over previous
#include <cuda_runtime.h>
#include <math.h>

// Problem constants
#define Bn   8
#define Ln   4096
#define Cn   128
#define BL   32768            // B*L rows

typedef unsigned long long u64;

// ---------------- packed f32x2 helpers (sm_103a FFMA2) ----------------
__device__ __forceinline__ u64 pk2(float lo, float hi) {
    u64 r; asm("mov.b64 %0, {%1, %2};" : "=l"(r) : "f"(lo), "f"(hi)); return r;
}
__device__ __forceinline__ void fma2(u64& d, u64 a, u64 b) {
    asm("fma.rn.f32x2 %0, %1, %2, %0;" : "+l"(d) : "l"(a), "l"(b));
}
__device__ __forceinline__ float2 upk(u64 v) {
    float2 f; asm("mov.b64 {%0, %1}, %2;" : "=f"(f.x), "=f"(f.y) : "l"(v)); return f;
}

// ---------------- scratch (device globals; no allocs allowed) ----------------
__device__ float d_x  [BL * Cn];     // running stream value (g / x)
__device__ float d_xw [BL * Cn];     // LN output (window layout or identity)
__device__ float d_big[BL * 512];    // qkv (384) and MLP hidden (512)
__device__ float d_att[BL * Cn];     // attention out (window layout); fusion tmp A
__device__ float d_t  [BL * Cn];     // fusion tmp
__device__ float d_loc[BL * Cn];     // deform-conv output, stored (B,C,L) flat
__device__ int   d_fp [Bn * 3 * Ln];
__device__ float d_a0 [Bn * 3 * Ln];
__device__ float d_a1 [Bn * 3 * Ln];

// window-layout row m  <->  token index (b*L + ho*64 + wo)
__device__ __forceinline__ int win_to_token(int m, int shift) {
    int n    = m & 63;
    int bw   = m >> 6;
    int widx = bw & 63;
    int b    = bw >> 6;
    int wh = widx >> 3, ww = widx & 7;
    int r = n >> 3, s = n & 7;
    int ho = (wh * 8 + r + shift) & 63;
    int wo = (ww * 8 + s + shift) & 63;
    return (b << 12) + (ho << 6) + wo;
}

// ---------------- GEMM: 128x128 tile, BK=16, 8x8 micro-tile, f32x2, dbl-buffer ----------------
enum { M_PLAIN = 0, M_CONCAT, M_GELU, M_RES, M_PERMRES, M_MULRELU, M_GATE };

template <int MODE>
__global__ void __launch_bounds__(256, 2) gemm_k(
    const float* __restrict__ A, const float* __restrict__ A2,
    const float* __restrict__ Bm, const float* __restrict__ bias,
    const float* extra, float* C,
    int M, int N, int K, int shift)
{
    __shared__ float As[2][16][132];
    __shared__ float Bs[2][16][128];
    int tid = threadIdx.x;
    int tx = tid & 15, ty = tid >> 4;
    int n0 = blockIdx.x << 7;
    int m0 = blockIdx.y << 7;

    u64 acc[8][4];
#pragma unroll
    for (int i = 0; i < 8; i++)
#pragma unroll
        for (int j = 0; j < 4; j++) acc[i][j] = 0ull;

    // staging indices: 512 load slots over 256 threads, 2 rounds
    const int aM0 = tid >> 2;            // A row (round 0); round 1 adds 64
    const int aK  = (tid & 3) << 2;      // A k-quad
    const int bK0 = tid >> 5;            // B k row (round 0); round 1 adds 8
    const int bN  = (tid & 31) << 2;     // B col-quad

    float4 ra[2], rb[2];

    auto gload = [&](int k0) {
#pragma unroll
        for (int r = 0; r < 2; r++) {
            int m = aM0 + (r << 6);
            if (MODE == M_CONCAT) {
                int gk = k0 + aK;
                const float* src = (gk < 128) ? (A  + (size_t)(m0 + m) * 128 + gk)
                                              : (A2 + (size_t)(m0 + m) * 128 + gk - 128);
                ra[r] = *(const float4*)src;
            } else {
                ra[r] = *(const float4*)(A + (size_t)(m0 + m) * K + k0 + aK);
            }
            rb[r] = *(const float4*)(Bm + (size_t)(k0 + bK0 + (r << 3)) * N + n0 + bN);
        }
    };
    auto sstore = [&](int buf) {
#pragma unroll
        for (int r = 0; r < 2; r++) {
            int m = aM0 + (r << 6);
            As[buf][aK + 0][m] = ra[r].x;
            As[buf][aK + 1][m] = ra[r].y;
            As[buf][aK + 2][m] = ra[r].z;
            As[buf][aK + 3][m] = ra[r].w;
            *(float4*)&Bs[buf][bK0 + (r << 3)][bN] = rb[r];
        }
    };

    gload(0); sstore(0); __syncthreads();
    int nk = K >> 4;
    for (int kt = 0; kt < nk; kt++) {
        int cur = kt & 1;
        if (kt + 1 < nk) gload((kt + 1) << 4);
#pragma unroll
        for (int kk = 0; kk < 16; kk++) {
            float4 a0v = *(const float4*)&As[cur][kk][(ty << 3)];
            float4 a1v = *(const float4*)&As[cur][kk][(ty << 3) + 4];
            float4 b0v = *(const float4*)&Bs[cur][kk][(tx << 3)];
            float4 b1v = *(const float4*)&Bs[cur][kk][(tx << 3) + 4];
            u64 b2[4] = { pk2(b0v.x, b0v.y), pk2(b0v.z, b0v.w),
                          pk2(b1v.x, b1v.y), pk2(b1v.z, b1v.w) };
            float aa[8] = {a0v.x, a0v.y, a0v.z, a0v.w, a1v.x, a1v.y, a1v.z, a1v.w};
#pragma unroll
            for (int i = 0; i < 8; i++) {
                u64 a2 = pk2(aa[i], aa[i]);
#pragma unroll
                for (int j = 0; j < 4; j++) fma2(acc[i][j], a2, b2[j]);
            }
        }
        if (kt + 1 < nk) { sstore((kt + 1) & 1); __syncthreads(); }
    }

#pragma unroll
    for (int i = 0; i < 8; i++) {
        int row = m0 + (ty << 3) + i;
        int dst = (MODE == M_PERMRES) ? win_to_token(row, shift) : row;
#pragma unroll
        for (int j = 0; j < 4; j++) {
            float2 v2 = upk(acc[i][j]);
            float vv[2] = {v2.x, v2.y};
#pragma unroll
            for (int h = 0; h < 2; h++) {
                int col = n0 + (tx << 3) + (j << 1) + h;
                float v = vv[h] + bias[col];
                size_t off = (size_t)dst * N + col;
                if (MODE == M_GELU) {
                    C[off] = 0.5f * v * (1.f + erff(v * 0.70710678118654752f));
                } else if (MODE == M_RES || MODE == M_PERMRES) {
                    C[off] = extra[off] + v;
                } else if (MODE == M_MULRELU) {
                    float t = extra[off] * v;
                    C[off] = t > 0.f ? t : 0.f;
                } else if (MODE == M_GATE) {
                    float gate = 1.f / (1.f + expf(-v));
                    float cell = tanhf(v);
                    float cy = gate * (extra[off] + cell);
                    C[off] = gate * tanhf(cy);
                } else {
                    C[off] = v;
                }
            }
        }
    }
}

// ---------------- LayerNorm (warp per row) with optional window gather ----------------
__global__ void __launch_bounds__(256) ln_k(
    const float* __restrict__ x, const float* __restrict__ gamma,
    const float* __restrict__ beta, float* __restrict__ y,
    int permute, int shift)
{
    int warp = threadIdx.x >> 5, lane = threadIdx.x & 31;
    int row = (blockIdx.x << 3) + warp;
    int src = permute ? win_to_token(row, shift) : row;
    float4 v = *((const float4*)(x + (size_t)src * 128) + lane);
    float s  = v.x + v.y + v.z + v.w;
    float ss = v.x * v.x + v.y * v.y + v.z * v.z + v.w * v.w;
#pragma unroll
    for (int o = 16; o > 0; o >>= 1) {
        s  += __shfl_xor_sync(0xffffffffu, s,  o);
        ss += __shfl_xor_sync(0xffffffffu, ss, o);
    }
    float mu  = s * 0.0078125f;
    float var = ss * 0.0078125f - mu * mu;
    float rs  = rsqrtf(var + 1e-5f);
    float4 g4 = *((const float4*)gamma + lane);
    float4 b4 = *((const float4*)beta  + lane);
    float4 o4;
    o4.x = (v.x - mu) * rs * g4.x + b4.x;
    o4.y = (v.y - mu) * rs * g4.y + b4.y;
    o4.z = (v.z - mu) * rs * g4.z + b4.z;
    o4.w = (v.w - mu) * rs * g4.w + b4.w;
    *((float4*)(y + (size_t)row * 128) + lane) = o4;
}

// ---------------- Window attention: one block per (window, head) ----------------
__global__ void __launch_bounds__(256) attn_k(
    const float* __restrict__ qkv, const float* __restrict__ rp,
    float* __restrict__ out, int shift)
{
    __shared__ float qs[64][36], ks[64][36], vs[64][36];   // 16B-aligned rows
    __shared__ float p[64][65];
    int tid = threadIdx.x;
    int bw = blockIdx.x >> 2;
    int h  = blockIdx.x & 3;
    const float SCALE = 0.17677669529663687f;   // 1/sqrt(32)
    const float* base = qkv + (size_t)bw * 64 * 384 + h * 32;

    for (int i = tid; i < 512; i += 256) {
        int n = i >> 3, d4 = (i & 7) << 2;
        float4 qv = *(const float4*)(base + n * 384 + d4);
        float4 kv = *(const float4*)(base + n * 384 + 128 + d4);
        float4 vv = *(const float4*)(base + n * 384 + 256 + d4);
        qv.x *= SCALE; qv.y *= SCALE; qv.z *= SCALE; qv.w *= SCALE;
        *(float4*)&qs[n][d4] = qv;
        *(float4*)&ks[n][d4] = kv;
        *(float4*)&vs[n][d4] = vv;
    }
    __syncthreads();

    int n = tid >> 2, quad = tid & 3;
    u64 q2[16];
#pragma unroll
    for (int d4 = 0; d4 < 8; d4++) {
        float4 qv = *(const float4*)&qs[n][d4 << 2];
        q2[2 * d4]     = pk2(qv.x, qv.y);
        q2[2 * d4 + 1] = pk2(qv.z, qv.w);
    }

    int r1 = n >> 3, s1 = n & 7;
    int widx = bw & 63;
    int wh = widx >> 3, ww = widx & 7;
    int h1 = wh * 8 + r1, w1 = ww * 8 + s1;
    int img1 = (h1 < 56 ? 0 : (h1 < 60 ? 1 : 2)) * 3 + (w1 < 56 ? 0 : (w1 < 60 ? 1 : 2));

#pragma unroll 4
    for (int mm = 0; mm < 16; mm++) {
        int m = (quad << 4) + mm;
        u64 s2 = 0ull;
#pragma unroll
        for (int d4 = 0; d4 < 8; d4++) {
            float4 kv = *(const float4*)&ks[m][d4 << 2];
            fma2(s2, q2[2 * d4],     pk2(kv.x, kv.y));
            fma2(s2, q2[2 * d4 + 1], pk2(kv.z, kv.w));
        }
        float2 sv = upk(s2);
        float s = sv.x + sv.y;
        int r2 = m >> 3, s2i = m & 7;
        s += rp[((r1 - r2 + 7) * 15 + (s1 - s2i + 7)) * 4 + h];
        if (shift) {
            int h2 = wh * 8 + r2, w2 = ww * 8 + s2i;
            int img2 = (h2 < 56 ? 0 : (h2 < 60 ? 1 : 2)) * 3 + (w2 < 56 ? 0 : (w2 < 60 ? 1 : 2));
            if (img1 != img2) s -= 100.f;
        }
        p[n][m] = s;
    }
    // quad-cooperative softmax (quads = lane pairs {1,2} within warp)
    float mx = -1e30f;
#pragma unroll
    for (int mm = 0; mm < 16; mm++) mx = fmaxf(mx, p[n][(quad << 4) + mm]);
    mx = fmaxf(mx, __shfl_xor_sync(0xffffffffu, mx, 1));
    mx = fmaxf(mx, __shfl_xor_sync(0xffffffffu, mx, 2));
    float sum = 0.f;
#pragma unroll
    for (int mm = 0; mm < 16; mm++) {
        int m = (quad << 4) + mm;
        float e = expf(p[n][m] - mx);
        p[n][m] = e; sum += e;
    }
    sum += __shfl_xor_sync(0xffffffffu, sum, 1);
    sum += __shfl_xor_sync(0xffffffffu, sum, 2);
    float inv = 1.f / sum;
#pragma unroll
    for (int mm = 0; mm < 16; mm++) p[n][(quad << 4) + mm] *= inv;
    __syncthreads();

    u64 acc2[4] = {0ull, 0ull, 0ull, 0ull};
    int db = quad << 3;
#pragma unroll 8
    for (int m = 0; m < 64; m++) {
        float pm = p[n][m];
        u64 pm2 = pk2(pm, pm);
        float4 v0 = *(const float4*)&vs[m][db];
        float4 v1 = *(const float4*)&vs[m][db + 4];
        fma2(acc2[0], pm2, pk2(v0.x, v0.y));
        fma2(acc2[1], pm2, pk2(v0.z, v0.w));
        fma2(acc2[2], pm2, pk2(v1.x, v1.y));
        fma2(acc2[3], pm2, pk2(v1.z, v1.w));
    }
    float* op = out + ((size_t)(bw * 64 + n)) * 128 + h * 32 + db;
    float2 o0 = upk(acc2[0]), o1 = upk(acc2[1]), o2 = upk(acc2[2]), o3 = upk(acc2[3]);
    float4 wo0 = {o0.x, o0.y, o1.x, o1.y};
    float4 wo1 = {o2.x, o2.y, o3.x, o3.y};
    *(float4*)op = wo0;
    *(float4*)(op + 4) = wo1;
}

// ---------------- deformable-conv branch ----------------
// warp per (b, l): coalesced row loads + warp reduction
__global__ void __launch_bounds__(256) offmask_k(
    const float* __restrict__ xt,
    const float* __restrict__ ow, const float* __restrict__ ob,
    const float* __restrict__ mw, const float* __restrict__ mb,
    int* __restrict__ fp, float* __restrict__ a0, float* __restrict__ a1)
{
    int warp = threadIdx.x >> 5, lane = threadIdx.x & 31;
    int bl = blockIdx.x * 8 + warp;
    int b = bl >> 12, l = bl & 4095;
    int c0 = lane << 2;
    float so[3] = {0.f, 0.f, 0.f}, sm[3] = {0.f, 0.f, 0.f};
#pragma unroll
    for (int j = 0; j < 3; j++) {
        int ll = l + j - 1;
        if (ll < 0 || ll > 4095) continue;
        float4 xv = *((const float4*)(xt + ((size_t)b * 4096 + ll) * 128) + lane);
#pragma unroll
        for (int k = 0; k < 3; k++) {
            const float* owp = ow + k * 384 + j;   // (K,C,K): stride 3 over c
            const float* mwp = mw + k * 384 + j;
            so[k] += xv.x * owp[(c0 + 0) * 3] + xv.y * owp[(c0 + 1) * 3]
                   + xv.z * owp[(c0 + 2) * 3] + xv.w * owp[(c0 + 3) * 3];
            sm[k] += xv.x * mwp[(c0 + 0) * 3] + xv.y * mwp[(c0 + 1) * 3]
                   + xv.z * mwp[(c0 + 2) * 3] + xv.w * mwp[(c0 + 3) * 3];
        }
    }
#pragma unroll
    for (int o = 16; o > 0; o >>= 1) {
#pragma unroll
        for (int k = 0; k < 3; k++) {
            so[k] += __shfl_xor_sync(0xffffffffu, so[k], o);
            sm[k] += __shfl_xor_sync(0xffffffffu, sm[k], o);
        }
    }
    if (lane < 3) {
        int k = lane;
        float off = ob[k] + so[k];
        float mk  = mb[k] + sm[k];
        float mask = 1.f / (1.f + expf(-mk));
        float pos = fminf(fmaxf((float)l + off, 0.f), 4095.f);
        float fpf = floorf(pos);
        int f = (int)fpf;
        float alpha = pos - fpf;
        int idx = (b * 3 + k) * 4096 + l;
        fp[idx] = f;
        a0[idx] = (1.f - alpha) * mask;
        a1[idx] = alpha * mask;
    }
}

__global__ void __launch_bounds__(128) deform_k(
    const float* __restrict__ xt, const int* __restrict__ fp,
    const float* __restrict__ a0, const float* __restrict__ a1,
    float* __restrict__ outp)
{
    int bl = blockIdx.x;                 // (b, l)
    int b = bl >> 12, l = bl & 4095;
    int c = threadIdx.x;
    float o = 0.f;
#pragma unroll
    for (int k = 0; k < 3; k++) {
        int base = (b * 3 + k) * 4096 + l;
        int f  = fp[base];
        int cp = min(f + 1, 4095);
        o += xt[((size_t)b * 4096 + f)  * 128 + c] * a0[base]
           + xt[((size_t)b * 4096 + cp) * 128 + c] * a1[base];
    }
    // torch .view: output stays in (B, C, L) memory order
    outp[(size_t)b * 524288 + (size_t)c * 4096 + l] = o;
}

// ---------------- host launcher ----------------
extern "C" void kernel_launch(void* const* d_in, const int* in_sizes, int n_in,
                              void* d_out, int out_size)
{
    const float* xt    = (const float*)d_in[0];
    const float* hx    = (const float*)d_in[1];
    const float* cx    = (const float*)d_in[2];
    const float* red_w = (const float*)d_in[3];
    const float* red_b = (const float*)d_in[4];
    const float* n1g   = (const float*)d_in[5];
    const float* n1b   = (const float*)d_in[6];
    const float* qkvw  = (const float*)d_in[7];
    const float* qkvb  = (const float*)d_in[8];
    const float* rp    = (const float*)d_in[9];
    const float* pw    = (const float*)d_in[10];
    const float* pb    = (const float*)d_in[11];
    const float* n2g   = (const float*)d_in[12];
    const float* n2b   = (const float*)d_in[13];
    const float* f1w   = (const float*)d_in[14];
    const float* f1b   = (const float*)d_in[15];
    const float* f2w   = (const float*)d_in[16];
    const float* f2b   = (const float*)d_in[17];
    const float* off_w = (const float*)d_in[18];
    const float* off_b = (const float*)d_in[19];
    const float* msk_w = (const float*)d_in[20];
    const float* msk_b = (const float*)d_in[21];
    const float* lf_w  = (const float*)d_in[22];
    const float* lf_b  = (const float*)d_in[23];
    const float* gf_w  = (const float*)d_in[24];
    const float* gf_b  = (const float*)d_in[25];
    const float* ff_w  = (const float*)d_in[26];
    const float* ff_b  = (const float*)d_in[27];

    float *px, *pxw, *pbig, *patt, *pt, *ploc, *pa0, *pa1;
    int* pfp;
    cudaGetSymbolAddress((void**)&px,   d_x);
    cudaGetSymbolAddress((void**)&pxw,  d_xw);
    cudaGetSymbolAddress((void**)&pbig, d_big);
    cudaGetSymbolAddress((void**)&patt, d_att);
    cudaGetSymbolAddress((void**)&pt,   d_t);
    cudaGetSymbolAddress((void**)&ploc, d_loc);
    cudaGetSymbolAddress((void**)&pfp,  d_fp);
    cudaGetSymbolAddress((void**)&pa0,  d_a0);
    cudaGetSymbolAddress((void**)&pa1,  d_a1);

    // local (deformable) branch — independent of global branch
    offmask_k<<<Bn * Ln / 8, 256>>>(xt, off_w, off_b, msk_w, msk_b, pfp, pa0, pa1);
    deform_k<<<BL, 128>>>(xt, pfp, pa0, pa1, ploc);

    // global branch: reduce (concat GEMM)
    gemm_k<M_CONCAT><<<dim3(1, 256), 256>>>(xt, hx, red_w, red_b, nullptr, px,
                                            BL, 128, 256, 0);

    for (int i = 0; i < 2; i++) {
        int shift = i ? 4 : 0;
        // LN1 + shift/window-partition gather
        ln_k<<<BL / 8, 256>>>(px, n1g + i * 128, n1b + i * 128, pxw, 1, shift);
        // QKV GEMM (window layout rows)
        gemm_k<M_PLAIN><<<dim3(3, 256), 256>>>(pxw, nullptr, qkvw + i * 49152,
                                               qkvb + i * 384, nullptr, pbig,
                                               BL, 384, 128, 0);
        // windowed attention + rel-pos bias + (shifted) mask + softmax
        attn_k<<<2048, 256>>>(pbig, rp + i * 900, patt, shift);
        // proj GEMM + window-reverse/roll permute + residual (in-place on d_x)
        gemm_k<M_PERMRES><<<dim3(1, 256), 256>>>(patt, nullptr, pw + i * 16384,
                                                 pb + i * 128, px, px,
                                                 BL, 128, 128, shift);
        // LN2
        ln_k<<<BL / 8, 256>>>(px, n2g + i * 128, n2b + i * 128, pxw, 0, 0);
        // MLP fc1 + exact GELU
        gemm_k<M_GELU><<<dim3(4, 256), 256>>>(pxw, nullptr, f1w + i * 65536,
                                              f1b + i * 512, nullptr, pbig,
                                              BL, 512, 128, 0);
        // MLP fc2 + residual (in-place on d_x)
        gemm_k<M_RES><<<dim3(1, 256), 256>>>(pbig, nullptr, f2w + i * 65536,
                                             f2b + i * 128, px, px,
                                             BL, 128, 512, 0);
    }

    // fusion: relu((local@lf + lf_b) * (g@gf + gf_b)) @ ff + ff_b, then LSTM gate
    gemm_k<M_PLAIN><<<dim3(1, 256), 256>>>(ploc, nullptr, lf_w, lf_b, nullptr, patt,
                                           BL, 128, 128, 0);
    gemm_k<M_MULRELU><<<dim3(1, 256), 256>>>(px, nullptr, gf_w, gf_b, patt, pt,
                                             BL, 128, 128, 0);
    gemm_k<M_GATE><<<dim3(1, 256), 256>>>(pt, nullptr, ff_w, ff_b, cx, (float*)d_out,
                                          BL, 128, 128, 0);
}

// round 4
// speedup vs baseline: 1.9351x; 1.8495x over previous
#include <cuda_runtime.h>
#include <math.h>

// Problem constants
#define Bn   8
#define Ln   4096
#define Cn   128
#define BL   32768            // B*L rows

typedef unsigned int u32;
typedef unsigned long long u64;

// ---------------- small helpers ----------------
__device__ __forceinline__ float rna(float x) {
    float r; asm("cvt.rna.tf32.f32 %0, %1;" : "=f"(r) : "f"(x)); return r;
}
__device__ __forceinline__ u32 smem_u32(const void* p) {
    u32 a;
    asm("{ .reg .u64 t; cvta.to.shared.u64 t, %1; cvt.u32.u64 %0, t; }" : "=r"(a) : "l"(p));
    return a;
}
__device__ __forceinline__ void cp16(u32 dst, const void* src) {
    size_t g = __cvta_generic_to_global(src);
    asm volatile("cp.async.cg.shared.global [%0], [%1], 16;" :: "r"(dst), "l"(g));
}
__device__ __forceinline__ u64 pk2(float lo, float hi) {
    u64 r; asm("mov.b64 %0, {%1, %2};" : "=l"(r) : "f"(lo), "f"(hi)); return r;
}
__device__ __forceinline__ void fma2(u64& d, u64 a, u64 b) {
    asm("fma.rn.f32x2 %0, %1, %2, %0;" : "+l"(d) : "l"(a), "l"(b));
}
__device__ __forceinline__ float2 upk(u64 v) {
    float2 f; asm("mov.b64 {%0, %1}, %2;" : "=f"(f.x), "=f"(f.y) : "l"(v)); return f;
}

// ---------------- scratch (device globals; no allocs allowed) ----------------
__device__ float d_x  [BL * Cn];     // running stream value (g / x), full fp32
__device__ float d_xw [BL * Cn];     // LN output (tf32-rounded)
__device__ float d_big[BL * 512];    // concat input (256) / qkv (384) / MLP hidden (512)
__device__ float d_att[BL * Cn];     // attention out; fusion tmp A
__device__ float d_t  [BL * Cn];     // fusion tmp
__device__ float d_loc[BL * Cn];     // deform-conv output, stored (B,C,L) flat
__device__ int   d_fp [Bn * 3 * Ln];
__device__ float d_a0 [Bn * 3 * Ln];
__device__ float d_a1 [Bn * 3 * Ln];

// window-layout row m  <->  token index (b*L + ho*64 + wo)
__device__ __forceinline__ int win_to_token(int m, int shift) {
    int n    = m & 63;
    int bw   = m >> 6;
    int widx = bw & 63;
    int b    = bw >> 6;
    int wh = widx >> 3, ww = widx & 7;
    int r = n >> 3, s = n & 7;
    int ho = (wh * 8 + r + shift) & 63;
    int wo = (ww * 8 + s + shift) & 63;
    return (b << 12) + (ho << 6) + wo;
}

// ---------------- tensor-core GEMM: 128x128 tile, K-tile 32, mma.m16n8k8 tf32 ----------------
enum { M_PLAIN = 0, M_GELU, M_RES, M_PERMRES, M_MULRELU, M_GATE };

#define AS_STRIDE 36               // 32 k + 4 pad
#define BS_STRIDE 132              // 128 n + 4 pad
#define A_WORDS   (128 * AS_STRIDE)          // 4608
#define B_WORDS   (32 * BS_STRIDE)           // 4224
#define BUF_WORDS (A_WORDS + B_WORDS)        // 8832
#define SMEM_BYTES (2 * BUF_WORDS * 4)       // 70656

template <int MODE>
__global__ void __launch_bounds__(256, 2) gemm_tc(
    const float* __restrict__ A, const float* __restrict__ Bm,
    const float* __restrict__ bias, const float* __restrict__ extra,
    float* __restrict__ C, int N, int K, int shift)
{
    extern __shared__ float sm[];
    int tid = threadIdx.x;
    int lane = tid & 31, warp = tid >> 5;
    int warp_m = warp & 1, warp_n = warp >> 1;    // 2 (M) x 4 (N)
    int m0 = blockIdx.y << 7, n0 = blockIdx.x << 7;
    int r = lane >> 2, c = lane & 3;

    float acc[4][4][4];
#pragma unroll
    for (int i = 0; i < 4; i++)
#pragma unroll
        for (int j = 0; j < 4; j++)
#pragma unroll
            for (int q = 0; q < 4; q++) acc[i][j][q] = 0.f;

    // prefetch tile (k0) into buffer b
    auto prefetch = [&](int k0, int b) {
        u32 abase = smem_u32(sm + b * BUF_WORDS);
        u32 bbase = smem_u32(sm + b * BUF_WORDS + A_WORDS);
#pragma unroll
        for (int i = 0; i < 4; i++) {
            int ch = tid + (i << 8);                  // 0..1023
            int ar = ch >> 3, ac = (ch & 7) << 2;     // A: 128 rows x 8 chunks
            cp16(abase + (u32)(ar * AS_STRIDE + ac) * 4,
                 A + (size_t)(m0 + ar) * K + k0 + ac);
            int br = ch >> 5, bc = (ch & 31) << 2;    // B: 32 rows x 32 chunks
            cp16(bbase + (u32)(br * BS_STRIDE + bc) * 4,
                 Bm + (size_t)(k0 + br) * N + n0 + bc);
        }
        asm volatile("cp.async.commit_group;");
    };

    int nt = K >> 5;
    prefetch(0, 0);
    for (int t = 0; t < nt; t++) {
        asm volatile("cp.async.wait_group 0;");
        __syncthreads();                       // tile t visible; compute(t-1) done everywhere
        if (t + 1 < nt) prefetch((t + 1) << 5, (t + 1) & 1);

        const float* As = sm + (t & 1) * BUF_WORDS;
        const float* Bs = As + A_WORDS;
#pragma unroll
        for (int k8 = 0; k8 < 4; k8++) {
            u32 afr[4][4];
#pragma unroll
            for (int mt = 0; mt < 4; mt++) {
                const float* ap = As + (warp_m * 64 + mt * 16 + r) * AS_STRIDE + k8 * 8 + c;
                afr[mt][0] = __float_as_uint(ap[0]);
                afr[mt][1] = __float_as_uint(ap[8 * AS_STRIDE]);
                afr[mt][2] = __float_as_uint(ap[4]);
                afr[mt][3] = __float_as_uint(ap[8 * AS_STRIDE + 4]);
            }
#pragma unroll
            for (int nt2 = 0; nt2 < 4; nt2++) {
                const float* bp = Bs + (k8 * 8 + c) * BS_STRIDE + warp_n * 32 + nt2 * 8 + r;
                u32 b0 = __float_as_uint(bp[0]);
                u32 b1 = __float_as_uint(bp[4 * BS_STRIDE]);
#pragma unroll
                for (int mt = 0; mt < 4; mt++) {
                    asm volatile(
                        "mma.sync.aligned.m16n8k8.row.col.f32.tf32.tf32.f32 "
                        "{%0,%1,%2,%3},{%4,%5,%6,%7},{%8,%9},{%0,%1,%2,%3};"
                        : "+f"(acc[mt][nt2][0]), "+f"(acc[mt][nt2][1]),
                          "+f"(acc[mt][nt2][2]), "+f"(acc[mt][nt2][3])
                        : "r"(afr[mt][0]), "r"(afr[mt][1]), "r"(afr[mt][2]), "r"(afr[mt][3]),
                          "r"(b0), "r"(b1));
                }
            }
        }
        __syncthreads();                        // done reading buf t before it is refilled
    }

    // epilogue
#pragma unroll
    for (int mt = 0; mt < 4; mt++) {
        int row0 = m0 + warp_m * 64 + mt * 16 + r;
#pragma unroll
        for (int half = 0; half < 2; half++) {
            int row = row0 + half * 8;
            int dst = (MODE == M_PERMRES) ? win_to_token(row, shift) : row;
#pragma unroll
            for (int nt2 = 0; nt2 < 4; nt2++) {
                int col = n0 + warp_n * 32 + nt2 * 8 + c * 2;
                float v0 = acc[mt][nt2][half * 2 + 0] + bias[col];
                float v1 = acc[mt][nt2][half * 2 + 1] + bias[col + 1];
                size_t off = (size_t)dst * N + col;
                if (MODE == M_GELU) {
                    v0 = rna(0.5f * v0 * (1.f + erff(v0 * 0.70710678118654752f)));
                    v1 = rna(0.5f * v1 * (1.f + erff(v1 * 0.70710678118654752f)));
                } else if (MODE == M_RES || MODE == M_PERMRES) {
                    float2 e = *(const float2*)&extra[off];
                    v0 += e.x; v1 += e.y;
                } else if (MODE == M_MULRELU) {
                    float2 e = *(const float2*)&extra[off];
                    float t0 = e.x * v0, t1 = e.y * v1;
                    v0 = rna(t0 > 0.f ? t0 : 0.f);
                    v1 = rna(t1 > 0.f ? t1 : 0.f);
                } else if (MODE == M_GATE) {
                    float2 e = *(const float2*)&extra[off];
                    float g0 = 1.f / (1.f + expf(-v0));
                    float g1 = 1.f / (1.f + expf(-v1));
                    float cy0 = g0 * (e.x + tanhf(v0));
                    float cy1 = g1 * (e.y + tanhf(v1));
                    v0 = g0 * tanhf(cy0);
                    v1 = g1 * tanhf(cy1);
                }
                *(float2*)&C[off] = make_float2(v0, v1);
            }
        }
    }
}

// ---------------- concat + tf32-round (reduce GEMM input) ----------------
__global__ void __launch_bounds__(256) concat_round_k(
    const float* __restrict__ xt, const float* __restrict__ hx, float* __restrict__ dst)
{
    int g = blockIdx.x * 256 + threadIdx.x;    // float4 id over BL*64
    int row = g >> 6, q = g & 63;
    const float* src = (q < 32) ? xt + (size_t)row * 128 + (q << 2)
                                : hx + (size_t)row * 128 + ((q - 32) << 2);
    float4 v = *(const float4*)src;
    v.x = rna(v.x); v.y = rna(v.y); v.z = rna(v.z); v.w = rna(v.w);
    *(float4*)(dst + (size_t)row * 256 + (q << 2)) = v;
}

// ---------------- LayerNorm (warp per row) with optional window gather ----------------
__global__ void __launch_bounds__(256) ln_k(
    const float* __restrict__ x, const float* __restrict__ gamma,
    const float* __restrict__ beta, float* __restrict__ y,
    int permute, int shift)
{
    int warp = threadIdx.x >> 5, lane = threadIdx.x & 31;
    int row = (blockIdx.x << 3) + warp;
    int src = permute ? win_to_token(row, shift) : row;
    float4 v = *((const float4*)(x + (size_t)src * 128) + lane);
    float s  = v.x + v.y + v.z + v.w;
    float ss = v.x * v.x + v.y * v.y + v.z * v.z + v.w * v.w;
#pragma unroll
    for (int o = 16; o > 0; o >>= 1) {
        s  += __shfl_xor_sync(0xffffffffu, s,  o);
        ss += __shfl_xor_sync(0xffffffffu, ss, o);
    }
    float mu  = s * 0.0078125f;
    float var = ss * 0.0078125f - mu * mu;
    float rs  = rsqrtf(var + 1e-5f);
    float4 g4 = *((const float4*)gamma + lane);
    float4 b4 = *((const float4*)beta  + lane);
    float4 o4;
    o4.x = rna((v.x - mu) * rs * g4.x + b4.x);
    o4.y = rna((v.y - mu) * rs * g4.y + b4.y);
    o4.z = rna((v.z - mu) * rs * g4.z + b4.z);
    o4.w = rna((v.w - mu) * rs * g4.w + b4.w);
    *((float4*)(y + (size_t)row * 128) + lane) = o4;
}

// ---------------- Window attention: one block per (window, head) ----------------
__global__ void __launch_bounds__(256) attn_k(
    const float* __restrict__ qkv, const float* __restrict__ rp,
    float* __restrict__ out, int shift)
{
    __shared__ float qs[64][36], ks[64][36], vs[64][36];   // 16B-aligned rows
    __shared__ float p[64][65];
    int tid = threadIdx.x;
    int bw = blockIdx.x >> 2;
    int h  = blockIdx.x & 3;
    const float SCALE = 0.17677669529663687f;   // 1/sqrt(32)
    const float* base = qkv + (size_t)bw * 64 * 384 + h * 32;

    for (int i = tid; i < 512; i += 256) {
        int n = i >> 3, d4 = (i & 7) << 2;
        float4 qv = *(const float4*)(base + n * 384 + d4);
        float4 kv = *(const float4*)(base + n * 384 + 128 + d4);
        float4 vv = *(const float4*)(base + n * 384 + 256 + d4);
        qv.x *= SCALE; qv.y *= SCALE; qv.z *= SCALE; qv.w *= SCALE;
        *(float4*)&qs[n][d4] = qv;
        *(float4*)&ks[n][d4] = kv;
        *(float4*)&vs[n][d4] = vv;
    }
    __syncthreads();

    int n = tid >> 2, quad = tid & 3;
    u64 q2[16];
#pragma unroll
    for (int d4 = 0; d4 < 8; d4++) {
        float4 qv = *(const float4*)&qs[n][d4 << 2];
        q2[2 * d4]     = pk2(qv.x, qv.y);
        q2[2 * d4 + 1] = pk2(qv.z, qv.w);
    }

    int r1 = n >> 3, s1 = n & 7;
    int widx = bw & 63;
    int wh = widx >> 3, ww = widx & 7;
    int h1 = wh * 8 + r1, w1 = ww * 8 + s1;
    int img1 = (h1 < 56 ? 0 : (h1 < 60 ? 1 : 2)) * 3 + (w1 < 56 ? 0 : (w1 < 60 ? 1 : 2));

#pragma unroll 4
    for (int mm = 0; mm < 16; mm++) {
        int m = (quad << 4) + mm;
        u64 s2 = 0ull;
#pragma unroll
        for (int d4 = 0; d4 < 8; d4++) {
            float4 kv = *(const float4*)&ks[m][d4 << 2];
            fma2(s2, q2[2 * d4],     pk2(kv.x, kv.y));
            fma2(s2, q2[2 * d4 + 1], pk2(kv.z, kv.w));
        }
        float2 sv = upk(s2);
        float s = sv.x + sv.y;
        int r2 = m >> 3, s2i = m & 7;
        s += rp[((r1 - r2 + 7) * 15 + (s1 - s2i + 7)) * 4 + h];
        if (shift) {
            int h2 = wh * 8 + r2, w2 = ww * 8 + s2i;
            int img2 = (h2 < 56 ? 0 : (h2 < 60 ? 1 : 2)) * 3 + (w2 < 56 ? 0 : (w2 < 60 ? 1 : 2));
            if (img1 != img2) s -= 100.f;
        }
        p[n][m] = s;
    }
    float mx = -1e30f;
#pragma unroll
    for (int mm = 0; mm < 16; mm++) mx = fmaxf(mx, p[n][(quad << 4) + mm]);
    mx = fmaxf(mx, __shfl_xor_sync(0xffffffffu, mx, 1));
    mx = fmaxf(mx, __shfl_xor_sync(0xffffffffu, mx, 2));
    float sum = 0.f;
#pragma unroll
    for (int mm = 0; mm < 16; mm++) {
        int m = (quad << 4) + mm;
        float e = expf(p[n][m] - mx);
        p[n][m] = e; sum += e;
    }
    sum += __shfl_xor_sync(0xffffffffu, sum, 1);
    sum += __shfl_xor_sync(0xffffffffu, sum, 2);
    float inv = 1.f / sum;
#pragma unroll
    for (int mm = 0; mm < 16; mm++) p[n][(quad << 4) + mm] *= inv;
    __syncthreads();

    u64 acc2[4] = {0ull, 0ull, 0ull, 0ull};
    int db = quad << 3;
#pragma unroll 8
    for (int m = 0; m < 64; m++) {
        float pm = p[n][m];
        u64 pm2 = pk2(pm, pm);
        float4 v0 = *(const float4*)&vs[m][db];
        float4 v1 = *(const float4*)&vs[m][db + 4];
        fma2(acc2[0], pm2, pk2(v0.x, v0.y));
        fma2(acc2[1], pm2, pk2(v0.z, v0.w));
        fma2(acc2[2], pm2, pk2(v1.x, v1.y));
        fma2(acc2[3], pm2, pk2(v1.z, v1.w));
    }
    float* op = out + ((size_t)(bw * 64 + n)) * 128 + h * 32 + db;
    float2 o0 = upk(acc2[0]), o1 = upk(acc2[1]), o2 = upk(acc2[2]), o3 = upk(acc2[3]);
    float4 wo0 = {rna(o0.x), rna(o0.y), rna(o1.x), rna(o1.y)};
    float4 wo1 = {rna(o2.x), rna(o2.y), rna(o3.x), rna(o3.y)};
    *(float4*)op = wo0;
    *(float4*)(op + 4) = wo1;
}

// ---------------- deformable-conv branch ----------------
__global__ void __launch_bounds__(256) offmask_k(
    const float* __restrict__ xt,
    const float* __restrict__ ow, const float* __restrict__ ob,
    const float* __restrict__ mw, const float* __restrict__ mb,
    int* __restrict__ fp, float* __restrict__ a0, float* __restrict__ a1)
{
    int warp = threadIdx.x >> 5, lane = threadIdx.x & 31;
    int bl = blockIdx.x * 8 + warp;
    int b = bl >> 12, l = bl & 4095;
    int c0 = lane << 2;
    float so[3] = {0.f, 0.f, 0.f}, sm[3] = {0.f, 0.f, 0.f};
#pragma unroll
    for (int j = 0; j < 3; j++) {
        int ll = l + j - 1;
        if (ll < 0 || ll > 4095) continue;
        float4 xv = *((const float4*)(xt + ((size_t)b * 4096 + ll) * 128) + lane);
#pragma unroll
        for (int k = 0; k < 3; k++) {
            const float* owp = ow + k * 384 + j;
            const float* mwp = mw + k * 384 + j;
            so[k] += xv.x * owp[(c0 + 0) * 3] + xv.y * owp[(c0 + 1) * 3]
                   + xv.z * owp[(c0 + 2) * 3] + xv.w * owp[(c0 + 3) * 3];
            sm[k] += xv.x * mwp[(c0 + 0) * 3] + xv.y * mwp[(c0 + 1) * 3]
                   + xv.z * mwp[(c0 + 2) * 3] + xv.w * mwp[(c0 + 3) * 3];
        }
    }
#pragma unroll
    for (int o = 16; o > 0; o >>= 1) {
#pragma unroll
        for (int k = 0; k < 3; k++) {
            so[k] += __shfl_xor_sync(0xffffffffu, so[k], o);
            sm[k] += __shfl_xor_sync(0xffffffffu, sm[k], o);
        }
    }
    if (lane < 3) {
        int k = lane;
        float off = ob[k] + so[k];
        float mk  = mb[k] + sm[k];
        float mask = 1.f / (1.f + expf(-mk));
        float pos = fminf(fmaxf((float)l + off, 0.f), 4095.f);
        float fpf = floorf(pos);
        int f = (int)fpf;
        float alpha = pos - fpf;
        int idx = (b * 3 + k) * 4096 + l;
        fp[idx] = f;
        a0[idx] = (1.f - alpha) * mask;
        a1[idx] = alpha * mask;
    }
}

__global__ void __launch_bounds__(128) deform_k(
    const float* __restrict__ xt, const int* __restrict__ fp,
    const float* __restrict__ a0, const float* __restrict__ a1,
    float* __restrict__ outp)
{
    int bl = blockIdx.x;                 // (b, l)
    int b = bl >> 12, l = bl & 4095;
    int c = threadIdx.x;
    float o = 0.f;
#pragma unroll
    for (int k = 0; k < 3; k++) {
        int base = (b * 3 + k) * 4096 + l;
        int f  = fp[base];
        int cp = min(f + 1, 4095);
        o += xt[((size_t)b * 4096 + f)  * 128 + c] * a0[base]
           + xt[((size_t)b * 4096 + cp) * 128 + c] * a1[base];
    }
    // torch .view: output stays in (B, C, L) memory order; rounded (feeds lf GEMM)
    outp[(size_t)b * 524288 + (size_t)c * 4096 + l] = rna(o);
}

// ---------------- host launcher ----------------
extern "C" void kernel_launch(void* const* d_in, const int* in_sizes, int n_in,
                              void* d_out, int out_size)
{
    const float* xt    = (const float*)d_in[0];
    const float* hx    = (const float*)d_in[1];
    const float* cx    = (const float*)d_in[2];
    const float* red_w = (const float*)d_in[3];
    const float* red_b = (const float*)d_in[4];
    const float* n1g   = (const float*)d_in[5];
    const float* n1b   = (const float*)d_in[6];
    const float* qkvw  = (const float*)d_in[7];
    const float* qkvb  = (const float*)d_in[8];
    const float* rp    = (const float*)d_in[9];
    const float* pw    = (const float*)d_in[10];
    const float* pb    = (const float*)d_in[11];
    const float* n2g   = (const float*)d_in[12];
    const float* n2b   = (const float*)d_in[13];
    const float* f1w   = (const float*)d_in[14];
    const float* f1b   = (const float*)d_in[15];
    const float* f2w   = (const float*)d_in[16];
    const float* f2b   = (const float*)d_in[17];
    const float* off_w = (const float*)d_in[18];
    const float* off_b = (const float*)d_in[19];
    const float* msk_w = (const float*)d_in[20];
    const float* msk_b = (const float*)d_in[21];
    const float* lf_w  = (const float*)d_in[22];
    const float* lf_b  = (const float*)d_in[23];
    const float* gf_w  = (const float*)d_in[24];
    const float* gf_b  = (const float*)d_in[25];
    const float* ff_w  = (const float*)d_in[26];
    const float* ff_b  = (const float*)d_in[27];

    float *px, *pxw, *pbig, *patt, *pt, *ploc, *pa0, *pa1;
    int* pfp;
    cudaGetSymbolAddress((void**)&px,   d_x);
    cudaGetSymbolAddress((void**)&pxw,  d_xw);
    cudaGetSymbolAddress((void**)&pbig, d_big);
    cudaGetSymbolAddress((void**)&patt, d_att);
    cudaGetSymbolAddress((void**)&pt,   d_t);
    cudaGetSymbolAddress((void**)&ploc, d_loc);
    cudaGetSymbolAddress((void**)&pfp,  d_fp);
    cudaGetSymbolAddress((void**)&pa0,  d_a0);
    cudaGetSymbolAddress((void**)&pa1,  d_a1);

    // allow 70656 B dynamic smem on all gemm_tc instantiations
    cudaFuncSetAttribute(gemm_tc<M_PLAIN>,   cudaFuncAttributeMaxDynamicSharedMemorySize, SMEM_BYTES);
    cudaFuncSetAttribute(gemm_tc<M_GELU>,    cudaFuncAttributeMaxDynamicSharedMemorySize, SMEM_BYTES);
    cudaFuncSetAttribute(gemm_tc<M_RES>,     cudaFuncAttributeMaxDynamicSharedMemorySize, SMEM_BYTES);
    cudaFuncSetAttribute(gemm_tc<M_PERMRES>, cudaFuncAttributeMaxDynamicSharedMemorySize, SMEM_BYTES);
    cudaFuncSetAttribute(gemm_tc<M_MULRELU>, cudaFuncAttributeMaxDynamicSharedMemorySize, SMEM_BYTES);
    cudaFuncSetAttribute(gemm_tc<M_GATE>,    cudaFuncAttributeMaxDynamicSharedMemorySize, SMEM_BYTES);

    // local (deformable) branch
    offmask_k<<<Bn * Ln / 8, 256>>>(xt, off_w, off_b, msk_w, msk_b, pfp, pa0, pa1);
    deform_k<<<BL, 128>>>(xt, pfp, pa0, pa1, ploc);

    // global branch: concat+round then reduce GEMM (K=256)
    concat_round_k<<<BL * 64 / 256, 256>>>(xt, hx, pbig);
    gemm_tc<M_PLAIN><<<dim3(1, 256), 256, SMEM_BYTES>>>(pbig, red_w, red_b, nullptr, px,
                                                        128, 256, 0);

    for (int i = 0; i < 2; i++) {
        int shift = i ? 4 : 0;
        ln_k<<<BL / 8, 256>>>(px, n1g + i * 128, n1b + i * 128, pxw, 1, shift);
        gemm_tc<M_PLAIN><<<dim3(3, 256), 256, SMEM_BYTES>>>(pxw, qkvw + i * 49152,
                                                            qkvb + i * 384, nullptr, pbig,
                                                            384, 128, 0);
        attn_k<<<2048, 256>>>(pbig, rp + i * 900, patt, shift);
        gemm_tc<M_PERMRES><<<dim3(1, 256), 256, SMEM_BYTES>>>(patt, pw + i * 16384,
                                                              pb + i * 128, px, px,
                                                              128, 128, shift);
        ln_k<<<BL / 8, 256>>>(px, n2g + i * 128, n2b + i * 128, pxw, 0, 0);
        gemm_tc<M_GELU><<<dim3(4, 256), 256, SMEM_BYTES>>>(pxw, f1w + i * 65536,
                                                           f1b + i * 512, nullptr, pbig,
                                                           512, 128, 0);
        gemm_tc<M_RES><<<dim3(1, 256), 256, SMEM_BYTES>>>(pbig, f2w + i * 65536,
                                                          f2b + i * 128, px, px,
                                                          128, 512, 0);
    }

    // fusion + LSTM gate
    gemm_tc<M_PLAIN><<<dim3(1, 256), 256, SMEM_BYTES>>>(ploc, lf_w, lf_b, nullptr, patt,
                                                        128, 128, 0);
    gemm_tc<M_MULRELU><<<dim3(1, 256), 256, SMEM_BYTES>>>(px, gf_w, gf_b, patt, pt,
                                                          128, 128, 0);
    gemm_tc<M_GATE><<<dim3(1, 256), 256, SMEM_BYTES>>>(pt, ff_w, ff_b, cx, (float*)d_out,
                                                       128, 128, 0);
}

// round 5
// speedup vs baseline: 2.1862x; 1.1298x over previous
#include <cuda_runtime.h>
#include <cuda_bf16.h>
#include <math.h>

// Problem constants
#define Bn   8
#define Ln   4096
#define Cn   128
#define BL   32768            // B*L rows

typedef unsigned int u32;
typedef unsigned long long u64;
typedef __nv_bfloat16 bf16;

// ---------------- helpers ----------------
__device__ __forceinline__ u32 smem_u32(const void* p) {
    u32 a;
    asm("{ .reg .u64 t; cvta.to.shared.u64 t, %1; cvt.u32.u64 %0, t; }" : "=r"(a) : "l"(p));
    return a;
}
__device__ __forceinline__ void cp16(u32 dst, const void* src) {
    size_t g = __cvta_generic_to_global(src);
    asm volatile("cp.async.cg.shared.global [%0], [%1], 16;" :: "r"(dst), "l"(g));
}
__device__ __forceinline__ void ldm_x4(u32& r0, u32& r1, u32& r2, u32& r3, u32 addr) {
    asm volatile("ldmatrix.sync.aligned.m8n8.x4.shared.b16 {%0,%1,%2,%3}, [%4];"
                 : "=r"(r0), "=r"(r1), "=r"(r2), "=r"(r3) : "r"(addr));
}
__device__ __forceinline__ u32 bf2(float a, float b) {
    __nv_bfloat162 h;
    h.x = __float2bfloat16_rn(a);
    h.y = __float2bfloat16_rn(b);
    return *(u32*)&h;
}
__device__ __forceinline__ u64 pk2(float lo, float hi) {
    u64 r; asm("mov.b64 %0, {%1, %2};" : "=l"(r) : "f"(lo), "f"(hi)); return r;
}
__device__ __forceinline__ void fma2(u64& d, u64 a, u64 b) {
    asm("fma.rn.f32x2 %0, %1, %2, %0;" : "+l"(d) : "l"(a), "l"(b));
}
__device__ __forceinline__ float2 upk(u64 v) {
    float2 f; asm("mov.b64 {%0, %1}, %2;" : "=f"(f.x), "=f"(f.y) : "l"(v)); return f;
}

// ---------------- scratch (device globals; no allocs allowed) ----------------
__device__ float d_x   [BL * Cn];      // running stream (fp32)
__device__ float d_big [BL * 384];     // qkv output (fp32, attn input)
__device__ float d_att [BL * Cn];      // lf output (fusion multiplier, fp32)
__device__ bf16  g_big16[BL * 512];    // concat input / MLP hidden (bf16)
__device__ bf16  g_xw16 [BL * Cn];     // LN output (bf16)
__device__ bf16  g_att16[BL * Cn];     // attention out (bf16)
__device__ bf16  g_loc16[BL * Cn];     // deform out (bf16, (B,C,L) flat)
__device__ bf16  g_t16  [BL * Cn];     // mulrelu out (bf16)
__device__ bf16  g_x16  [BL * Cn];     // final g (bf16)
__device__ int   d_fp [Bn * 3 * Ln];
__device__ float d_a0 [Bn * 3 * Ln];
__device__ float d_a1 [Bn * 3 * Ln];
// transposed bf16 weights (N x K row-major)
__device__ bf16  g_redT[128 * 256];
__device__ bf16  g_qkvT[2 * 384 * 128];
__device__ bf16  g_pwT [2 * 128 * 128];
__device__ bf16  g_f1T [2 * 512 * 128];
__device__ bf16  g_f2T [2 * 128 * 512];
__device__ bf16  g_lfT [128 * 128];
__device__ bf16  g_gfT [128 * 128];
__device__ bf16  g_ffT [128 * 128];

// window-layout row m  <->  token index (b*L + ho*64 + wo)
__device__ __forceinline__ int win_to_token(int m, int shift) {
    int n    = m & 63;
    int bw   = m >> 6;
    int widx = bw & 63;
    int b    = bw >> 6;
    int wh = widx >> 3, ww = widx & 7;
    int r = n >> 3, s = n & 7;
    int ho = (wh * 8 + r + shift) & 63;
    int wo = (ww * 8 + s + shift) & 63;
    return (b << 12) + (ho << 6) + wo;
}

// ---------------- weight transpose-convert: (K x N fp32) -> (N x K bf16) ----------------
struct WEnt { const float* src; bf16* dst; int K; int N; };
struct WPack { WEnt e[12]; };

__global__ void __launch_bounds__(256) wconv_k(WPack p) {
    WEnt w = p.e[blockIdx.y];
    int total = w.K * w.N;
    for (int i = blockIdx.x * 256 + threadIdx.x; i < total; i += gridDim.x * 256) {
        int n = i / w.K, k = i - n * w.K;
        w.dst[i] = __float2bfloat16_rn(w.src[(size_t)k * w.N + n]);
    }
}

// ---------------- bf16 tensor-core GEMM: 128x128 tile, K-tile 32, m16n8k16 ----------------
enum { M_PLAIN = 0, M_GELU, M_RES, M_PERMRES, M_MULRELU, M_GATE };

#define TSTRIDE 40   // 32 k halfs + 8 pad (80 B rows: odd # of 16B units -> ldmatrix conflict-free)

template <int MODE>
__global__ void __launch_bounds__(256, 2) gemm_tc(
    const bf16* __restrict__ A, const bf16* __restrict__ BT,
    const float* __restrict__ bias, const float* __restrict__ extra,
    float* __restrict__ C, bf16* __restrict__ C16,
    int N, int K, int shift)
{
    __shared__ bf16 As[2][128 * TSTRIDE];
    __shared__ bf16 Bs[2][128 * TSTRIDE];
    int tid = threadIdx.x;
    int lane = tid & 31, warp = tid >> 5;
    int warp_m = warp & 1, warp_n = warp >> 1;    // 2 (M) x 4 (N)
    int m0 = blockIdx.y << 7, n0 = blockIdx.x << 7;
    int r = lane >> 2, c = lane & 3;

    float acc[4][4][4];
#pragma unroll
    for (int i = 0; i < 4; i++)
#pragma unroll
        for (int j = 0; j < 4; j++)
#pragma unroll
            for (int q = 0; q < 4; q++) acc[i][j][q] = 0.f;

    auto prefetch = [&](int k0, int b) {
        u32 abase = smem_u32(&As[b][0]);
        u32 bbase = smem_u32(&Bs[b][0]);
#pragma unroll
        for (int i = 0; i < 2; i++) {
            int ch = tid + (i << 8);              // 0..511
            int rr = ch >> 2, cc = (ch & 3) << 3; // row, half-offset (16B chunks)
            cp16(abase + (u32)(rr * TSTRIDE + cc) * 2,
                 A + (size_t)(m0 + rr) * K + k0 + cc);
            cp16(bbase + (u32)(rr * TSTRIDE + cc) * 2,
                 BT + (size_t)(n0 + rr) * K + k0 + cc);
        }
        asm volatile("cp.async.commit_group;");
    };

    int lrow = lane & 15;
    int lcol = (lane >> 4) << 3;                 // 0 or 8 halfs

    int ntk = K >> 5;
    prefetch(0, 0);
    for (int t = 0; t < ntk; t++) {
        asm volatile("cp.async.wait_group 0;");
        __syncthreads();
        if (t + 1 < ntk) prefetch((t + 1) << 5, (t + 1) & 1);

        u32 abase = smem_u32(&As[t & 1][0]);
        u32 bbase = smem_u32(&Bs[t & 1][0]);
#pragma unroll
        for (int ks = 0; ks < 2; ks++) {
            u32 af[4][4];
#pragma unroll
            for (int mt = 0; mt < 4; mt++)
                ldm_x4(af[mt][0], af[mt][1], af[mt][2], af[mt][3],
                       abase + (u32)((warp_m * 64 + mt * 16 + lrow) * TSTRIDE + ks * 16 + lcol) * 2);
            u32 bfr[2][4];
#pragma unroll
            for (int p = 0; p < 2; p++)
                ldm_x4(bfr[p][0], bfr[p][1], bfr[p][2], bfr[p][3],
                       bbase + (u32)((warp_n * 32 + p * 16 + lrow) * TSTRIDE + ks * 16 + lcol) * 2);
#pragma unroll
            for (int p = 0; p < 2; p++)
#pragma unroll
                for (int q = 0; q < 2; q++) {
                    int nt2 = p * 2 + q;
                    u32 b0 = bfr[p][q], b1 = bfr[p][q + 2];
#pragma unroll
                    for (int mt = 0; mt < 4; mt++) {
                        asm volatile(
                            "mma.sync.aligned.m16n8k16.row.col.f32.bf16.bf16.f32 "
                            "{%0,%1,%2,%3},{%4,%5,%6,%7},{%8,%9},{%0,%1,%2,%3};"
                            : "+f"(acc[mt][nt2][0]), "+f"(acc[mt][nt2][1]),
                              "+f"(acc[mt][nt2][2]), "+f"(acc[mt][nt2][3])
                            : "r"(af[mt][0]), "r"(af[mt][1]), "r"(af[mt][2]), "r"(af[mt][3]),
                              "r"(b0), "r"(b1));
                    }
                }
        }
        __syncthreads();
    }

    // epilogue
#pragma unroll
    for (int mt = 0; mt < 4; mt++) {
        int row0 = m0 + warp_m * 64 + mt * 16 + r;
#pragma unroll
        for (int half = 0; half < 2; half++) {
            int row = row0 + half * 8;
            int dst = (MODE == M_PERMRES) ? win_to_token(row, shift) : row;
#pragma unroll
            for (int nt2 = 0; nt2 < 4; nt2++) {
                int col = n0 + warp_n * 32 + nt2 * 8 + c * 2;
                float v0 = acc[mt][nt2][half * 2 + 0] + bias[col];
                float v1 = acc[mt][nt2][half * 2 + 1] + bias[col + 1];
                size_t off = (size_t)dst * N + col;
                if (MODE == M_GELU) {
                    v0 = 0.5f * v0 * (1.f + erff(v0 * 0.70710678118654752f));
                    v1 = 0.5f * v1 * (1.f + erff(v1 * 0.70710678118654752f));
                } else if (MODE == M_RES || MODE == M_PERMRES) {
                    float2 e = *(const float2*)&extra[off];
                    v0 += e.x; v1 += e.y;
                } else if (MODE == M_MULRELU) {
                    float2 e = *(const float2*)&extra[off];
                    float t0 = e.x * v0, t1 = e.y * v1;
                    v0 = t0 > 0.f ? t0 : 0.f;
                    v1 = t1 > 0.f ? t1 : 0.f;
                } else if (MODE == M_GATE) {
                    float2 e = *(const float2*)&extra[off];
                    float g0 = 1.f / (1.f + expf(-v0));
                    float g1 = 1.f / (1.f + expf(-v1));
                    float cy0 = g0 * (e.x + tanhf(v0));
                    float cy1 = g1 * (e.y + tanhf(v1));
                    v0 = g0 * tanhf(cy0);
                    v1 = g1 * tanhf(cy1);
                }
                if (C)   *(float2*)&C[off] = make_float2(v0, v1);
                if (C16) *(u32*)&C16[off]  = bf2(v0, v1);
            }
        }
    }
}

// ---------------- concat + bf16 (reduce GEMM input) ----------------
__global__ void __launch_bounds__(256) concat_k(
    const float* __restrict__ xt, const float* __restrict__ hx, bf16* __restrict__ dst)
{
    int g = blockIdx.x * 256 + threadIdx.x;    // float4 id over BL*64
    int row = g >> 6, q = g & 63;
    const float* src = (q < 32) ? xt + (size_t)row * 128 + (q << 2)
                                : hx + (size_t)row * 128 + ((q - 32) << 2);
    float4 v = *(const float4*)src;
    uint2 o = make_uint2(bf2(v.x, v.y), bf2(v.z, v.w));
    *(uint2*)(dst + (size_t)row * 256 + (q << 2)) = o;
}

// ---------------- LayerNorm (warp per row) -> bf16, optional window gather ----------------
__global__ void __launch_bounds__(256) ln_k(
    const float* __restrict__ x, const float* __restrict__ gamma,
    const float* __restrict__ beta, bf16* __restrict__ y,
    int permute, int shift)
{
    int warp = threadIdx.x >> 5, lane = threadIdx.x & 31;
    int row = (blockIdx.x << 3) + warp;
    int src = permute ? win_to_token(row, shift) : row;
    float4 v = *((const float4*)(x + (size_t)src * 128) + lane);
    float s  = v.x + v.y + v.z + v.w;
    float ss = v.x * v.x + v.y * v.y + v.z * v.z + v.w * v.w;
#pragma unroll
    for (int o = 16; o > 0; o >>= 1) {
        s  += __shfl_xor_sync(0xffffffffu, s,  o);
        ss += __shfl_xor_sync(0xffffffffu, ss, o);
    }
    float mu  = s * 0.0078125f;
    float var = ss * 0.0078125f - mu * mu;
    float rs  = rsqrtf(var + 1e-5f);
    float4 g4 = *((const float4*)gamma + lane);
    float4 b4 = *((const float4*)beta  + lane);
    uint2 o2;
    o2.x = bf2((v.x - mu) * rs * g4.x + b4.x, (v.y - mu) * rs * g4.y + b4.y);
    o2.y = bf2((v.z - mu) * rs * g4.z + b4.z, (v.w - mu) * rs * g4.w + b4.w);
    *((uint2*)(y + (size_t)row * 128) + lane) = o2;
}

// ---------------- Window attention: one block per (window, head) ----------------
__global__ void __launch_bounds__(256) attn_k(
    const float* __restrict__ qkv, const float* __restrict__ rp,
    bf16* __restrict__ out, int shift)
{
    __shared__ float qs[64][36], ks[64][36], vs[64][36];
    __shared__ float p[64][65];
    int tid = threadIdx.x;
    int bw = blockIdx.x >> 2;
    int h  = blockIdx.x & 3;
    const float SCALE = 0.17677669529663687f;   // 1/sqrt(32)
    const float* base = qkv + (size_t)bw * 64 * 384 + h * 32;

    for (int i = tid; i < 512; i += 256) {
        int n = i >> 3, d4 = (i & 7) << 2;
        float4 qv = *(const float4*)(base + n * 384 + d4);
        float4 kv = *(const float4*)(base + n * 384 + 128 + d4);
        float4 vv = *(const float4*)(base + n * 384 + 256 + d4);
        qv.x *= SCALE; qv.y *= SCALE; qv.z *= SCALE; qv.w *= SCALE;
        *(float4*)&qs[n][d4] = qv;
        *(float4*)&ks[n][d4] = kv;
        *(float4*)&vs[n][d4] = vv;
    }
    __syncthreads();

    int n = tid >> 2, quad = tid & 3;
    u64 q2[16];
#pragma unroll
    for (int d4 = 0; d4 < 8; d4++) {
        float4 qv = *(const float4*)&qs[n][d4 << 2];
        q2[2 * d4]     = pk2(qv.x, qv.y);
        q2[2 * d4 + 1] = pk2(qv.z, qv.w);
    }

    int r1 = n >> 3, s1 = n & 7;
    int widx = bw & 63;
    int wh = widx >> 3, ww = widx & 7;
    int h1 = wh * 8 + r1, w1 = ww * 8 + s1;
    int img1 = (h1 < 56 ? 0 : (h1 < 60 ? 1 : 2)) * 3 + (w1 < 56 ? 0 : (w1 < 60 ? 1 : 2));

#pragma unroll 4
    for (int mm = 0; mm < 16; mm++) {
        int m = (quad << 4) + mm;
        u64 s2 = 0ull;
#pragma unroll
        for (int d4 = 0; d4 < 8; d4++) {
            float4 kv = *(const float4*)&ks[m][d4 << 2];
            fma2(s2, q2[2 * d4],     pk2(kv.x, kv.y));
            fma2(s2, q2[2 * d4 + 1], pk2(kv.z, kv.w));
        }
        float2 sv = upk(s2);
        float s = sv.x + sv.y;
        int r2 = m >> 3, s2i = m & 7;
        s += rp[((r1 - r2 + 7) * 15 + (s1 - s2i + 7)) * 4 + h];
        if (shift) {
            int h2 = wh * 8 + r2, w2 = ww * 8 + s2i;
            int img2 = (h2 < 56 ? 0 : (h2 < 60 ? 1 : 2)) * 3 + (w2 < 56 ? 0 : (w2 < 60 ? 1 : 2));
            if (img1 != img2) s -= 100.f;
        }
        p[n][m] = s;
    }
    float mx = -1e30f;
#pragma unroll
    for (int mm = 0; mm < 16; mm++) mx = fmaxf(mx, p[n][(quad << 4) + mm]);
    mx = fmaxf(mx, __shfl_xor_sync(0xffffffffu, mx, 1));
    mx = fmaxf(mx, __shfl_xor_sync(0xffffffffu, mx, 2));
    float sum = 0.f;
#pragma unroll
    for (int mm = 0; mm < 16; mm++) {
        int m = (quad << 4) + mm;
        float e = expf(p[n][m] - mx);
        p[n][m] = e; sum += e;
    }
    sum += __shfl_xor_sync(0xffffffffu, sum, 1);
    sum += __shfl_xor_sync(0xffffffffu, sum, 2);
    float inv = 1.f / sum;
#pragma unroll
    for (int mm = 0; mm < 16; mm++) p[n][(quad << 4) + mm] *= inv;
    __syncthreads();

    u64 acc2[4] = {0ull, 0ull, 0ull, 0ull};
    int db = quad << 3;
#pragma unroll 8
    for (int m = 0; m < 64; m++) {
        float pm = p[n][m];
        u64 pm2 = pk2(pm, pm);
        float4 v0 = *(const float4*)&vs[m][db];
        float4 v1 = *(const float4*)&vs[m][db + 4];
        fma2(acc2[0], pm2, pk2(v0.x, v0.y));
        fma2(acc2[1], pm2, pk2(v0.z, v0.w));
        fma2(acc2[2], pm2, pk2(v1.x, v1.y));
        fma2(acc2[3], pm2, pk2(v1.z, v1.w));
    }
    bf16* op = out + ((size_t)(bw * 64 + n)) * 128 + h * 32 + db;
    float2 o0 = upk(acc2[0]), o1 = upk(acc2[1]), o2 = upk(acc2[2]), o3 = upk(acc2[3]);
    uint4 w4;
    w4.x = bf2(o0.x, o0.y); w4.y = bf2(o1.x, o1.y);
    w4.z = bf2(o2.x, o2.y); w4.w = bf2(o3.x, o3.y);
    *(uint4*)op = w4;
}

// ---------------- deformable-conv branch ----------------
__global__ void __launch_bounds__(256) offmask_k(
    const float* __restrict__ xt,
    const float* __restrict__ ow, const float* __restrict__ ob,
    const float* __restrict__ mw, const float* __restrict__ mb,
    int* __restrict__ fp, float* __restrict__ a0, float* __restrict__ a1)
{
    int warp = threadIdx.x >> 5, lane = threadIdx.x & 31;
    int bl = blockIdx.x * 8 + warp;
    int b = bl >> 12, l = bl & 4095;
    int c0 = lane << 2;
    float so[3] = {0.f, 0.f, 0.f}, sm[3] = {0.f, 0.f, 0.f};
#pragma unroll
    for (int j = 0; j < 3; j++) {
        int ll = l + j - 1;
        if (ll < 0 || ll > 4095) continue;
        float4 xv = *((const float4*)(xt + ((size_t)b * 4096 + ll) * 128) + lane);
#pragma unroll
        for (int k = 0; k < 3; k++) {
            const float* owp = ow + k * 384 + j;
            const float* mwp = mw + k * 384 + j;
            so[k] += xv.x * owp[(c0 + 0) * 3] + xv.y * owp[(c0 + 1) * 3]
                   + xv.z * owp[(c0 + 2) * 3] + xv.w * owp[(c0 + 3) * 3];
            sm[k] += xv.x * mwp[(c0 + 0) * 3] + xv.y * mwp[(c0 + 1) * 3]
                   + xv.z * mwp[(c0 + 2) * 3] + xv.w * mwp[(c0 + 3) * 3];
        }
    }
#pragma unroll
    for (int o = 16; o > 0; o >>= 1) {
#pragma unroll
        for (int k = 0; k < 3; k++) {
            so[k] += __shfl_xor_sync(0xffffffffu, so[k], o);
            sm[k] += __shfl_xor_sync(0xffffffffu, sm[k], o);
        }
    }
    if (lane < 3) {
        int k = lane;
        float off = ob[k] + so[k];
        float mk  = mb[k] + sm[k];
        float mask = 1.f / (1.f + expf(-mk));
        float pos = fminf(fmaxf((float)l + off, 0.f), 4095.f);
        float fpf = floorf(pos);
        int f = (int)fpf;
        float alpha = pos - fpf;
        int idx = (b * 3 + k) * 4096 + l;
        fp[idx] = f;
        a0[idx] = (1.f - alpha) * mask;
        a1[idx] = alpha * mask;
    }
}

// block = (b, 32-l tile); coalesced reads + smem-transposed coalesced bf16 writes
__global__ void __launch_bounds__(256) deform_k(
    const float* __restrict__ xt, const int* __restrict__ fp,
    const float* __restrict__ a0, const float* __restrict__ a1,
    bf16* __restrict__ outp)
{
    __shared__ bf16 sm[32][130];
    int b  = blockIdx.x >> 7;
    int l0 = (blockIdx.x & 127) << 5;
    int tid = threadIdx.x;
#pragma unroll
    for (int i = 0; i < 16; i++) {
        int idx = i * 256 + tid;          // 0..4095
        int dl = idx >> 7, c = idx & 127;
        int l = l0 + dl;
        float o = 0.f;
#pragma unroll
        for (int k = 0; k < 3; k++) {
            int base = (b * 3 + k) * 4096 + l;
            int f  = fp[base];
            int cp = min(f + 1, 4095);
            o += xt[((size_t)b * 4096 + f)  * 128 + c] * a0[base]
               + xt[((size_t)b * 4096 + cp) * 128 + c] * a1[base];
        }
        sm[dl][c] = __float2bfloat16_rn(o);
    }
    __syncthreads();
    // torch .view: output stays (B, C, L) flat
#pragma unroll
    for (int i = 0; i < 16; i++) {
        int idx = i * 256 + tid;
        int c = idx >> 5, dl = idx & 31;
        outp[(size_t)b * 524288 + (size_t)c * 4096 + l0 + dl] = sm[dl][c];
    }
}

// ---------------- host launcher ----------------
extern "C" void kernel_launch(void* const* d_in, const int* in_sizes, int n_in,
                              void* d_out, int out_size)
{
    const float* xt    = (const float*)d_in[0];
    const float* hx    = (const float*)d_in[1];
    const float* cx    = (const float*)d_in[2];
    const float* red_w = (const float*)d_in[3];
    const float* red_b = (const float*)d_in[4];
    const float* n1g   = (const float*)d_in[5];
    const float* n1b   = (const float*)d_in[6];
    const float* qkvw  = (const float*)d_in[7];
    const float* qkvb  = (const float*)d_in[8];
    const float* rp    = (const float*)d_in[9];
    const float* pw    = (const float*)d_in[10];
    const float* pb    = (const float*)d_in[11];
    const float* n2g   = (const float*)d_in[12];
    const float* n2b   = (const float*)d_in[13];
    const float* f1w   = (const float*)d_in[14];
    const float* f1b   = (const float*)d_in[15];
    const float* f2w   = (const float*)d_in[16];
    const float* f2b   = (const float*)d_in[17];
    const float* off_w = (const float*)d_in[18];
    const float* off_b = (const float*)d_in[19];
    const float* msk_w = (const float*)d_in[20];
    const float* msk_b = (const float*)d_in[21];
    const float* lf_w  = (const float*)d_in[22];
    const float* lf_b  = (const float*)d_in[23];
    const float* gf_w  = (const float*)d_in[24];
    const float* gf_b  = (const float*)d_in[25];
    const float* ff_w  = (const float*)d_in[26];
    const float* ff_b  = (const float*)d_in[27];

    float *px, *pbig, *patt, *pa0, *pa1;
    bf16 *pbig16, *pxw16, *patt16, *ploc16, *pt16, *px16;
    bf16 *predT, *pqkvT, *ppwT, *pf1T, *pf2T, *plfT, *pgfT, *pffT;
    int* pfp;
    cudaGetSymbolAddress((void**)&px,    d_x);
    cudaGetSymbolAddress((void**)&pbig,  d_big);
    cudaGetSymbolAddress((void**)&patt,  d_att);
    cudaGetSymbolAddress((void**)&pbig16, g_big16);
    cudaGetSymbolAddress((void**)&pxw16, g_xw16);
    cudaGetSymbolAddress((void**)&patt16, g_att16);
    cudaGetSymbolAddress((void**)&ploc16, g_loc16);
    cudaGetSymbolAddress((void**)&pt16,  g_t16);
    cudaGetSymbolAddress((void**)&px16,  g_x16);
    cudaGetSymbolAddress((void**)&pfp,   d_fp);
    cudaGetSymbolAddress((void**)&pa0,   d_a0);
    cudaGetSymbolAddress((void**)&pa1,   d_a1);
    cudaGetSymbolAddress((void**)&predT, g_redT);
    cudaGetSymbolAddress((void**)&pqkvT, g_qkvT);
    cudaGetSymbolAddress((void**)&ppwT,  g_pwT);
    cudaGetSymbolAddress((void**)&pf1T,  g_f1T);
    cudaGetSymbolAddress((void**)&pf2T,  g_f2T);
    cudaGetSymbolAddress((void**)&plfT,  g_lfT);
    cudaGetSymbolAddress((void**)&pgfT,  g_gfT);
    cudaGetSymbolAddress((void**)&pffT,  g_ffT);

    // weight transpose-convert (fp32 KxN -> bf16 NxK)
    WPack wp;
    wp.e[0]  = { red_w,           predT,           256, 128 };
    wp.e[1]  = { qkvw,            pqkvT,           128, 384 };
    wp.e[2]  = { qkvw + 49152,    pqkvT + 49152,   128, 384 };
    wp.e[3]  = { pw,              ppwT,            128, 128 };
    wp.e[4]  = { pw + 16384,      ppwT + 16384,    128, 128 };
    wp.e[5]  = { f1w,             pf1T,            128, 512 };
    wp.e[6]  = { f1w + 65536,     pf1T + 65536,    128, 512 };
    wp.e[7]  = { f2w,             pf2T,            512, 128 };
    wp.e[8]  = { f2w + 65536,     pf2T + 65536,    512, 128 };
    wp.e[9]  = { lf_w,            plfT,            128, 128 };
    wp.e[10] = { gf_w,            pgfT,            128, 128 };
    wp.e[11] = { ff_w,            pffT,            128, 128 };
    wconv_k<<<dim3(48, 12), 256>>>(wp);

    // local (deformable) branch
    offmask_k<<<Bn * Ln / 8, 256>>>(xt, off_w, off_b, msk_w, msk_b, pfp, pa0, pa1);
    deform_k<<<Bn * 128, 256>>>(xt, pfp, pa0, pa1, ploc16);

    // global branch: concat then reduce GEMM (K=256)
    concat_k<<<BL * 64 / 256, 256>>>(xt, hx, pbig16);
    gemm_tc<M_PLAIN><<<dim3(1, 256), 256>>>(pbig16, predT, red_b, nullptr,
                                            px, nullptr, 128, 256, 0);

    for (int i = 0; i < 2; i++) {
        int shift = i ? 4 : 0;
        ln_k<<<BL / 8, 256>>>(px, n1g + i * 128, n1b + i * 128, pxw16, 1, shift);
        gemm_tc<M_PLAIN><<<dim3(3, 256), 256>>>(pxw16, pqkvT + i * 49152, qkvb + i * 384,
                                                nullptr, pbig, nullptr, 384, 128, 0);
        attn_k<<<2048, 256>>>(pbig, rp + i * 900, patt16, shift);
        gemm_tc<M_PERMRES><<<dim3(1, 256), 256>>>(patt16, ppwT + i * 16384, pb + i * 128,
                                                  px, px, nullptr, 128, 128, shift);
        ln_k<<<BL / 8, 256>>>(px, n2g + i * 128, n2b + i * 128, pxw16, 0, 0);
        gemm_tc<M_GELU><<<dim3(4, 256), 256>>>(pxw16, pf1T + i * 65536, f1b + i * 512,
                                               nullptr, nullptr, pbig16, 512, 128, 0);
        gemm_tc<M_RES><<<dim3(1, 256), 256>>>(pbig16, pf2T + i * 65536, f2b + i * 128,
                                              px, px, (i == 1) ? px16 : nullptr,
                                              128, 512, 0);
    }

    // fusion + LSTM gate
    gemm_tc<M_PLAIN><<<dim3(1, 256), 256>>>(ploc16, plfT, lf_b, nullptr,
                                            patt, nullptr, 128, 128, 0);
    gemm_tc<M_MULRELU><<<dim3(1, 256), 256>>>(px16, pgfT, gf_b, patt,
                                              nullptr, pt16, 128, 128, 0);
    gemm_tc<M_GATE><<<dim3(1, 256), 256>>>(pt16, pffT, ff_b, cx,
                                           (float*)d_out, nullptr, 128, 128, 0);
}

// round 8
// speedup vs baseline: 3.8999x; 1.7839x over previous
#include <cuda_runtime.h>
#include <cuda_bf16.h>
#include <math.h>

// Problem constants
#define Bn   8
#define Ln   4096
#define Cn   128
#define BL   32768            // B*L rows

typedef unsigned int u32;
typedef unsigned long long u64;
typedef __nv_bfloat16 bf16;

// ---------------- helpers ----------------
__device__ __forceinline__ u32 smem_u32(const void* p) {
    u32 a;
    asm("{ .reg .u64 t; cvta.to.shared.u64 t, %1; cvt.u32.u64 %0, t; }" : "=r"(a) : "l"(p));
    return a;
}
__device__ __forceinline__ void cp16(u32 dst, const void* src) {
    size_t g = __cvta_generic_to_global(src);
    asm volatile("cp.async.cg.shared.global [%0], [%1], 16;" :: "r"(dst), "l"(g));
}
__device__ __forceinline__ void ldm_x4(u32& r0, u32& r1, u32& r2, u32& r3, u32 addr) {
    asm volatile("ldmatrix.sync.aligned.m8n8.x4.shared.b16 {%0,%1,%2,%3}, [%4];"
                 : "=r"(r0), "=r"(r1), "=r"(r2), "=r"(r3) : "r"(addr));
}
__device__ __forceinline__ void ldmt_x4(u32& r0, u32& r1, u32& r2, u32& r3, u32 addr) {
    asm volatile("ldmatrix.sync.aligned.m8n8.x4.trans.shared.b16 {%0,%1,%2,%3}, [%4];"
                 : "=r"(r0), "=r"(r1), "=r"(r2), "=r"(r3) : "r"(addr));
}
__device__ __forceinline__ u32 bf2(float a, float b) {
    __nv_bfloat162 h;
    h.x = __float2bfloat16_rn(a);
    h.y = __float2bfloat16_rn(b);
    return *(u32*)&h;
}
__device__ __forceinline__ void mma_bf(float* c, const u32* a, u32 b0, u32 b1) {
    asm volatile(
        "mma.sync.aligned.m16n8k16.row.col.f32.bf16.bf16.f32 "
        "{%0,%1,%2,%3},{%4,%5,%6,%7},{%8,%9},{%0,%1,%2,%3};"
        : "+f"(c[0]), "+f"(c[1]), "+f"(c[2]), "+f"(c[3])
        : "r"(a[0]), "r"(a[1]), "r"(a[2]), "r"(a[3]), "r"(b0), "r"(b1));
}

// ---------------- scratch (device globals; no allocs allowed) ----------------
__device__ float d_x   [BL * Cn];      // running stream (fp32)
__device__ float d_att [BL * Cn];      // lf output (fusion multiplier, fp32)
__device__ bf16  g_big16[BL * 512];    // concat input / qkv / MLP hidden (bf16)
__device__ bf16  g_xw16 [BL * Cn];     // LN output (bf16)
__device__ bf16  g_att16[BL * Cn];     // attention out (bf16)
__device__ bf16  g_loc16[BL * Cn];     // deform out (bf16, (B,C,L) flat)
__device__ bf16  g_t16  [BL * Cn];     // mulrelu out (bf16)
__device__ bf16  g_x16  [BL * Cn];     // final g (bf16)
__device__ int   d_fp [Bn * 3 * Ln];
__device__ float d_a0 [Bn * 3 * Ln];
__device__ float d_a1 [Bn * 3 * Ln];
// transposed bf16 weights (N x K row-major)
__device__ bf16  g_redT[128 * 256];
__device__ bf16  g_qkvT[2 * 384 * 128];
__device__ bf16  g_pwT [2 * 128 * 128];
__device__ bf16  g_f1T [2 * 512 * 128];
__device__ bf16  g_f2T [2 * 128 * 512];
__device__ bf16  g_lfT [128 * 128];
__device__ bf16  g_gfT [128 * 128];
__device__ bf16  g_ffT [128 * 128];

// window-layout row m  <->  token index (b*L + ho*64 + wo)
__device__ __forceinline__ int win_to_token(int m, int shift) {
    int n    = m & 63;
    int bw   = m >> 6;
    int widx = bw & 63;
    int b    = bw >> 6;
    int wh = widx >> 3, ww = widx & 7;
    int r = n >> 3, s = n & 7;
    int ho = (wh * 8 + r + shift) & 63;
    int wo = (ww * 8 + s + shift) & 63;
    return (b << 12) + (ho << 6) + wo;
}

// ---------------- weight transpose-convert: (K x N fp32) -> (N x K bf16) ----------------
struct WEnt { const float* src; bf16* dst; int K; int N; };
struct WPack { WEnt e[12]; };

__global__ void __launch_bounds__(256) wconv_k(WPack p) {
    WEnt w = p.e[blockIdx.y];
    int total = w.K * w.N;
    for (int i = blockIdx.x * 256 + threadIdx.x; i < total; i += gridDim.x * 256) {
        int n = i / w.K, k = i - n * w.K;
        w.dst[i] = __float2bfloat16_rn(w.src[(size_t)k * w.N + n]);
    }
}

// ---------------- bf16 tensor-core GEMM: 128x128 tile, K-tile 32, 4-stage pipeline --------
enum { M_PLAIN = 0, M_GELU, M_RES, M_PERMRES, M_MULRELU, M_GATE };

#define TSTRIDE 40            // 32 k halfs + 8 pad (80 B rows)
#define STG_HALFS 10240       // per stage: A 5120 halfs + B 5120 halfs (20480 B)
#define GEMM_SMEM (4 * STG_HALFS * 2)   // 81920 B

template <int MODE>
__global__ void __launch_bounds__(256, 2) gemm_tc(
    const bf16* __restrict__ A, const bf16* __restrict__ BT,
    const float* __restrict__ bias, const float* __restrict__ extra,
    float* __restrict__ C, bf16* __restrict__ C16,
    int N, int K, int shift)
{
    extern __shared__ bf16 smg[];
    int tid = threadIdx.x;
    int lane = tid & 31, warp = tid >> 5;
    int warp_m = warp & 1, warp_n = warp >> 1;    // 2 (M) x 4 (N)
    int m0 = blockIdx.y << 7, n0 = blockIdx.x << 7;
    int r = lane >> 2, c = lane & 3;

    float acc[4][4][4];
#pragma unroll
    for (int i = 0; i < 4; i++)
#pragma unroll
        for (int j = 0; j < 4; j++)
#pragma unroll
            for (int q = 0; q < 4; q++) acc[i][j][q] = 0.f;

    auto prefetch = [&](int k0, int s) {
        u32 abase = smem_u32(smg + s * STG_HALFS);
        u32 bbase = abase + 5120 * 2;
#pragma unroll
        for (int i = 0; i < 2; i++) {
            int ch = tid + (i << 8);              // 0..511
            int rr = ch >> 2, cc = (ch & 3) << 3; // row, 16B chunk offset
            cp16(abase + (u32)(rr * TSTRIDE + cc) * 2,
                 A + (size_t)(m0 + rr) * K + k0 + cc);
            cp16(bbase + (u32)(rr * TSTRIDE + cc) * 2,
                 BT + (size_t)(n0 + rr) * K + k0 + cc);
        }
        asm volatile("cp.async.commit_group;");
    };

    int lrow = lane & 15;
    int lcol = (lane >> 4) << 3;                 // 0 or 8 halfs

    int ntk = K >> 5;
    prefetch(0, 0);
    if (ntk > 1) prefetch(32, 1);
    for (int t = 0; t < ntk; t++) {
        if (t + 2 < ntk) prefetch((t + 2) << 5, (t + 2) & 3);
        if (t < ntk - 2)       asm volatile("cp.async.wait_group 2;");
        else if (t == ntk - 2) asm volatile("cp.async.wait_group 1;");
        else                   asm volatile("cp.async.wait_group 0;");
        __syncthreads();

        u32 abase = smem_u32(smg + (t & 3) * STG_HALFS);
        u32 bbase = abase + 5120 * 2;
#pragma unroll
        for (int ks = 0; ks < 2; ks++) {
            u32 af[4][4];
#pragma unroll
            for (int mt = 0; mt < 4; mt++)
                ldm_x4(af[mt][0], af[mt][1], af[mt][2], af[mt][3],
                       abase + (u32)((warp_m * 64 + mt * 16 + lrow) * TSTRIDE + ks * 16 + lcol) * 2);
            u32 bfr[2][4];
#pragma unroll
            for (int p = 0; p < 2; p++)
                ldm_x4(bfr[p][0], bfr[p][1], bfr[p][2], bfr[p][3],
                       bbase + (u32)((warp_n * 32 + p * 16 + lrow) * TSTRIDE + ks * 16 + lcol) * 2);
#pragma unroll
            for (int p = 0; p < 2; p++)
#pragma unroll
                for (int q = 0; q < 2; q++) {
                    int nt2 = p * 2 + q;
                    u32 b0 = bfr[p][q], b1 = bfr[p][q + 2];
#pragma unroll
                    for (int mt = 0; mt < 4; mt++)
                        mma_bf(acc[mt][nt2], af[mt], b0, b1);
                }
        }
    }

    // epilogue
#pragma unroll
    for (int mt = 0; mt < 4; mt++) {
        int row0 = m0 + warp_m * 64 + mt * 16 + r;
#pragma unroll
        for (int half = 0; half < 2; half++) {
            int row = row0 + half * 8;
            int dst = (MODE == M_PERMRES) ? win_to_token(row, shift) : row;
#pragma unroll
            for (int nt2 = 0; nt2 < 4; nt2++) {
                int col = n0 + warp_n * 32 + nt2 * 8 + c * 2;
                float v0 = acc[mt][nt2][half * 2 + 0] + bias[col];
                float v1 = acc[mt][nt2][half * 2 + 1] + bias[col + 1];
                size_t off = (size_t)dst * N + col;
                if (MODE == M_GELU) {
                    v0 = 0.5f * v0 * (1.f + erff(v0 * 0.70710678118654752f));
                    v1 = 0.5f * v1 * (1.f + erff(v1 * 0.70710678118654752f));
                } else if (MODE == M_RES || MODE == M_PERMRES) {
                    float2 e = *(const float2*)&extra[off];
                    v0 += e.x; v1 += e.y;
                } else if (MODE == M_MULRELU) {
                    float2 e = *(const float2*)&extra[off];
                    float t0 = e.x * v0, t1 = e.y * v1;
                    v0 = t0 > 0.f ? t0 : 0.f;
                    v1 = t1 > 0.f ? t1 : 0.f;
                } else if (MODE == M_GATE) {
                    float2 e = *(const float2*)&extra[off];
                    float g0 = 1.f / (1.f + expf(-v0));
                    float g1 = 1.f / (1.f + expf(-v1));
                    float cy0 = g0 * (e.x + tanhf(v0));
                    float cy1 = g1 * (e.y + tanhf(v1));
                    v0 = g0 * tanhf(cy0);
                    v1 = g1 * tanhf(cy1);
                }
                if (C)   *(float2*)&C[off] = make_float2(v0, v1);
                if (C16) *(u32*)&C16[off]  = bf2(v0, v1);
            }
        }
    }
}

// ---------------- concat + bf16 (reduce GEMM input) ----------------
__global__ void __launch_bounds__(256) concat_k(
    const float* __restrict__ xt, const float* __restrict__ hx, bf16* __restrict__ dst)
{
    int g = blockIdx.x * 256 + threadIdx.x;    // float4 id over BL*64
    int row = g >> 6, q = g & 63;
    const float* src = (q < 32) ? xt + (size_t)row * 128 + (q << 2)
                                : hx + (size_t)row * 128 + ((q - 32) << 2);
    float4 v = *(const float4*)src;
    uint2 o = make_uint2(bf2(v.x, v.y), bf2(v.z, v.w));
    *(uint2*)(dst + (size_t)row * 256 + (q << 2)) = o;
}

// ---------------- LayerNorm (warp per row) -> bf16, optional window gather ----------------
__global__ void __launch_bounds__(256) ln_k(
    const float* __restrict__ x, const float* __restrict__ gamma,
    const float* __restrict__ beta, bf16* __restrict__ y,
    int permute, int shift)
{
    int warp = threadIdx.x >> 5, lane = threadIdx.x & 31;
    int row = (blockIdx.x << 3) + warp;
    int src = permute ? win_to_token(row, shift) : row;
    float4 v = *((const float4*)(x + (size_t)src * 128) + lane);
    float s  = v.x + v.y + v.z + v.w;
    float ss = v.x * v.x + v.y * v.y + v.z * v.z + v.w * v.w;
#pragma unroll
    for (int o = 16; o > 0; o >>= 1) {
        s  += __shfl_xor_sync(0xffffffffu, s,  o);
        ss += __shfl_xor_sync(0xffffffffu, ss, o);
    }
    float mu  = s * 0.0078125f;
    float var = ss * 0.0078125f - mu * mu;
    float rs  = rsqrtf(var + 1e-5f);
    float4 g4 = *((const float4*)gamma + lane);
    float4 b4 = *((const float4*)beta  + lane);
    uint2 o2;
    o2.x = bf2((v.x - mu) * rs * g4.x + b4.x, (v.y - mu) * rs * g4.y + b4.y);
    o2.y = bf2((v.z - mu) * rs * g4.z + b4.z, (v.w - mu) * rs * g4.w + b4.w);
    *((uint2*)(y + (size_t)row * 128) + lane) = o2;
}

// ---------------- tensor-core window attention ----------------
// block = 1 window (512 blocks), 8 warps: warp = head*2 + (32-row half)
#define ATT_STRIDE 136    // 128 d halfs + 8 pad (272 B rows)
#define ATT_SMEM   (3 * 64 * ATT_STRIDE * 2 + 900 * 4)

__global__ void __launch_bounds__(256) attn5(
    const bf16* __restrict__ qkv, const float* __restrict__ rp,
    bf16* __restrict__ out, int shift)
{
    extern __shared__ char smr[];
    bf16* qs = (bf16*)smr;
    bf16* ks = qs + 64 * ATT_STRIDE;
    bf16* vs = ks + 64 * ATT_STRIDE;
    float* rps = (float*)(vs + 64 * ATT_STRIDE);
    int tid = threadIdx.x;
    int lane = tid & 31, warp = tid >> 5;
    int bw = blockIdx.x;
    const float SCALE = 0.17677669529663687f;   // 1/sqrt(32)

    const bf16* base = qkv + (size_t)bw * 64 * 384;
#pragma unroll
    for (int i = 0; i < 12; i++) {
        int idx = tid + i * 256;                 // 0..3071
        int n = idx / 48, part = idx % 48;
        uint4 val = *(const uint4*)(base + (size_t)n * 384 + part * 8);
        bf16* dstp = (part < 16) ? qs : (part < 32) ? ks : vs;
        *(uint4*)&dstp[n * ATT_STRIDE + (part & 15) * 8] = val;
    }
    for (int i = tid; i < 900; i += 256) rps[i] = rp[i];
    __syncthreads();

    int h = warp >> 1;
    int m0 = (warp & 1) * 32;
    int cb = h * 32;
    int lrow = lane & 15;
    int lcol = (lane >> 4) << 3;

    // Q fragments (A operand): [mt][kt]
    u32 aq[2][2][4];
#pragma unroll
    for (int mt = 0; mt < 2; mt++)
#pragma unroll
        for (int kt = 0; kt < 2; kt++)
            ldm_x4(aq[mt][kt][0], aq[mt][kt][1], aq[mt][kt][2], aq[mt][kt][3],
                   smem_u32(&qs[(m0 + 16 * mt + lrow) * ATT_STRIDE + cb + 16 * kt + lcol]));

    // S = Q K^T  (64-col scores per warp-row-half)
    float sacc[2][8][4];
#pragma unroll
    for (int mt = 0; mt < 2; mt++)
#pragma unroll
        for (int nt = 0; nt < 8; nt++)
#pragma unroll
            for (int q = 0; q < 4; q++) sacc[mt][nt][q] = 0.f;

#pragma unroll
    for (int ntp = 0; ntp < 4; ntp++)
#pragma unroll
        for (int kt = 0; kt < 2; kt++) {
            u32 b0, b1, b2, b3;
            ldm_x4(b0, b1, b2, b3,
                   smem_u32(&ks[(16 * ntp + lrow) * ATT_STRIDE + cb + 16 * kt + lcol]));
#pragma unroll
            for (int mt = 0; mt < 2; mt++) {
                mma_bf(sacc[mt][2 * ntp],     aq[mt][kt], b0, b2);
                mma_bf(sacc[mt][2 * ntp + 1], aq[mt][kt], b1, b3);
            }
        }

    // scale + rel-pos bias + shift mask (element coords known analytically)
    int widx = bw & 63;
    int wh = widx >> 3, ww = widx & 7;
#pragma unroll
    for (int mt = 0; mt < 2; mt++)
#pragma unroll
        for (int q = 0; q < 4; q++) {
            int t1 = m0 + 16 * mt + (lane >> 2) + ((q >> 1) << 3);
            int r1 = t1 >> 3, s1 = t1 & 7;
            int h1 = wh * 8 + r1, w1 = ww * 8 + s1;
            int img1 = (h1 < 56 ? 0 : (h1 < 60 ? 1 : 2)) * 3 + (w1 < 56 ? 0 : (w1 < 60 ? 1 : 2));
#pragma unroll
            for (int nt = 0; nt < 8; nt++) {
                int t2 = nt * 8 + 2 * (lane & 3) + (q & 1);
                int r2 = t2 >> 3, s2 = t2 & 7;
                float v = sacc[mt][nt][q] * SCALE
                        + rps[((r1 - r2 + 7) * 15 + (s1 - s2 + 7)) * 4 + h];
                if (shift) {
                    int h2 = wh * 8 + r2, w2 = ww * 8 + s2;
                    int img2 = (h2 < 56 ? 0 : (h2 < 60 ? 1 : 2)) * 3 + (w2 < 56 ? 0 : (w2 < 60 ? 1 : 2));
                    if (img1 != img2) v -= 100.f;
                }
                sacc[mt][nt][q] = v;
            }
        }

    // softmax per row (row = (mt, half); 4 quad lanes hold 16 values each)
#pragma unroll
    for (int mt = 0; mt < 2; mt++)
#pragma unroll
        for (int half = 0; half < 2; half++) {
            float mx = -1e30f;
#pragma unroll
            for (int nt = 0; nt < 8; nt++) {
                mx = fmaxf(mx, sacc[mt][nt][2 * half]);
                mx = fmaxf(mx, sacc[mt][nt][2 * half + 1]);
            }
            mx = fmaxf(mx, __shfl_xor_sync(0xffffffffu, mx, 1));
            mx = fmaxf(mx, __shfl_xor_sync(0xffffffffu, mx, 2));
            float sum = 0.f;
#pragma unroll
            for (int nt = 0; nt < 8; nt++) {
#pragma unroll
                for (int qq = 0; qq < 2; qq++) {
                    float e = __expf(sacc[mt][nt][2 * half + qq] - mx);
                    sacc[mt][nt][2 * half + qq] = e;
                    sum += e;
                }
            }
            sum += __shfl_xor_sync(0xffffffffu, sum, 1);
            sum += __shfl_xor_sync(0xffffffffu, sum, 2);
            float inv = 1.f / sum;
#pragma unroll
            for (int nt = 0; nt < 8; nt++) {
                sacc[mt][nt][2 * half] *= inv;
                sacc[mt][nt][2 * half + 1] *= inv;
            }
        }

    // P fragments (A operand) repacked straight from S accumulators
    u32 pa[2][4][4];
#pragma unroll
    for (int mt = 0; mt < 2; mt++)
#pragma unroll
        for (int j = 0; j < 4; j++) {
            pa[mt][j][0] = bf2(sacc[mt][2 * j][0],     sacc[mt][2 * j][1]);
            pa[mt][j][1] = bf2(sacc[mt][2 * j][2],     sacc[mt][2 * j][3]);
            pa[mt][j][2] = bf2(sacc[mt][2 * j + 1][0], sacc[mt][2 * j + 1][1]);
            pa[mt][j][3] = bf2(sacc[mt][2 * j + 1][2], sacc[mt][2 * j + 1][3]);
        }

    // O = P V
    float oacc[2][4][4];
#pragma unroll
    for (int mt = 0; mt < 2; mt++)
#pragma unroll
        for (int nt2 = 0; nt2 < 4; nt2++)
#pragma unroll
            for (int q = 0; q < 4; q++) oacc[mt][nt2][q] = 0.f;

#pragma unroll
    for (int j = 0; j < 4; j++)
#pragma unroll
        for (int ntp = 0; ntp < 2; ntp++) {
            u32 b0, b1, b2, b3;
            ldmt_x4(b0, b1, b2, b3,
                    smem_u32(&vs[(16 * j + lrow) * ATT_STRIDE + cb + 16 * ntp + lcol]));
#pragma unroll
            for (int mt = 0; mt < 2; mt++) {
                mma_bf(oacc[mt][2 * ntp],     pa[mt][j], b0, b1);
                mma_bf(oacc[mt][2 * ntp + 1], pa[mt][j], b2, b3);
            }
        }

    // store O (bf16)
#pragma unroll
    for (int mt = 0; mt < 2; mt++) {
        int row0 = bw * 64 + m0 + 16 * mt + (lane >> 2);
        int col  = cb + 2 * (lane & 3);
#pragma unroll
        for (int nt2 = 0; nt2 < 4; nt2++) {
            *(u32*)&out[(size_t)row0 * 128 + col + nt2 * 8]       = bf2(oacc[mt][nt2][0], oacc[mt][nt2][1]);
            *(u32*)&out[(size_t)(row0 + 8) * 128 + col + nt2 * 8] = bf2(oacc[mt][nt2][2], oacc[mt][nt2][3]);
        }
    }
}

// ---------------- deformable-conv branch ----------------
__global__ void __launch_bounds__(256) offmask_k(
    const float* __restrict__ xt,
    const float* __restrict__ ow, const float* __restrict__ ob,
    const float* __restrict__ mw, const float* __restrict__ mb,
    int* __restrict__ fp, float* __restrict__ a0, float* __restrict__ a1)
{
    int warp = threadIdx.x >> 5, lane = threadIdx.x & 31;
    int bl = blockIdx.x * 8 + warp;
    int b = bl >> 12, l = bl & 4095;
    int c0 = lane << 2;
    float so[3] = {0.f, 0.f, 0.f}, sm[3] = {0.f, 0.f, 0.f};
#pragma unroll
    for (int j = 0; j < 3; j++) {
        int ll = l + j - 1;
        if (ll < 0 || ll > 4095) continue;
        float4 xv = *((const float4*)(xt + ((size_t)b * 4096 + ll) * 128) + lane);
#pragma unroll
        for (int k = 0; k < 3; k++) {
            const float* owp = ow + k * 384 + j;
            const float* mwp = mw + k * 384 + j;
            so[k] += xv.x * owp[(c0 + 0) * 3] + xv.y * owp[(c0 + 1) * 3]
                   + xv.z * owp[(c0 + 2) * 3] + xv.w * owp[(c0 + 3) * 3];
            sm[k] += xv.x * mwp[(c0 + 0) * 3] + xv.y * mwp[(c0 + 1) * 3]
                   + xv.z * mwp[(c0 + 2) * 3] + xv.w * mwp[(c0 + 3) * 3];
        }
    }
#pragma unroll
    for (int o = 16; o > 0; o >>= 1) {
#pragma unroll
        for (int k = 0; k < 3; k++) {
            so[k] += __shfl_xor_sync(0xffffffffu, so[k], o);
            sm[k] += __shfl_xor_sync(0xffffffffu, sm[k], o);
        }
    }
    if (lane < 3) {
        int k = lane;
        float off = ob[k] + so[k];
        float mk  = mb[k] + sm[k];
        float mask = 1.f / (1.f + expf(-mk));
        float pos = fminf(fmaxf((float)l + off, 0.f), 4095.f);
        float fpf = floorf(pos);
        int f = (int)fpf;
        float alpha = pos - fpf;
        int idx = (b * 3 + k) * 4096 + l;
        fp[idx] = f;
        a0[idx] = (1.f - alpha) * mask;
        a1[idx] = alpha * mask;
    }
}

// block = (b, 32-l tile); coalesced reads + smem-transposed coalesced bf16 writes
__global__ void __launch_bounds__(256) deform_k(
    const float* __restrict__ xt, const int* __restrict__ fp,
    const float* __restrict__ a0, const float* __restrict__ a1,
    bf16* __restrict__ outp)
{
    __shared__ bf16 sm[32][130];
    int b  = blockIdx.x >> 7;
    int l0 = (blockIdx.x & 127) << 5;
    int tid = threadIdx.x;
#pragma unroll
    for (int i = 0; i < 16; i++) {
        int idx = i * 256 + tid;          // 0..4095
        int dl = idx >> 7, c = idx & 127;
        int l = l0 + dl;
        float o = 0.f;
#pragma unroll
        for (int k = 0; k < 3; k++) {
            int base = (b * 3 + k) * 4096 + l;
            int f  = fp[base];
            int cp = min(f + 1, 4095);
            o += xt[((size_t)b * 4096 + f)  * 128 + c] * a0[base]
               + xt[((size_t)b * 4096 + cp) * 128 + c] * a1[base];
        }
        sm[dl][c] = __float2bfloat16_rn(o);
    }
    __syncthreads();
    // torch .view: output stays (B, C, L) flat
#pragma unroll
    for (int i = 0; i < 16; i++) {
        int idx = i * 256 + tid;
        int c = idx >> 5, dl = idx & 31;
        outp[(size_t)b * 524288 + (size_t)c * 4096 + l0 + dl] = sm[dl][c];
    }
}

// ---------------- host launcher ----------------
extern "C" void kernel_launch(void* const* d_in, const int* in_sizes, int n_in,
                              void* d_out, int out_size)
{
    const float* xt    = (const float*)d_in[0];
    const float* hx    = (const float*)d_in[1];
    const float* cx    = (const float*)d_in[2];
    const float* red_w = (const float*)d_in[3];
    const float* red_b = (const float*)d_in[4];
    const float* n1g   = (const float*)d_in[5];
    const float* n1b   = (const float*)d_in[6];
    const float* qkvw  = (const float*)d_in[7];
    const float* qkvb  = (const float*)d_in[8];
    const float* rp    = (const float*)d_in[9];
    const float* pw    = (const float*)d_in[10];
    const float* pb    = (const float*)d_in[11];
    const float* n2g   = (const float*)d_in[12];
    const float* n2b   = (const float*)d_in[13];
    const float* f1w   = (const float*)d_in[14];
    const float* f1b   = (const float*)d_in[15];
    const float* f2w   = (const float*)d_in[16];
    const float* f2b   = (const float*)d_in[17];
    const float* off_w = (const float*)d_in[18];
    const float* off_b = (const float*)d_in[19];
    const float* msk_w = (const float*)d_in[20];
    const float* msk_b = (const float*)d_in[21];
    const float* lf_w  = (const float*)d_in[22];
    const float* lf_b  = (const float*)d_in[23];
    const float* gf_w  = (const float*)d_in[24];
    const float* gf_b  = (const float*)d_in[25];
    const float* ff_w  = (const float*)d_in[26];
    const float* ff_b  = (const float*)d_in[27];

    float *px, *patt, *pa0, *pa1;
    bf16 *pbig16, *pxw16, *patt16, *ploc16, *pt16, *px16;
    bf16 *predT, *pqkvT, *ppwT, *pf1T, *pf2T, *plfT, *pgfT, *pffT;
    int* pfp;
    cudaGetSymbolAddress((void**)&px,    d_x);
    cudaGetSymbolAddress((void**)&patt,  d_att);
    cudaGetSymbolAddress((void**)&pbig16, g_big16);
    cudaGetSymbolAddress((void**)&pxw16, g_xw16);
    cudaGetSymbolAddress((void**)&patt16, g_att16);
    cudaGetSymbolAddress((void**)&ploc16, g_loc16);
    cudaGetSymbolAddress((void**)&pt16,  g_t16);
    cudaGetSymbolAddress((void**)&px16,  g_x16);
    cudaGetSymbolAddress((void**)&pfp,   d_fp);
    cudaGetSymbolAddress((void**)&pa0,   d_a0);
    cudaGetSymbolAddress((void**)&pa1,   d_a1);
    cudaGetSymbolAddress((void**)&predT, g_redT);
    cudaGetSymbolAddress((void**)&pqkvT, g_qkvT);
    cudaGetSymbolAddress((void**)&ppwT,  g_pwT);
    cudaGetSymbolAddress((void**)&pf1T,  g_f1T);
    cudaGetSymbolAddress((void**)&pf2T,  g_f2T);
    cudaGetSymbolAddress((void**)&plfT,  g_lfT);
    cudaGetSymbolAddress((void**)&pgfT,  g_gfT);
    cudaGetSymbolAddress((void**)&pffT,  g_ffT);

    cudaFuncSetAttribute(gemm_tc<M_PLAIN>,   cudaFuncAttributeMaxDynamicSharedMemorySize, GEMM_SMEM);
    cudaFuncSetAttribute(gemm_tc<M_GELU>,    cudaFuncAttributeMaxDynamicSharedMemorySize, GEMM_SMEM);
    cudaFuncSetAttribute(gemm_tc<M_RES>,     cudaFuncAttributeMaxDynamicSharedMemorySize, GEMM_SMEM);
    cudaFuncSetAttribute(gemm_tc<M_PERMRES>, cudaFuncAttributeMaxDynamicSharedMemorySize, GEMM_SMEM);
    cudaFuncSetAttribute(gemm_tc<M_MULRELU>, cudaFuncAttributeMaxDynamicSharedMemorySize, GEMM_SMEM);
    cudaFuncSetAttribute(gemm_tc<M_GATE>,    cudaFuncAttributeMaxDynamicSharedMemorySize, GEMM_SMEM);
    cudaFuncSetAttribute(attn5,              cudaFuncAttributeMaxDynamicSharedMemorySize, ATT_SMEM);

    // weight transpose-convert (fp32 KxN -> bf16 NxK)
    WPack wp;
    wp.e[0]  = { red_w,           predT,           256, 128 };
    wp.e[1]  = { qkvw,            pqkvT,           128, 384 };
    wp.e[2]  = { qkvw + 49152,    pqkvT + 49152,   128, 384 };
    wp.e[3]  = { pw,              ppwT,            128, 128 };
    wp.e[4]  = { pw + 16384,      ppwT + 16384,    128, 128 };
    wp.e[5]  = { f1w,             pf1T,            128, 512 };
    wp.e[6]  = { f1w + 65536,     pf1T + 65536,    128, 512 };
    wp.e[7]  = { f2w,             pf2T,            512, 128 };
    wp.e[8]  = { f2w + 65536,     pf2T + 65536,    512, 128 };
    wp.e[9]  = { lf_w,            plfT,            128, 128 };
    wp.e[10] = { gf_w,            pgfT,            128, 128 };
    wp.e[11] = { ff_w,            pffT,            128, 128 };
    wconv_k<<<dim3(48, 12), 256>>>(wp);

    // local (deformable) branch
    offmask_k<<<Bn * Ln / 8, 256>>>(xt, off_w, off_b, msk_w, msk_b, pfp, pa0, pa1);
    deform_k<<<Bn * 128, 256>>>(xt, pfp, pa0, pa1, ploc16);

    // global branch: concat then reduce GEMM (K=256)
    concat_k<<<BL * 64 / 256, 256>>>(xt, hx, pbig16);
    gemm_tc<M_PLAIN><<<dim3(1, 256), 256, GEMM_SMEM>>>(pbig16, predT, red_b, nullptr,
                                                       px, nullptr, 128, 256, 0);

    for (int i = 0; i < 2; i++) {
        int shift = i ? 4 : 0;
        ln_k<<<BL / 8, 256>>>(px, n1g + i * 128, n1b + i * 128, pxw16, 1, shift);
        // QKV GEMM -> bf16 only (attention consumes bf16 directly)
        gemm_tc<M_PLAIN><<<dim3(3, 256), 256, GEMM_SMEM>>>(pxw16, pqkvT + i * 49152,
                                                           qkvb + i * 384, nullptr,
                                                           nullptr, pbig16, 384, 128, 0);
        attn5<<<512, 256, ATT_SMEM>>>(pbig16, rp + i * 900, patt16, shift);
        gemm_tc<M_PERMRES><<<dim3(1, 256), 256, GEMM_SMEM>>>(patt16, ppwT + i * 16384,
                                                             pb + i * 128, px, px, nullptr,
                                                             128, 128, shift);
        ln_k<<<BL / 8, 256>>>(px, n2g + i * 128, n2b + i * 128, pxw16, 0, 0);
        gemm_tc<M_GELU><<<dim3(4, 256), 256, GEMM_SMEM>>>(pxw16, pf1T + i * 65536,
                                                          f1b + i * 512, nullptr,
                                                          nullptr, pbig16, 512, 128, 0);
        gemm_tc<M_RES><<<dim3(1, 256), 256, GEMM_SMEM>>>(pbig16, pf2T + i * 65536,
                                                         f2b + i * 128, px, px,
                                                         (i == 1) ? px16 : nullptr,
                                                         128, 512, 0);
    }

    // fusion + LSTM gate
    gemm_tc<M_PLAIN><<<dim3(1, 256), 256, GEMM_SMEM>>>(ploc16, plfT, lf_b, nullptr,
                                                       patt, nullptr, 128, 128, 0);
    gemm_tc<M_MULRELU><<<dim3(1, 256), 256, GEMM_SMEM>>>(px16, pgfT, gf_b, patt,
                                                         nullptr, pt16, 128, 128, 0);
    gemm_tc<M_GATE><<<dim3(1, 256), 256, GEMM_SMEM>>>(pt16, pffT, ff_b, cx,
                                                      (float*)d_out, nullptr, 128, 128, 0);
}

// round 9
// speedup vs baseline: 4.1495x; 1.0640x over previous
#include <cuda_runtime.h>
#include <cuda_bf16.h>
#include <math.h>

// Problem constants
#define Bn   8
#define Ln   4096
#define Cn   128
#define BL   32768            // B*L rows

typedef unsigned int u32;
typedef unsigned long long u64;
typedef __nv_bfloat16 bf16;

// ---------------- helpers ----------------
__device__ __forceinline__ u32 smem_u32(const void* p) {
    u32 a;
    asm("{ .reg .u64 t; cvta.to.shared.u64 t, %1; cvt.u32.u64 %0, t; }" : "=r"(a) : "l"(p));
    return a;
}
__device__ __forceinline__ void cp16(u32 dst, const void* src) {
    size_t g = __cvta_generic_to_global(src);
    asm volatile("cp.async.cg.shared.global [%0], [%1], 16;" :: "r"(dst), "l"(g));
}
__device__ __forceinline__ void ldm_x4(u32& r0, u32& r1, u32& r2, u32& r3, u32 addr) {
    asm volatile("ldmatrix.sync.aligned.m8n8.x4.shared.b16 {%0,%1,%2,%3}, [%4];"
                 : "=r"(r0), "=r"(r1), "=r"(r2), "=r"(r3) : "r"(addr));
}
__device__ __forceinline__ void ldmt_x4(u32& r0, u32& r1, u32& r2, u32& r3, u32 addr) {
    asm volatile("ldmatrix.sync.aligned.m8n8.x4.trans.shared.b16 {%0,%1,%2,%3}, [%4];"
                 : "=r"(r0), "=r"(r1), "=r"(r2), "=r"(r3) : "r"(addr));
}
__device__ __forceinline__ u32 bf2(float a, float b) {
    __nv_bfloat162 h;
    h.x = __float2bfloat16_rn(a);
    h.y = __float2bfloat16_rn(b);
    return *(u32*)&h;
}
__device__ __forceinline__ void mma_bf(float* c, const u32* a, u32 b0, u32 b1) {
    asm volatile(
        "mma.sync.aligned.m16n8k16.row.col.f32.bf16.bf16.f32 "
        "{%0,%1,%2,%3},{%4,%5,%6,%7},{%8,%9},{%0,%1,%2,%3};"
        : "+f"(c[0]), "+f"(c[1]), "+f"(c[2]), "+f"(c[3])
        : "r"(a[0]), "r"(a[1]), "r"(a[2]), "r"(a[3]), "r"(b0), "r"(b1));
}

// ---------------- scratch (device globals; no allocs allowed) ----------------
__device__ float d_x   [BL * Cn];      // running stream (fp32)
__device__ float d_att [BL * Cn];      // lf output (fusion multiplier, fp32)
__device__ bf16  g_big16[BL * 512];    // concat input / qkv / MLP hidden (bf16)
__device__ bf16  g_xw16 [BL * Cn];     // LN output (bf16)
__device__ bf16  g_att16[BL * Cn];     // attention out (bf16)
__device__ bf16  g_loc16[BL * Cn];     // deform out (bf16, (B,C,L) flat)
__device__ bf16  g_t16  [BL * Cn];     // mulrelu out (bf16)
__device__ bf16  g_x16  [BL * Cn];     // final g (bf16)
__device__ int   d_fp [Bn * 3 * Ln];
__device__ float d_a0 [Bn * 3 * Ln];
__device__ float d_a1 [Bn * 3 * Ln];
// transposed bf16 weights (N x K row-major)
__device__ bf16  g_redT[128 * 256];
__device__ bf16  g_qkvT[2 * 384 * 128];
__device__ bf16  g_pwT [2 * 128 * 128];
__device__ bf16  g_f1T [2 * 512 * 128];
__device__ bf16  g_f2T [2 * 128 * 512];
__device__ bf16  g_lfT [128 * 128];
__device__ bf16  g_gfT [128 * 128];
__device__ bf16  g_ffT [128 * 128];

// window-layout row m  ->  token index (b*L + ho*64 + wo)
__device__ __forceinline__ int win_to_token(int m, int shift) {
    int n    = m & 63;
    int bw   = m >> 6;
    int widx = bw & 63;
    int b    = bw >> 6;
    int wh = widx >> 3, ww = widx & 7;
    int r = n >> 3, s = n & 7;
    int ho = (wh * 8 + r + shift) & 63;
    int wo = (ww * 8 + s + shift) & 63;
    return (b << 12) + (ho << 6) + wo;
}
// token index -> window-layout row (exact inverse of win_to_token)
__device__ __forceinline__ int token_to_win(int t, int shift) {
    int b = t >> 12, rem = t & 4095;
    int ho = rem >> 6, wo = rem & 63;
    int u = (ho - shift) & 63, v = (wo - shift) & 63;
    int wh = u >> 3, r = u & 7;
    int ww = v >> 3, s = v & 7;
    return (((b << 6) + (wh << 3) + ww) << 6) + (r << 3) + s;
}

// ---------------- weight transpose-convert: (K x N fp32) -> (N x K bf16) ----------------
struct WEnt { const float* src; bf16* dst; int K; int N; };
struct WPack { WEnt e[12]; };

__global__ void __launch_bounds__(256) wconv_k(WPack p) {
    WEnt w = p.e[blockIdx.y];
    int total = w.K * w.N;
    for (int i = blockIdx.x * 256 + threadIdx.x; i < total; i += gridDim.x * 256) {
        int n = i / w.K, k = i - n * w.K;
        w.dst[i] = __float2bfloat16_rn(w.src[(size_t)k * w.N + n]);
    }
}

// ---------------- bf16 tensor-core GEMM: 128x128 tile, K-tile 32, 4-stage pipeline --------
// LN modes fuse a full LayerNorm over each output row (N must be 128).
enum { M_PLAIN = 0, M_GELU, M_RES, M_PERMRES, M_MULRELU, M_GATE,
       M_PLAIN_LN, M_RES_LN, M_PERMRES_LN };

#define TSTRIDE 40            // 32 k halfs + 8 pad (80 B rows)
#define STG_HALFS 10240       // per stage: A 5120 halfs + B 5120 halfs (20480 B)
#define GEMM_SMEM (4 * STG_HALFS * 2)   // 81920 B

template <int MODE>
__global__ void __launch_bounds__(256, 2) gemm_tc(
    const bf16* __restrict__ A, const bf16* __restrict__ BT,
    const float* __restrict__ bias, const float* __restrict__ extra,
    float* __restrict__ C, bf16* __restrict__ C16,
    const float* __restrict__ lng, const float* __restrict__ lnb,
    int N, int K, int shift)
{
    extern __shared__ bf16 smg[];
    int tid = threadIdx.x;
    int lane = tid & 31, warp = tid >> 5;
    int warp_m = warp & 1, warp_n = warp >> 1;    // 2 (M) x 4 (N)
    int m0 = blockIdx.y << 7, n0 = blockIdx.x << 7;
    int r = lane >> 2, c = lane & 3;

    const bool LN = (MODE == M_PLAIN_LN || MODE == M_RES_LN || MODE == M_PERMRES_LN);

    float acc[4][4][4];
#pragma unroll
    for (int i = 0; i < 4; i++)
#pragma unroll
        for (int j = 0; j < 4; j++)
#pragma unroll
            for (int q = 0; q < 4; q++) acc[i][j][q] = 0.f;

    auto prefetch = [&](int k0, int s) {
        u32 abase = smem_u32(smg + s * STG_HALFS);
        u32 bbase = abase + 5120 * 2;
#pragma unroll
        for (int i = 0; i < 2; i++) {
            int ch = tid + (i << 8);              // 0..511
            int rr = ch >> 2, cc = (ch & 3) << 3; // row, 16B chunk offset
            cp16(abase + (u32)(rr * TSTRIDE + cc) * 2,
                 A + (size_t)(m0 + rr) * K + k0 + cc);
            cp16(bbase + (u32)(rr * TSTRIDE + cc) * 2,
                 BT + (size_t)(n0 + rr) * K + k0 + cc);
        }
        asm volatile("cp.async.commit_group;");
    };

    int lrow = lane & 15;
    int lcol = (lane >> 4) << 3;                 // 0 or 8 halfs

    int ntk = K >> 5;
    prefetch(0, 0);
    if (ntk > 1) prefetch(32, 1);
    for (int t = 0; t < ntk; t++) {
        if (t + 2 < ntk) prefetch((t + 2) << 5, (t + 2) & 3);
        if (t < ntk - 2)       asm volatile("cp.async.wait_group 2;");
        else if (t == ntk - 2) asm volatile("cp.async.wait_group 1;");
        else                   asm volatile("cp.async.wait_group 0;");
        __syncthreads();

        u32 abase = smem_u32(smg + (t & 3) * STG_HALFS);
        u32 bbase = abase + 5120 * 2;
#pragma unroll
        for (int ks = 0; ks < 2; ks++) {
            u32 af[4][4];
#pragma unroll
            for (int mt = 0; mt < 4; mt++)
                ldm_x4(af[mt][0], af[mt][1], af[mt][2], af[mt][3],
                       abase + (u32)((warp_m * 64 + mt * 16 + lrow) * TSTRIDE + ks * 16 + lcol) * 2);
            u32 bfr[2][4];
#pragma unroll
            for (int p = 0; p < 2; p++)
                ldm_x4(bfr[p][0], bfr[p][1], bfr[p][2], bfr[p][3],
                       bbase + (u32)((warp_n * 32 + p * 16 + lrow) * TSTRIDE + ks * 16 + lcol) * 2);
#pragma unroll
            for (int p = 0; p < 2; p++)
#pragma unroll
                for (int q = 0; q < 2; q++) {
                    int nt2 = p * 2 + q;
                    u32 b0 = bfr[p][q], b1 = bfr[p][q + 2];
#pragma unroll
                    for (int mt = 0; mt < 4; mt++)
                        mma_bf(acc[mt][nt2], af[mt], b0, b1);
                }
        }
    }

    if (!LN) {
        // plain epilogue
#pragma unroll
        for (int mt = 0; mt < 4; mt++) {
            int row0 = m0 + warp_m * 64 + mt * 16 + r;
#pragma unroll
            for (int half = 0; half < 2; half++) {
                int row = row0 + half * 8;
                int dst = (MODE == M_PERMRES) ? win_to_token(row, shift) : row;
#pragma unroll
                for (int nt2 = 0; nt2 < 4; nt2++) {
                    int col = n0 + warp_n * 32 + nt2 * 8 + c * 2;
                    float v0 = acc[mt][nt2][half * 2 + 0] + bias[col];
                    float v1 = acc[mt][nt2][half * 2 + 1] + bias[col + 1];
                    size_t off = (size_t)dst * N + col;
                    if (MODE == M_GELU) {
                        v0 = 0.5f * v0 * (1.f + erff(v0 * 0.70710678118654752f));
                        v1 = 0.5f * v1 * (1.f + erff(v1 * 0.70710678118654752f));
                    } else if (MODE == M_RES || MODE == M_PERMRES) {
                        float2 e = *(const float2*)&extra[off];
                        v0 += e.x; v1 += e.y;
                    } else if (MODE == M_MULRELU) {
                        float2 e = *(const float2*)&extra[off];
                        float t0 = e.x * v0, t1 = e.y * v1;
                        v0 = t0 > 0.f ? t0 : 0.f;
                        v1 = t1 > 0.f ? t1 : 0.f;
                    } else if (MODE == M_GATE) {
                        float2 e = *(const float2*)&extra[off];
                        float g0 = 1.f / (1.f + expf(-v0));
                        float g1 = 1.f / (1.f + expf(-v1));
                        float cy0 = g0 * (e.x + tanhf(v0));
                        float cy1 = g1 * (e.y + tanhf(v1));
                        v0 = g0 * tanhf(cy0);
                        v1 = g1 * tanhf(cy1);
                    }
                    if (C)   *(float2*)&C[off] = make_float2(v0, v1);
                    if (C16) *(u32*)&C16[off]  = bf2(v0, v1);
                }
            }
        }
        return;
    }

    // ---- fused-LN epilogue (N == 128) ----
    float rsum[4][2], rsq[4][2];
#pragma unroll
    for (int mt = 0; mt < 4; mt++) {
        int row0 = m0 + warp_m * 64 + mt * 16 + r;
#pragma unroll
        for (int half = 0; half < 2; half++) {
            int row = row0 + half * 8;
            int dst = (MODE == M_PERMRES_LN) ? win_to_token(row, shift) : row;
            float s = 0.f, sq = 0.f;
#pragma unroll
            for (int nt2 = 0; nt2 < 4; nt2++) {
                int col = n0 + warp_n * 32 + nt2 * 8 + c * 2;
                float v0 = acc[mt][nt2][half * 2 + 0] + bias[col];
                float v1 = acc[mt][nt2][half * 2 + 1] + bias[col + 1];
                if (MODE == M_RES_LN || MODE == M_PERMRES_LN) {
                    float2 e = *(const float2*)&extra[(size_t)dst * 128 + col];
                    v0 += e.x; v1 += e.y;
                }
                acc[mt][nt2][half * 2 + 0] = v0;
                acc[mt][nt2][half * 2 + 1] = v1;
                s += v0 + v1; sq += v0 * v0 + v1 * v1;
            }
            s  += __shfl_xor_sync(0xffffffffu, s, 1);
            s  += __shfl_xor_sync(0xffffffffu, s, 2);
            sq += __shfl_xor_sync(0xffffffffu, sq, 1);
            sq += __shfl_xor_sync(0xffffffffu, sq, 2);
            rsum[mt][half] = s; rsq[mt][half] = sq;
        }
    }
    __syncthreads();                       // mainloop smem reads done everywhere
    float* part = (float*)smg;             // [128 rows][4 warp_n][2]
    if ((lane & 3) == 0) {
#pragma unroll
        for (int mt = 0; mt < 4; mt++)
#pragma unroll
            for (int half = 0; half < 2; half++) {
                int rowloc = warp_m * 64 + mt * 16 + (lane >> 2) + half * 8;
                part[rowloc * 8 + warp_n * 2 + 0] = rsum[mt][half];
                part[rowloc * 8 + warp_n * 2 + 1] = rsq[mt][half];
            }
    }
    __syncthreads();
#pragma unroll
    for (int mt = 0; mt < 4; mt++) {
#pragma unroll
        for (int half = 0; half < 2; half++) {
            int rowloc = warp_m * 64 + mt * 16 + r + half * 8;
            float s  = part[rowloc * 8] + part[rowloc * 8 + 2]
                     + part[rowloc * 8 + 4] + part[rowloc * 8 + 6];
            float sq = part[rowloc * 8 + 1] + part[rowloc * 8 + 3]
                     + part[rowloc * 8 + 5] + part[rowloc * 8 + 7];
            float mu = s * 0.0078125f;
            float var = sq * 0.0078125f - mu * mu;
            float rstd = rsqrtf(var + 1e-5f);
            int row = m0 + rowloc;
            int xdst, wdst;
            if (MODE == M_PERMRES_LN) { xdst = win_to_token(row, shift); wdst = xdst; }
            else                      { xdst = row; wdst = token_to_win(row, shift); }
#pragma unroll
            for (int nt2 = 0; nt2 < 4; nt2++) {
                int col = n0 + warp_n * 32 + nt2 * 8 + c * 2;
                float v0 = acc[mt][nt2][half * 2 + 0];
                float v1 = acc[mt][nt2][half * 2 + 1];
                *(float2*)&C[(size_t)xdst * 128 + col] = make_float2(v0, v1);
                float w0 = (v0 - mu) * rstd * lng[col]     + lnb[col];
                float w1 = (v1 - mu) * rstd * lng[col + 1] + lnb[col + 1];
                *(u32*)&C16[(size_t)wdst * 128 + col] = bf2(w0, w1);
            }
        }
    }
}

// ---------------- concat + bf16 (reduce GEMM input) ----------------
__global__ void __launch_bounds__(256) concat_k(
    const float* __restrict__ xt, const float* __restrict__ hx, bf16* __restrict__ dst)
{
#pragma unroll
    for (int it = 0; it < 2; it++) {
        int g = (blockIdx.x * 256 + threadIdx.x) * 2 + it;   // float4 id over BL*64
        int row = g >> 6, q = g & 63;
        const float* src = (q < 32) ? xt + (size_t)row * 128 + (q << 2)
                                    : hx + (size_t)row * 128 + ((q - 32) << 2);
        float4 v = *(const float4*)src;
        uint2 o = make_uint2(bf2(v.x, v.y), bf2(v.z, v.w));
        *(uint2*)(dst + (size_t)row * 256 + (q << 2)) = o;
    }
}

// ---------------- tensor-core window attention ----------------
// block = 1 window (512 blocks), 8 warps: warp = head*2 + (32-row half)
#define ATT_STRIDE 136    // 128 d halfs + 8 pad (272 B rows)
#define ATT_SMEM   (3 * 64 * ATT_STRIDE * 2 + 900 * 4)

__global__ void __launch_bounds__(256) attn5(
    const bf16* __restrict__ qkv, const float* __restrict__ rp,
    bf16* __restrict__ out, int shift)
{
    extern __shared__ char smr[];
    bf16* qs = (bf16*)smr;
    bf16* ks = qs + 64 * ATT_STRIDE;
    bf16* vs = ks + 64 * ATT_STRIDE;
    float* rps = (float*)(vs + 64 * ATT_STRIDE);
    int tid = threadIdx.x;
    int lane = tid & 31, warp = tid >> 5;
    int bw = blockIdx.x;
    const float SCALE = 0.17677669529663687f;   // 1/sqrt(32)

    const bf16* base = qkv + (size_t)bw * 64 * 384;
#pragma unroll
    for (int i = 0; i < 12; i++) {
        int idx = tid + i * 256;                 // 0..3071
        int n = idx / 48, part = idx % 48;
        uint4 val = *(const uint4*)(base + (size_t)n * 384 + part * 8);
        bf16* dstp = (part < 16) ? qs : (part < 32) ? ks : vs;
        *(uint4*)&dstp[n * ATT_STRIDE + (part & 15) * 8] = val;
    }
    for (int i = tid; i < 900; i += 256) rps[i] = rp[i];
    __syncthreads();

    int h = warp >> 1;
    int m0 = (warp & 1) * 32;
    int cb = h * 32;
    int lrow = lane & 15;
    int lcol = (lane >> 4) << 3;

    u32 aq[2][2][4];
#pragma unroll
    for (int mt = 0; mt < 2; mt++)
#pragma unroll
        for (int kt = 0; kt < 2; kt++)
            ldm_x4(aq[mt][kt][0], aq[mt][kt][1], aq[mt][kt][2], aq[mt][kt][3],
                   smem_u32(&qs[(m0 + 16 * mt + lrow) * ATT_STRIDE + cb + 16 * kt + lcol]));

    float sacc[2][8][4];
#pragma unroll
    for (int mt = 0; mt < 2; mt++)
#pragma unroll
        for (int nt = 0; nt < 8; nt++)
#pragma unroll
            for (int q = 0; q < 4; q++) sacc[mt][nt][q] = 0.f;

#pragma unroll
    for (int ntp = 0; ntp < 4; ntp++)
#pragma unroll
        for (int kt = 0; kt < 2; kt++) {
            u32 b0, b1, b2, b3;
            ldm_x4(b0, b1, b2, b3,
                   smem_u32(&ks[(16 * ntp + lrow) * ATT_STRIDE + cb + 16 * kt + lcol]));
#pragma unroll
            for (int mt = 0; mt < 2; mt++) {
                mma_bf(sacc[mt][2 * ntp],     aq[mt][kt], b0, b2);
                mma_bf(sacc[mt][2 * ntp + 1], aq[mt][kt], b1, b3);
            }
        }

    int widx = bw & 63;
    int wh = widx >> 3, ww = widx & 7;
#pragma unroll
    for (int mt = 0; mt < 2; mt++)
#pragma unroll
        for (int q = 0; q < 4; q++) {
            int t1 = m0 + 16 * mt + (lane >> 2) + ((q >> 1) << 3);
            int r1 = t1 >> 3, s1 = t1 & 7;
            int h1 = wh * 8 + r1, w1 = ww * 8 + s1;
            int img1 = (h1 < 56 ? 0 : (h1 < 60 ? 1 : 2)) * 3 + (w1 < 56 ? 0 : (w1 < 60 ? 1 : 2));
#pragma unroll
            for (int nt = 0; nt < 8; nt++) {
                int t2 = nt * 8 + 2 * (lane & 3) + (q & 1);
                int r2 = t2 >> 3, s2 = t2 & 7;
                float v = sacc[mt][nt][q] * SCALE
                        + rps[((r1 - r2 + 7) * 15 + (s1 - s2 + 7)) * 4 + h];
                if (shift) {
                    int h2 = wh * 8 + r2, w2 = ww * 8 + s2;
                    int img2 = (h2 < 56 ? 0 : (h2 < 60 ? 1 : 2)) * 3 + (w2 < 56 ? 0 : (w2 < 60 ? 1 : 2));
                    if (img1 != img2) v -= 100.f;
                }
                sacc[mt][nt][q] = v;
            }
        }

#pragma unroll
    for (int mt = 0; mt < 2; mt++)
#pragma unroll
        for (int half = 0; half < 2; half++) {
            float mx = -1e30f;
#pragma unroll
            for (int nt = 0; nt < 8; nt++) {
                mx = fmaxf(mx, sacc[mt][nt][2 * half]);
                mx = fmaxf(mx, sacc[mt][nt][2 * half + 1]);
            }
            mx = fmaxf(mx, __shfl_xor_sync(0xffffffffu, mx, 1));
            mx = fmaxf(mx, __shfl_xor_sync(0xffffffffu, mx, 2));
            float sum = 0.f;
#pragma unroll
            for (int nt = 0; nt < 8; nt++) {
#pragma unroll
                for (int qq = 0; qq < 2; qq++) {
                    float e = __expf(sacc[mt][nt][2 * half + qq] - mx);
                    sacc[mt][nt][2 * half + qq] = e;
                    sum += e;
                }
            }
            sum += __shfl_xor_sync(0xffffffffu, sum, 1);
            sum += __shfl_xor_sync(0xffffffffu, sum, 2);
            float inv = 1.f / sum;
#pragma unroll
            for (int nt = 0; nt < 8; nt++) {
                sacc[mt][nt][2 * half] *= inv;
                sacc[mt][nt][2 * half + 1] *= inv;
            }
        }

    u32 pa[2][4][4];
#pragma unroll
    for (int mt = 0; mt < 2; mt++)
#pragma unroll
        for (int j = 0; j < 4; j++) {
            pa[mt][j][0] = bf2(sacc[mt][2 * j][0],     sacc[mt][2 * j][1]);
            pa[mt][j][1] = bf2(sacc[mt][2 * j][2],     sacc[mt][2 * j][3]);
            pa[mt][j][2] = bf2(sacc[mt][2 * j + 1][0], sacc[mt][2 * j + 1][1]);
            pa[mt][j][3] = bf2(sacc[mt][2 * j + 1][2], sacc[mt][2 * j + 1][3]);
        }

    float oacc[2][4][4];
#pragma unroll
    for (int mt = 0; mt < 2; mt++)
#pragma unroll
        for (int nt2 = 0; nt2 < 4; nt2++)
#pragma unroll
            for (int q = 0; q < 4; q++) oacc[mt][nt2][q] = 0.f;

#pragma unroll
    for (int j = 0; j < 4; j++)
#pragma unroll
        for (int ntp = 0; ntp < 2; ntp++) {
            u32 b0, b1, b2, b3;
            ldmt_x4(b0, b1, b2, b3,
                    smem_u32(&vs[(16 * j + lrow) * ATT_STRIDE + cb + 16 * ntp + lcol]));
#pragma unroll
            for (int mt = 0; mt < 2; mt++) {
                mma_bf(oacc[mt][2 * ntp],     pa[mt][j], b0, b1);
                mma_bf(oacc[mt][2 * ntp + 1], pa[mt][j], b2, b3);
            }
        }

#pragma unroll
    for (int mt = 0; mt < 2; mt++) {
        int row0 = bw * 64 + m0 + 16 * mt + (lane >> 2);
        int col  = cb + 2 * (lane & 3);
#pragma unroll
        for (int nt2 = 0; nt2 < 4; nt2++) {
            *(u32*)&out[(size_t)row0 * 128 + col + nt2 * 8]       = bf2(oacc[mt][nt2][0], oacc[mt][nt2][1]);
            *(u32*)&out[(size_t)(row0 + 8) * 128 + col + nt2 * 8] = bf2(oacc[mt][nt2][2], oacc[mt][nt2][3]);
        }
    }
}

// ---------------- deformable-conv branch ----------------
// block = (b, 32 tokens): stage 34 x-rows + conv weights in smem, warp computes 4 tokens
__global__ void __launch_bounds__(256) offmask_k(
    const float* __restrict__ xt,
    const float* __restrict__ ow, const float* __restrict__ ob,
    const float* __restrict__ mw, const float* __restrict__ mb,
    int* __restrict__ fp, float* __restrict__ a0, float* __restrict__ a1)
{
    __shared__ float rows[34][128];
    __shared__ float wo_s[1152], wm_s[1152];
    int b  = blockIdx.x >> 7;
    int l0 = (blockIdx.x & 127) << 5;
    int tid = threadIdx.x;
    int warp = tid >> 5, lane = tid & 31;

    for (int i = tid; i < 1152; i += 256) { wo_s[i] = ow[i]; wm_s[i] = mw[i]; }
#pragma unroll
    for (int i = 0; i < 5; i++) {
        int idx = i * 256 + tid;             // float4 ids, need 34*32 = 1088
        if (idx < 1088) {
            int rr = idx >> 5, c4 = (idx & 31) << 2;
            int l = l0 - 1 + rr;
            if (l >= 0 && l < 4096)
                *(float4*)&rows[rr][c4] = *(const float4*)(xt + ((size_t)b * 4096 + l) * 128 + c4);
        }
    }
    __syncthreads();

    int c0 = lane << 2;
#pragma unroll
    for (int it = 0; it < 4; it++) {
        int tl = warp * 4 + it;              // local token 0..31
        int l = l0 + tl;
        float so[3] = {0.f, 0.f, 0.f}, sm[3] = {0.f, 0.f, 0.f};
#pragma unroll
        for (int j = 0; j < 3; j++) {
            int ll = l + j - 1;
            if (ll < 0 || ll > 4095) continue;
            float4 xv = *(const float4*)&rows[tl + j][c0];
#pragma unroll
            for (int k = 0; k < 3; k++) {
                const float* owp = wo_s + k * 384 + j;
                const float* mwp = wm_s + k * 384 + j;
                so[k] += xv.x * owp[(c0 + 0) * 3] + xv.y * owp[(c0 + 1) * 3]
                       + xv.z * owp[(c0 + 2) * 3] + xv.w * owp[(c0 + 3) * 3];
                sm[k] += xv.x * mwp[(c0 + 0) * 3] + xv.y * mwp[(c0 + 1) * 3]
                       + xv.z * mwp[(c0 + 2) * 3] + xv.w * mwp[(c0 + 3) * 3];
            }
        }
#pragma unroll
        for (int o = 16; o > 0; o >>= 1) {
#pragma unroll
            for (int k = 0; k < 3; k++) {
                so[k] += __shfl_xor_sync(0xffffffffu, so[k], o);
                sm[k] += __shfl_xor_sync(0xffffffffu, sm[k], o);
            }
        }
        if (lane < 3) {
            int k = lane;
            float off = ob[k] + so[k];
            float mk  = mb[k] + sm[k];
            float mask = 1.f / (1.f + expf(-mk));
            float pos = fminf(fmaxf((float)l + off, 0.f), 4095.f);
            float fpf = floorf(pos);
            int f = (int)fpf;
            float alpha = pos - fpf;
            int idx = (b * 3 + k) * 4096 + l;
            fp[idx] = f;
            a0[idx] = (1.f - alpha) * mask;
            a1[idx] = alpha * mask;
        }
    }
}

// block = (b, 32-l tile); coalesced reads + smem-transposed coalesced bf16 writes
__global__ void __launch_bounds__(256) deform_k(
    const float* __restrict__ xt, const int* __restrict__ fp,
    const float* __restrict__ a0, const float* __restrict__ a1,
    bf16* __restrict__ outp)
{
    __shared__ bf16 sm[32][130];
    int b  = blockIdx.x >> 7;
    int l0 = (blockIdx.x & 127) << 5;
    int tid = threadIdx.x;
#pragma unroll
    for (int i = 0; i < 16; i++) {
        int idx = i * 256 + tid;          // 0..4095
        int dl = idx >> 7, c = idx & 127;
        int l = l0 + dl;
        float o = 0.f;
#pragma unroll
        for (int k = 0; k < 3; k++) {
            int base = (b * 3 + k) * 4096 + l;
            int f  = fp[base];
            int cp = min(f + 1, 4095);
            o += xt[((size_t)b * 4096 + f)  * 128 + c] * a0[base]
               + xt[((size_t)b * 4096 + cp) * 128 + c] * a1[base];
        }
        sm[dl][c] = __float2bfloat16_rn(o);
    }
    __syncthreads();
    // torch .view: output stays (B, C, L) flat
#pragma unroll
    for (int i = 0; i < 16; i++) {
        int idx = i * 256 + tid;
        int c = idx >> 5, dl = idx & 31;
        outp[(size_t)b * 524288 + (size_t)c * 4096 + l0 + dl] = sm[dl][c];
    }
}

// ---------------- host launcher ----------------
extern "C" void kernel_launch(void* const* d_in, const int* in_sizes, int n_in,
                              void* d_out, int out_size)
{
    const float* xt    = (const float*)d_in[0];
    const float* hx    = (const float*)d_in[1];
    const float* cx    = (const float*)d_in[2];
    const float* red_w = (const float*)d_in[3];
    const float* red_b = (const float*)d_in[4];
    const float* n1g   = (const float*)d_in[5];
    const float* n1b   = (const float*)d_in[6];
    const float* qkvw  = (const float*)d_in[7];
    const float* qkvb  = (const float*)d_in[8];
    const float* rp    = (const float*)d_in[9];
    const float* pw    = (const float*)d_in[10];
    const float* pb    = (const float*)d_in[11];
    const float* n2g   = (const float*)d_in[12];
    const float* n2b   = (const float*)d_in[13];
    const float* f1w   = (const float*)d_in[14];
    const float* f1b   = (const float*)d_in[15];
    const float* f2w   = (const float*)d_in[16];
    const float* f2b   = (const float*)d_in[17];
    const float* off_w = (const float*)d_in[18];
    const float* off_b = (const float*)d_in[19];
    const float* msk_w = (const float*)d_in[20];
    const float* msk_b = (const float*)d_in[21];
    const float* lf_w  = (const float*)d_in[22];
    const float* lf_b  = (const float*)d_in[23];
    const float* gf_w  = (const float*)d_in[24];
    const float* gf_b  = (const float*)d_in[25];
    const float* ff_w  = (const float*)d_in[26];
    const float* ff_b  = (const float*)d_in[27];

    float *px, *patt, *pa0, *pa1;
    bf16 *pbig16, *pxw16, *patt16, *ploc16, *pt16, *px16;
    bf16 *predT, *pqkvT, *ppwT, *pf1T, *pf2T, *plfT, *pgfT, *pffT;
    int* pfp;
    cudaGetSymbolAddress((void**)&px,    d_x);
    cudaGetSymbolAddress((void**)&patt,  d_att);
    cudaGetSymbolAddress((void**)&pbig16, g_big16);
    cudaGetSymbolAddress((void**)&pxw16, g_xw16);
    cudaGetSymbolAddress((void**)&patt16, g_att16);
    cudaGetSymbolAddress((void**)&ploc16, g_loc16);
    cudaGetSymbolAddress((void**)&pt16,  g_t16);
    cudaGetSymbolAddress((void**)&px16,  g_x16);
    cudaGetSymbolAddress((void**)&pfp,   d_fp);
    cudaGetSymbolAddress((void**)&pa0,   d_a0);
    cudaGetSymbolAddress((void**)&pa1,   d_a1);
    cudaGetSymbolAddress((void**)&predT, g_redT);
    cudaGetSymbolAddress((void**)&pqkvT, g_qkvT);
    cudaGetSymbolAddress((void**)&ppwT,  g_pwT);
    cudaGetSymbolAddress((void**)&pf1T,  g_f1T);
    cudaGetSymbolAddress((void**)&pf2T,  g_f2T);
    cudaGetSymbolAddress((void**)&plfT,  g_lfT);
    cudaGetSymbolAddress((void**)&pgfT,  g_gfT);
    cudaGetSymbolAddress((void**)&pffT,  g_ffT);

    cudaFuncSetAttribute(gemm_tc<M_PLAIN>,      cudaFuncAttributeMaxDynamicSharedMemorySize, GEMM_SMEM);
    cudaFuncSetAttribute(gemm_tc<M_GELU>,       cudaFuncAttributeMaxDynamicSharedMemorySize, GEMM_SMEM);
    cudaFuncSetAttribute(gemm_tc<M_RES>,        cudaFuncAttributeMaxDynamicSharedMemorySize, GEMM_SMEM);
    cudaFuncSetAttribute(gemm_tc<M_MULRELU>,    cudaFuncAttributeMaxDynamicSharedMemorySize, GEMM_SMEM);
    cudaFuncSetAttribute(gemm_tc<M_GATE>,       cudaFuncAttributeMaxDynamicSharedMemorySize, GEMM_SMEM);
    cudaFuncSetAttribute(gemm_tc<M_PLAIN_LN>,   cudaFuncAttributeMaxDynamicSharedMemorySize, GEMM_SMEM);
    cudaFuncSetAttribute(gemm_tc<M_RES_LN>,     cudaFuncAttributeMaxDynamicSharedMemorySize, GEMM_SMEM);
    cudaFuncSetAttribute(gemm_tc<M_PERMRES_LN>, cudaFuncAttributeMaxDynamicSharedMemorySize, GEMM_SMEM);
    cudaFuncSetAttribute(attn5,                 cudaFuncAttributeMaxDynamicSharedMemorySize, ATT_SMEM);

    // weight transpose-convert (fp32 KxN -> bf16 NxK)
    WPack wp;
    wp.e[0]  = { red_w,           predT,           256, 128 };
    wp.e[1]  = { qkvw,            pqkvT,           128, 384 };
    wp.e[2]  = { qkvw + 49152,    pqkvT + 49152,   128, 384 };
    wp.e[3]  = { pw,              ppwT,            128, 128 };
    wp.e[4]  = { pw + 16384,      ppwT + 16384,    128, 128 };
    wp.e[5]  = { f1w,             pf1T,            128, 512 };
    wp.e[6]  = { f1w + 65536,     pf1T + 65536,    128, 512 };
    wp.e[7]  = { f2w,             pf2T,            512, 128 };
    wp.e[8]  = { f2w + 65536,     pf2T + 65536,    512, 128 };
    wp.e[9]  = { lf_w,            plfT,            128, 128 };
    wp.e[10] = { gf_w,            pgfT,            128, 128 };
    wp.e[11] = { ff_w,            pffT,            128, 128 };
    wconv_k<<<dim3(48, 12), 256>>>(wp);

    // local (deformable) branch
    offmask_k<<<Bn * 128, 256>>>(xt, off_w, off_b, msk_w, msk_b, pfp, pa0, pa1);
    deform_k<<<Bn * 128, 256>>>(xt, pfp, pa0, pa1, ploc16);

    // global branch: concat then reduce GEMM (K=256) + fused LN1(block0, shift 0)
    concat_k<<<BL * 64 / 512, 256>>>(xt, hx, pbig16);
    gemm_tc<M_PLAIN_LN><<<dim3(1, 256), 256, GEMM_SMEM>>>(
        pbig16, predT, red_b, nullptr, px, pxw16, n1g, n1b, 128, 256, 0);

    for (int i = 0; i < 2; i++) {
        int shift = i ? 4 : 0;
        // QKV GEMM (A = window-ordered LN output)
        gemm_tc<M_PLAIN><<<dim3(3, 256), 256, GEMM_SMEM>>>(
            pxw16, pqkvT + i * 49152, qkvb + i * 384, nullptr,
            nullptr, pbig16, nullptr, nullptr, 384, 128, 0);
        attn5<<<512, 256, ATT_SMEM>>>(pbig16, rp + i * 900, patt16, shift);
        // proj + window-reverse residual + fused LN2 (token order)
        gemm_tc<M_PERMRES_LN><<<dim3(1, 256), 256, GEMM_SMEM>>>(
            patt16, ppwT + i * 16384, pb + i * 128, px,
            px, pxw16, n2g + i * 128, n2b + i * 128, 128, 128, shift);
        gemm_tc<M_GELU><<<dim3(4, 256), 256, GEMM_SMEM>>>(
            pxw16, pf1T + i * 65536, f1b + i * 512, nullptr,
            nullptr, pbig16, nullptr, nullptr, 512, 128, 0);
        if (i == 0) {
            // f2 + residual + fused LN1(block1, shift 4 window scatter)
            gemm_tc<M_RES_LN><<<dim3(1, 256), 256, GEMM_SMEM>>>(
                pbig16, pf2T, f2b, px,
                px, pxw16, n1g + 128, n1b + 128, 128, 512, 4);
        } else {
            gemm_tc<M_RES><<<dim3(1, 256), 256, GEMM_SMEM>>>(
                pbig16, pf2T + 65536, f2b + 128, px,
                px, px16, nullptr, nullptr, 128, 512, 0);
        }
    }

    // fusion + LSTM gate
    gemm_tc<M_PLAIN><<<dim3(1, 256), 256, GEMM_SMEM>>>(
        ploc16, plfT, lf_b, nullptr, patt, nullptr, nullptr, nullptr, 128, 128, 0);
    gemm_tc<M_MULRELU><<<dim3(1, 256), 256, GEMM_SMEM>>>(
        px16, pgfT, gf_b, patt, nullptr, pt16, nullptr, nullptr, 128, 128, 0);
    gemm_tc<M_GATE><<<dim3(1, 256), 256, GEMM_SMEM>>>(
        pt16, pffT, ff_b, cx, (float*)d_out, nullptr, nullptr, nullptr, 128, 128, 0);
}

// round 10
// speedup vs baseline: 4.1706x; 1.0051x over previous
#include <cuda_runtime.h>
#include <cuda_bf16.h>
#include <math.h>

// Problem constants
#define Bn   8
#define Ln   4096
#define Cn   128
#define BL   32768            // B*L rows

typedef unsigned int u32;
typedef unsigned long long u64;
typedef __nv_bfloat16 bf16;

// ---------------- helpers ----------------
__device__ __forceinline__ u32 smem_u32(const void* p) {
    u32 a;
    asm("{ .reg .u64 t; cvta.to.shared.u64 t, %1; cvt.u32.u64 %0, t; }" : "=r"(a) : "l"(p));
    return a;
}
__device__ __forceinline__ void cp16(u32 dst, const void* src) {
    size_t g = __cvta_generic_to_global(src);
    asm volatile("cp.async.cg.shared.global [%0], [%1], 16;" :: "r"(dst), "l"(g));
}
__device__ __forceinline__ void ldm_x4(u32& r0, u32& r1, u32& r2, u32& r3, u32 addr) {
    asm volatile("ldmatrix.sync.aligned.m8n8.x4.shared.b16 {%0,%1,%2,%3}, [%4];"
                 : "=r"(r0), "=r"(r1), "=r"(r2), "=r"(r3) : "r"(addr));
}
__device__ __forceinline__ void ldmt_x4(u32& r0, u32& r1, u32& r2, u32& r3, u32 addr) {
    asm volatile("ldmatrix.sync.aligned.m8n8.x4.trans.shared.b16 {%0,%1,%2,%3}, [%4];"
                 : "=r"(r0), "=r"(r1), "=r"(r2), "=r"(r3) : "r"(addr));
}
__device__ __forceinline__ u32 bf2(float a, float b) {
    __nv_bfloat162 h;
    h.x = __float2bfloat16_rn(a);
    h.y = __float2bfloat16_rn(b);
    return *(u32*)&h;
}
__device__ __forceinline__ void mma_bf(float* c, const u32* a, u32 b0, u32 b1) {
    asm volatile(
        "mma.sync.aligned.m16n8k16.row.col.f32.bf16.bf16.f32 "
        "{%0,%1,%2,%3},{%4,%5,%6,%7},{%8,%9},{%0,%1,%2,%3};"
        : "+f"(c[0]), "+f"(c[1]), "+f"(c[2]), "+f"(c[3])
        : "r"(a[0]), "r"(a[1]), "r"(a[2]), "r"(a[3]), "r"(b0), "r"(b1));
}

// ---------------- scratch (device globals; no allocs allowed) ----------------
__device__ float d_x   [BL * Cn];      // running stream (fp32)
__device__ bf16  g_big16[BL * 512];    // concat input / qkv / MLP hidden (bf16)
__device__ bf16  g_xw16 [BL * Cn];     // LN output (bf16)
__device__ bf16  g_att16[BL * Cn];     // attention out (bf16)
__device__ bf16  g_loc16[BL * Cn];     // deform out (bf16, (B,C,L) flat)
__device__ bf16  g_x16  [BL * Cn];     // final g (bf16)
// transposed bf16 weights (N x K row-major)
__device__ bf16  g_redT[128 * 256];
__device__ bf16  g_qkvT[2 * 384 * 128];
__device__ bf16  g_pwT [2 * 128 * 128];
__device__ bf16  g_f1T [2 * 512 * 128];
__device__ bf16  g_f2T [2 * 128 * 512];
__device__ bf16  g_lfT [128 * 128];
__device__ bf16  g_gfT [128 * 128];
__device__ bf16  g_ffT [128 * 128];

// window-layout row m  ->  token index (b*L + ho*64 + wo)
__device__ __forceinline__ int win_to_token(int m, int shift) {
    int n    = m & 63;
    int bw   = m >> 6;
    int widx = bw & 63;
    int b    = bw >> 6;
    int wh = widx >> 3, ww = widx & 7;
    int r = n >> 3, s = n & 7;
    int ho = (wh * 8 + r + shift) & 63;
    int wo = (ww * 8 + s + shift) & 63;
    return (b << 12) + (ho << 6) + wo;
}
// token index -> window-layout row (exact inverse)
__device__ __forceinline__ int token_to_win(int t, int shift) {
    int b = t >> 12, rem = t & 4095;
    int ho = rem >> 6, wo = rem & 63;
    int u = (ho - shift) & 63, v = (wo - shift) & 63;
    int wh = u >> 3, r = u & 7;
    int ww = v >> 3, s = v & 7;
    return (((b << 6) + (wh << 3) + ww) << 6) + (r << 3) + s;
}

// ---------------- weight transpose-convert: (K x N fp32) -> (N x K bf16) ----------------
struct WEnt { const float* src; bf16* dst; int K; int N; };
struct WPack { WEnt e[12]; };

__global__ void __launch_bounds__(256) wconv_k(WPack p) {
    WEnt w = p.e[blockIdx.y];
    int total = w.K * w.N;
    for (int i = blockIdx.x * 256 + threadIdx.x; i < total; i += gridDim.x * 256) {
        int n = i / w.K, k = i - n * w.K;
        w.dst[i] = __float2bfloat16_rn(w.src[(size_t)k * w.N + n]);
    }
}

// ---------------- bf16 tensor-core GEMM: 128x128 tile, K-tile 32, 4-stage pipeline --------
enum { M_PLAIN = 0, M_GELU, M_RES, M_PERMRES,
       M_PLAIN_LN, M_RES_LN, M_PERMRES_LN };

#define TSTRIDE 40            // 32 k halfs + 8 pad (80 B rows)
#define STG_HALFS 10240       // per stage: A 5120 halfs + B 5120 halfs (20480 B)
#define GEMM_SMEM (4 * STG_HALFS * 2)   // 81920 B

template <int MODE>
__global__ void __launch_bounds__(256, 2) gemm_tc(
    const bf16* __restrict__ A, const bf16* __restrict__ BT,
    const float* __restrict__ bias, const float* __restrict__ extra,
    float* __restrict__ C, bf16* __restrict__ C16,
    const float* __restrict__ lng, const float* __restrict__ lnb,
    int N, int K, int shift)
{
    extern __shared__ bf16 smg[];
    int tid = threadIdx.x;
    int lane = tid & 31, warp = tid >> 5;
    int warp_m = warp & 1, warp_n = warp >> 1;    // 2 (M) x 4 (N)
    int m0 = blockIdx.y << 7, n0 = blockIdx.x << 7;
    int r = lane >> 2, c = lane & 3;

    const bool LN = (MODE == M_PLAIN_LN || MODE == M_RES_LN || MODE == M_PERMRES_LN);

    float acc[4][4][4];
#pragma unroll
    for (int i = 0; i < 4; i++)
#pragma unroll
        for (int j = 0; j < 4; j++)
#pragma unroll
            for (int q = 0; q < 4; q++) acc[i][j][q] = 0.f;

    auto prefetch = [&](int k0, int s) {
        u32 abase = smem_u32(smg + s * STG_HALFS);
        u32 bbase = abase + 5120 * 2;
#pragma unroll
        for (int i = 0; i < 2; i++) {
            int ch = tid + (i << 8);              // 0..511
            int rr = ch >> 2, cc = (ch & 3) << 3; // row, 16B chunk offset
            cp16(abase + (u32)(rr * TSTRIDE + cc) * 2,
                 A + (size_t)(m0 + rr) * K + k0 + cc);
            cp16(bbase + (u32)(rr * TSTRIDE + cc) * 2,
                 BT + (size_t)(n0 + rr) * K + k0 + cc);
        }
        asm volatile("cp.async.commit_group;");
    };

    int lrow = lane & 15;
    int lcol = (lane >> 4) << 3;                 // 0 or 8 halfs

    int ntk = K >> 5;
    prefetch(0, 0);
    if (ntk > 1) prefetch(32, 1);
    for (int t = 0; t < ntk; t++) {
        if (t + 2 < ntk) prefetch((t + 2) << 5, (t + 2) & 3);
        if (t < ntk - 2)       asm volatile("cp.async.wait_group 2;");
        else if (t == ntk - 2) asm volatile("cp.async.wait_group 1;");
        else                   asm volatile("cp.async.wait_group 0;");
        __syncthreads();

        u32 abase = smem_u32(smg + (t & 3) * STG_HALFS);
        u32 bbase = abase + 5120 * 2;
#pragma unroll
        for (int ks = 0; ks < 2; ks++) {
            u32 af[4][4];
#pragma unroll
            for (int mt = 0; mt < 4; mt++)
                ldm_x4(af[mt][0], af[mt][1], af[mt][2], af[mt][3],
                       abase + (u32)((warp_m * 64 + mt * 16 + lrow) * TSTRIDE + ks * 16 + lcol) * 2);
            u32 bfr[2][4];
#pragma unroll
            for (int p = 0; p < 2; p++)
                ldm_x4(bfr[p][0], bfr[p][1], bfr[p][2], bfr[p][3],
                       bbase + (u32)((warp_n * 32 + p * 16 + lrow) * TSTRIDE + ks * 16 + lcol) * 2);
#pragma unroll
            for (int p = 0; p < 2; p++)
#pragma unroll
                for (int q = 0; q < 2; q++) {
                    int nt2 = p * 2 + q;
                    u32 b0 = bfr[p][q], b1 = bfr[p][q + 2];
#pragma unroll
                    for (int mt = 0; mt < 4; mt++)
                        mma_bf(acc[mt][nt2], af[mt], b0, b1);
                }
        }
    }

    if (!LN) {
#pragma unroll
        for (int mt = 0; mt < 4; mt++) {
            int row0 = m0 + warp_m * 64 + mt * 16 + r;
#pragma unroll
            for (int half = 0; half < 2; half++) {
                int row = row0 + half * 8;
                int dst = (MODE == M_PERMRES) ? win_to_token(row, shift) : row;
#pragma unroll
                for (int nt2 = 0; nt2 < 4; nt2++) {
                    int col = n0 + warp_n * 32 + nt2 * 8 + c * 2;
                    float v0 = acc[mt][nt2][half * 2 + 0] + bias[col];
                    float v1 = acc[mt][nt2][half * 2 + 1] + bias[col + 1];
                    size_t off = (size_t)dst * N + col;
                    if (MODE == M_GELU) {
                        v0 = 0.5f * v0 * (1.f + erff(v0 * 0.70710678118654752f));
                        v1 = 0.5f * v1 * (1.f + erff(v1 * 0.70710678118654752f));
                    } else if (MODE == M_RES || MODE == M_PERMRES) {
                        float2 e = *(const float2*)&extra[off];
                        v0 += e.x; v1 += e.y;
                    }
                    if (C)   *(float2*)&C[off] = make_float2(v0, v1);
                    if (C16) *(u32*)&C16[off]  = bf2(v0, v1);
                }
            }
        }
        return;
    }

    // ---- fused-LN epilogue (N == 128) ----
    float rsum[4][2], rsq[4][2];
#pragma unroll
    for (int mt = 0; mt < 4; mt++) {
        int row0 = m0 + warp_m * 64 + mt * 16 + r;
#pragma unroll
        for (int half = 0; half < 2; half++) {
            int row = row0 + half * 8;
            int dst = (MODE == M_PERMRES_LN) ? win_to_token(row, shift) : row;
            float s = 0.f, sq = 0.f;
#pragma unroll
            for (int nt2 = 0; nt2 < 4; nt2++) {
                int col = n0 + warp_n * 32 + nt2 * 8 + c * 2;
                float v0 = acc[mt][nt2][half * 2 + 0] + bias[col];
                float v1 = acc[mt][nt2][half * 2 + 1] + bias[col + 1];
                if (MODE == M_RES_LN || MODE == M_PERMRES_LN) {
                    float2 e = *(const float2*)&extra[(size_t)dst * 128 + col];
                    v0 += e.x; v1 += e.y;
                }
                acc[mt][nt2][half * 2 + 0] = v0;
                acc[mt][nt2][half * 2 + 1] = v1;
                s += v0 + v1; sq += v0 * v0 + v1 * v1;
            }
            s  += __shfl_xor_sync(0xffffffffu, s, 1);
            s  += __shfl_xor_sync(0xffffffffu, s, 2);
            sq += __shfl_xor_sync(0xffffffffu, sq, 1);
            sq += __shfl_xor_sync(0xffffffffu, sq, 2);
            rsum[mt][half] = s; rsq[mt][half] = sq;
        }
    }
    __syncthreads();
    float* part = (float*)smg;             // [128 rows][4 warp_n][2]
    if ((lane & 3) == 0) {
#pragma unroll
        for (int mt = 0; mt < 4; mt++)
#pragma unroll
            for (int half = 0; half < 2; half++) {
                int rowloc = warp_m * 64 + mt * 16 + (lane >> 2) + half * 8;
                part[rowloc * 8 + warp_n * 2 + 0] = rsum[mt][half];
                part[rowloc * 8 + warp_n * 2 + 1] = rsq[mt][half];
            }
    }
    __syncthreads();
#pragma unroll
    for (int mt = 0; mt < 4; mt++) {
#pragma unroll
        for (int half = 0; half < 2; half++) {
            int rowloc = warp_m * 64 + mt * 16 + r + half * 8;
            float s  = part[rowloc * 8] + part[rowloc * 8 + 2]
                     + part[rowloc * 8 + 4] + part[rowloc * 8 + 6];
            float sq = part[rowloc * 8 + 1] + part[rowloc * 8 + 3]
                     + part[rowloc * 8 + 5] + part[rowloc * 8 + 7];
            float mu = s * 0.0078125f;
            float var = sq * 0.0078125f - mu * mu;
            float rstd = rsqrtf(var + 1e-5f);
            int row = m0 + rowloc;
            int xdst, wdst;
            if (MODE == M_PERMRES_LN) { xdst = win_to_token(row, shift); wdst = xdst; }
            else                      { xdst = row; wdst = token_to_win(row, shift); }
#pragma unroll
            for (int nt2 = 0; nt2 < 4; nt2++) {
                int col = n0 + warp_n * 32 + nt2 * 8 + c * 2;
                float v0 = acc[mt][nt2][half * 2 + 0];
                float v1 = acc[mt][nt2][half * 2 + 1];
                *(float2*)&C[(size_t)xdst * 128 + col] = make_float2(v0, v1);
                float w0 = (v0 - mu) * rstd * lng[col]     + lnb[col];
                float w1 = (v1 - mu) * rstd * lng[col + 1] + lnb[col + 1];
                *(u32*)&C16[(size_t)wdst * 128 + col] = bf2(w0, w1);
            }
        }
    }
}

// ---------------- fused fusion + LSTM gate kernel ----------------
// One CTA per 128-row tile: t = relu((loc@lf+b)*(g@gf+b)); out = gate(t@ff+b, cx)
// K=128 for all three mainloops; 4 stages hold all 4 k-tiles at once.

__device__ __forceinline__ void ml_k128(
    bf16* smg, const bf16* A, const bf16* BT, int m0,
    int tid, int warp_m, int warp_n, int lrow, int lcol,
    float (&acc)[4][4][4])
{
    __syncthreads();   // previous smem users done
#pragma unroll
    for (int s = 0; s < 4; s++) {
        u32 abase = smem_u32(smg + s * STG_HALFS);
        u32 bbase = abase + 5120 * 2;
#pragma unroll
        for (int i = 0; i < 2; i++) {
            int ch = tid + (i << 8);
            int rr = ch >> 2, cc = (ch & 3) << 3;
            cp16(abase + (u32)(rr * TSTRIDE + cc) * 2,
                 A + (size_t)(m0 + rr) * 128 + s * 32 + cc);
            cp16(bbase + (u32)(rr * TSTRIDE + cc) * 2,
                 BT + (size_t)rr * 128 + s * 32 + cc);
        }
    }
    asm volatile("cp.async.commit_group;");
    asm volatile("cp.async.wait_group 0;");
    __syncthreads();
#pragma unroll
    for (int t = 0; t < 4; t++) {
        u32 abase = smem_u32(smg + t * STG_HALFS);
        u32 bbase = abase + 5120 * 2;
#pragma unroll
        for (int ks = 0; ks < 2; ks++) {
            u32 af[4][4];
#pragma unroll
            for (int mt = 0; mt < 4; mt++)
                ldm_x4(af[mt][0], af[mt][1], af[mt][2], af[mt][3],
                       abase + (u32)((warp_m * 64 + mt * 16 + lrow) * TSTRIDE + ks * 16 + lcol) * 2);
            u32 bfr[2][4];
#pragma unroll
            for (int p = 0; p < 2; p++)
                ldm_x4(bfr[p][0], bfr[p][1], bfr[p][2], bfr[p][3],
                       bbase + (u32)((warp_n * 32 + p * 16 + lrow) * TSTRIDE + ks * 16 + lcol) * 2);
#pragma unroll
            for (int p = 0; p < 2; p++)
#pragma unroll
                for (int q = 0; q < 2; q++) {
                    int nt2 = p * 2 + q;
#pragma unroll
                    for (int mt = 0; mt < 4; mt++)
                        mma_bf(acc[mt][nt2], af[mt], bfr[p][q], bfr[p][q + 2]);
                }
        }
    }
}

__global__ void __launch_bounds__(256, 1) fusion_k(
    const bf16* __restrict__ g16, const bf16* __restrict__ loc16,
    const bf16* __restrict__ gfT, const bf16* __restrict__ lfT,
    const bf16* __restrict__ ffT,
    const float* __restrict__ gf_b, const float* __restrict__ lf_b,
    const float* __restrict__ ff_b,
    const float* __restrict__ cx, float* __restrict__ outp)
{
    extern __shared__ bf16 smg[];
    int tid = threadIdx.x;
    int lane = tid & 31, warp = tid >> 5;
    int warp_m = warp & 1, warp_n = warp >> 1;
    int m0 = blockIdx.x << 7;
    int r = lane >> 2, c = lane & 3;
    int lrow = lane & 15;
    int lcol = (lane >> 4) << 3;

    float acc1[4][4][4], acc2[4][4][4];
#pragma unroll
    for (int i = 0; i < 4; i++)
#pragma unroll
        for (int j = 0; j < 4; j++)
#pragma unroll
            for (int q = 0; q < 4; q++) { acc1[i][j][q] = 0.f; acc2[i][j][q] = 0.f; }

    // ML1: g @ gfT
    ml_k128(smg, g16, gfT, m0, tid, warp_m, warp_n, lrow, lcol, acc1);
    // ML2: loc @ lfT
    ml_k128(smg, loc16, lfT, m0, tid, warp_m, warp_n, lrow, lcol, acc2);

    __syncthreads();   // all ML2 smem reads done before t overwrites stages
    // t = relu((acc2+lf_b)*(acc1+gf_b)) -> stage A regions (kt = warp_n), ldmatrix layout
    {
        u32 abase = smem_u32(smg + warp_n * STG_HALFS);
#pragma unroll
        for (int mt = 0; mt < 4; mt++)
#pragma unroll
            for (int half = 0; half < 2; half++) {
                int row = warp_m * 64 + mt * 16 + r + half * 8;
#pragma unroll
                for (int nt2 = 0; nt2 < 4; nt2++) {
                    int cc = nt2 * 8 + c * 2;          // 0..31 within this k-tile
                    int col = warp_n * 32 + cc;
                    float a0 = acc1[mt][nt2][half * 2 + 0] + gf_b[col];
                    float a1 = acc1[mt][nt2][half * 2 + 1] + gf_b[col + 1];
                    float b0 = acc2[mt][nt2][half * 2 + 0] + lf_b[col];
                    float b1 = acc2[mt][nt2][half * 2 + 1] + lf_b[col + 1];
                    float t0 = a0 * b0, t1 = a1 * b1;
                    t0 = t0 > 0.f ? t0 : 0.f;
                    t1 = t1 > 0.f ? t1 : 0.f;
                    u32 pkv = bf2(t0, t1);
                    asm volatile("st.shared.b32 [%0], %1;"
                                 :: "r"(abase + (u32)(row * TSTRIDE + cc) * 2), "r"(pkv));
                }
            }
    }
    // prefetch ffT into stage B regions
#pragma unroll
    for (int s = 0; s < 4; s++) {
        u32 bbase = smem_u32(smg + s * STG_HALFS) + 5120 * 2;
#pragma unroll
        for (int i = 0; i < 2; i++) {
            int ch = tid + (i << 8);
            int rr = ch >> 2, cc = (ch & 3) << 3;
            cp16(bbase + (u32)(rr * TSTRIDE + cc) * 2,
                 ffT + (size_t)rr * 128 + s * 32 + cc);
        }
    }
    asm volatile("cp.async.commit_group;");
    asm volatile("cp.async.wait_group 0;");
    __syncthreads();

    // ML3: t @ ffT (both resident in smem)
#pragma unroll
    for (int i = 0; i < 4; i++)
#pragma unroll
        for (int j = 0; j < 4; j++)
#pragma unroll
            for (int q = 0; q < 4; q++) acc1[i][j][q] = 0.f;
#pragma unroll
    for (int t = 0; t < 4; t++) {
        u32 abase = smem_u32(smg + t * STG_HALFS);
        u32 bbase = abase + 5120 * 2;
#pragma unroll
        for (int ks = 0; ks < 2; ks++) {
            u32 af[4][4];
#pragma unroll
            for (int mt = 0; mt < 4; mt++)
                ldm_x4(af[mt][0], af[mt][1], af[mt][2], af[mt][3],
                       abase + (u32)((warp_m * 64 + mt * 16 + lrow) * TSTRIDE + ks * 16 + lcol) * 2);
            u32 bfr[2][4];
#pragma unroll
            for (int p = 0; p < 2; p++)
                ldm_x4(bfr[p][0], bfr[p][1], bfr[p][2], bfr[p][3],
                       bbase + (u32)((warp_n * 32 + p * 16 + lrow) * TSTRIDE + ks * 16 + lcol) * 2);
#pragma unroll
            for (int p = 0; p < 2; p++)
#pragma unroll
                for (int q = 0; q < 2; q++) {
                    int nt2 = p * 2 + q;
#pragma unroll
                    for (int mt = 0; mt < 4; mt++)
                        mma_bf(acc1[mt][nt2], af[mt], bfr[p][q], bfr[p][q + 2]);
                }
        }
    }

    // gate epilogue -> d_out (fp32)
#pragma unroll
    for (int mt = 0; mt < 4; mt++) {
        int row0 = m0 + warp_m * 64 + mt * 16 + r;
#pragma unroll
        for (int half = 0; half < 2; half++) {
            int row = row0 + half * 8;
#pragma unroll
            for (int nt2 = 0; nt2 < 4; nt2++) {
                int col = warp_n * 32 + nt2 * 8 + c * 2;
                float v0 = acc1[mt][nt2][half * 2 + 0] + ff_b[col];
                float v1 = acc1[mt][nt2][half * 2 + 1] + ff_b[col + 1];
                size_t off = (size_t)row * 128 + col;
                float2 e = *(const float2*)&cx[off];
                float g0 = 1.f / (1.f + expf(-v0));
                float g1 = 1.f / (1.f + expf(-v1));
                float cy0 = g0 * (e.x + tanhf(v0));
                float cy1 = g1 * (e.y + tanhf(v1));
                *(float2*)&outp[off] = make_float2(g0 * tanhf(cy0), g1 * tanhf(cy1));
            }
        }
    }
}

// ---------------- concat + bf16 (reduce GEMM input) ----------------
__global__ void __launch_bounds__(256) concat_k(
    const float* __restrict__ xt, const float* __restrict__ hx, bf16* __restrict__ dst)
{
#pragma unroll
    for (int it = 0; it < 2; it++) {
        int g = (blockIdx.x * 256 + threadIdx.x) * 2 + it;
        int row = g >> 6, q = g & 63;
        const float* src = (q < 32) ? xt + (size_t)row * 128 + (q << 2)
                                    : hx + (size_t)row * 128 + ((q - 32) << 2);
        float4 v = *(const float4*)src;
        uint2 o = make_uint2(bf2(v.x, v.y), bf2(v.z, v.w));
        *(uint2*)(dst + (size_t)row * 256 + (q << 2)) = o;
    }
}

// ---------------- tensor-core window attention ----------------
#define ATT_STRIDE 136    // 128 d halfs + 8 pad (272 B rows)
#define ATT_SMEM   (3 * 64 * ATT_STRIDE * 2 + 900 * 4)

__global__ void __launch_bounds__(256) attn5(
    const bf16* __restrict__ qkv, const float* __restrict__ rp,
    bf16* __restrict__ out, int shift)
{
    extern __shared__ char smr[];
    bf16* qs = (bf16*)smr;
    bf16* ks = qs + 64 * ATT_STRIDE;
    bf16* vs = ks + 64 * ATT_STRIDE;
    float* rps = (float*)(vs + 64 * ATT_STRIDE);
    int tid = threadIdx.x;
    int lane = tid & 31, warp = tid >> 5;
    int bw = blockIdx.x;
    const float SCALE = 0.17677669529663687f;

    const bf16* base = qkv + (size_t)bw * 64 * 384;
#pragma unroll
    for (int i = 0; i < 12; i++) {
        int idx = tid + i * 256;
        int n = idx / 48, part = idx % 48;
        uint4 val = *(const uint4*)(base + (size_t)n * 384 + part * 8);
        bf16* dstp = (part < 16) ? qs : (part < 32) ? ks : vs;
        *(uint4*)&dstp[n * ATT_STRIDE + (part & 15) * 8] = val;
    }
    for (int i = tid; i < 900; i += 256) rps[i] = rp[i];
    __syncthreads();

    int h = warp >> 1;
    int m0 = (warp & 1) * 32;
    int cb = h * 32;
    int lrow = lane & 15;
    int lcol = (lane >> 4) << 3;

    u32 aq[2][2][4];
#pragma unroll
    for (int mt = 0; mt < 2; mt++)
#pragma unroll
        for (int kt = 0; kt < 2; kt++)
            ldm_x4(aq[mt][kt][0], aq[mt][kt][1], aq[mt][kt][2], aq[mt][kt][3],
                   smem_u32(&qs[(m0 + 16 * mt + lrow) * ATT_STRIDE + cb + 16 * kt + lcol]));

    float sacc[2][8][4];
#pragma unroll
    for (int mt = 0; mt < 2; mt++)
#pragma unroll
        for (int nt = 0; nt < 8; nt++)
#pragma unroll
            for (int q = 0; q < 4; q++) sacc[mt][nt][q] = 0.f;

#pragma unroll
    for (int ntp = 0; ntp < 4; ntp++)
#pragma unroll
        for (int kt = 0; kt < 2; kt++) {
            u32 b0, b1, b2, b3;
            ldm_x4(b0, b1, b2, b3,
                   smem_u32(&ks[(16 * ntp + lrow) * ATT_STRIDE + cb + 16 * kt + lcol]));
#pragma unroll
            for (int mt = 0; mt < 2; mt++) {
                mma_bf(sacc[mt][2 * ntp],     aq[mt][kt], b0, b2);
                mma_bf(sacc[mt][2 * ntp + 1], aq[mt][kt], b1, b3);
            }
        }

    int widx = bw & 63;
    int wh = widx >> 3, ww = widx & 7;
#pragma unroll
    for (int mt = 0; mt < 2; mt++)
#pragma unroll
        for (int q = 0; q < 4; q++) {
            int t1 = m0 + 16 * mt + (lane >> 2) + ((q >> 1) << 3);
            int r1 = t1 >> 3, s1 = t1 & 7;
            int h1 = wh * 8 + r1, w1 = ww * 8 + s1;
            int img1 = (h1 < 56 ? 0 : (h1 < 60 ? 1 : 2)) * 3 + (w1 < 56 ? 0 : (w1 < 60 ? 1 : 2));
#pragma unroll
            for (int nt = 0; nt < 8; nt++) {
                int t2 = nt * 8 + 2 * (lane & 3) + (q & 1);
                int r2 = t2 >> 3, s2 = t2 & 7;
                float v = sacc[mt][nt][q] * SCALE
                        + rps[((r1 - r2 + 7) * 15 + (s1 - s2 + 7)) * 4 + h];
                if (shift) {
                    int h2 = wh * 8 + r2, w2 = ww * 8 + s2;
                    int img2 = (h2 < 56 ? 0 : (h2 < 60 ? 1 : 2)) * 3 + (w2 < 56 ? 0 : (w2 < 60 ? 1 : 2));
                    if (img1 != img2) v -= 100.f;
                }
                sacc[mt][nt][q] = v;
            }
        }

#pragma unroll
    for (int mt = 0; mt < 2; mt++)
#pragma unroll
        for (int half = 0; half < 2; half++) {
            float mx = -1e30f;
#pragma unroll
            for (int nt = 0; nt < 8; nt++) {
                mx = fmaxf(mx, sacc[mt][nt][2 * half]);
                mx = fmaxf(mx, sacc[mt][nt][2 * half + 1]);
            }
            mx = fmaxf(mx, __shfl_xor_sync(0xffffffffu, mx, 1));
            mx = fmaxf(mx, __shfl_xor_sync(0xffffffffu, mx, 2));
            float sum = 0.f;
#pragma unroll
            for (int nt = 0; nt < 8; nt++) {
#pragma unroll
                for (int qq = 0; qq < 2; qq++) {
                    float e = __expf(sacc[mt][nt][2 * half + qq] - mx);
                    sacc[mt][nt][2 * half + qq] = e;
                    sum += e;
                }
            }
            sum += __shfl_xor_sync(0xffffffffu, sum, 1);
            sum += __shfl_xor_sync(0xffffffffu, sum, 2);
            float inv = 1.f / sum;
#pragma unroll
            for (int nt = 0; nt < 8; nt++) {
                sacc[mt][nt][2 * half] *= inv;
                sacc[mt][nt][2 * half + 1] *= inv;
            }
        }

    u32 pa[2][4][4];
#pragma unroll
    for (int mt = 0; mt < 2; mt++)
#pragma unroll
        for (int j = 0; j < 4; j++) {
            pa[mt][j][0] = bf2(sacc[mt][2 * j][0],     sacc[mt][2 * j][1]);
            pa[mt][j][1] = bf2(sacc[mt][2 * j][2],     sacc[mt][2 * j][3]);
            pa[mt][j][2] = bf2(sacc[mt][2 * j + 1][0], sacc[mt][2 * j + 1][1]);
            pa[mt][j][3] = bf2(sacc[mt][2 * j + 1][2], sacc[mt][2 * j + 1][3]);
        }

    float oacc[2][4][4];
#pragma unroll
    for (int mt = 0; mt < 2; mt++)
#pragma unroll
        for (int nt2 = 0; nt2 < 4; nt2++)
#pragma unroll
            for (int q = 0; q < 4; q++) oacc[mt][nt2][q] = 0.f;

#pragma unroll
    for (int j = 0; j < 4; j++)
#pragma unroll
        for (int ntp = 0; ntp < 2; ntp++) {
            u32 b0, b1, b2, b3;
            ldmt_x4(b0, b1, b2, b3,
                    smem_u32(&vs[(16 * j + lrow) * ATT_STRIDE + cb + 16 * ntp + lcol]));
#pragma unroll
            for (int mt = 0; mt < 2; mt++) {
                mma_bf(oacc[mt][2 * ntp],     pa[mt][j], b0, b1);
                mma_bf(oacc[mt][2 * ntp + 1], pa[mt][j], b2, b3);
            }
        }

#pragma unroll
    for (int mt = 0; mt < 2; mt++) {
        int row0 = bw * 64 + m0 + 16 * mt + (lane >> 2);
        int col  = cb + 2 * (lane & 3);
#pragma unroll
        for (int nt2 = 0; nt2 < 4; nt2++) {
            *(u32*)&out[(size_t)row0 * 128 + col + nt2 * 8]       = bf2(oacc[mt][nt2][0], oacc[mt][nt2][1]);
            *(u32*)&out[(size_t)(row0 + 8) * 128 + col + nt2 * 8] = bf2(oacc[mt][nt2][2], oacc[mt][nt2][3]);
        }
    }
}

// ---------------- fused deformable-conv branch (offset/mask conv + gather) ----------------
// block = (b, 32 tokens): phase 1 computes offsets/masks, phase 2 gathers + writes (B,C,L)
__global__ void __launch_bounds__(256) local_k(
    const float* __restrict__ xt,
    const float* __restrict__ ow, const float* __restrict__ ob,
    const float* __restrict__ mw, const float* __restrict__ mb,
    bf16* __restrict__ outp)
{
    __shared__ float rows[34][128];
    __shared__ float wo_s[1152], wm_s[1152];
    __shared__ int   s_fp[3][32];
    __shared__ float s_a0[3][32], s_a1[3][32];
    __shared__ bf16  smout[32][130];
    int b  = blockIdx.x >> 7;
    int l0 = (blockIdx.x & 127) << 5;
    int tid = threadIdx.x;
    int warp = tid >> 5, lane = tid & 31;

    for (int i = tid; i < 1152; i += 256) { wo_s[i] = ow[i]; wm_s[i] = mw[i]; }
#pragma unroll
    for (int i = 0; i < 5; i++) {
        int idx = i * 256 + tid;             // float4 ids, need 34*32 = 1088
        if (idx < 1088) {
            int rr = idx >> 5, c4 = (idx & 31) << 2;
            int l = l0 - 1 + rr;
            if (l >= 0 && l < 4096)
                *(float4*)&rows[rr][c4] = *(const float4*)(xt + ((size_t)b * 4096 + l) * 128 + c4);
        }
    }
    __syncthreads();

    int c0 = lane << 2;
#pragma unroll
    for (int it = 0; it < 4; it++) {
        int tl = warp * 4 + it;              // local token 0..31
        int l = l0 + tl;
        float so[3] = {0.f, 0.f, 0.f}, sm[3] = {0.f, 0.f, 0.f};
#pragma unroll
        for (int j = 0; j < 3; j++) {
            int ll = l + j - 1;
            if (ll < 0 || ll > 4095) continue;
            float4 xv = *(const float4*)&rows[tl + j][c0];
#pragma unroll
            for (int k = 0; k < 3; k++) {
                const float* owp = wo_s + k * 384 + j;
                const float* mwp = wm_s + k * 384 + j;
                so[k] += xv.x * owp[(c0 + 0) * 3] + xv.y * owp[(c0 + 1) * 3]
                       + xv.z * owp[(c0 + 2) * 3] + xv.w * owp[(c0 + 3) * 3];
                sm[k] += xv.x * mwp[(c0 + 0) * 3] + xv.y * mwp[(c0 + 1) * 3]
                       + xv.z * mwp[(c0 + 2) * 3] + xv.w * mwp[(c0 + 3) * 3];
            }
        }
#pragma unroll
        for (int o = 16; o > 0; o >>= 1) {
#pragma unroll
            for (int k = 0; k < 3; k++) {
                so[k] += __shfl_xor_sync(0xffffffffu, so[k], o);
                sm[k] += __shfl_xor_sync(0xffffffffu, sm[k], o);
            }
        }
        if (lane < 3) {
            int k = lane;
            float off = ob[k] + so[k];
            float mk  = mb[k] + sm[k];
            float mask = 1.f / (1.f + expf(-mk));
            float pos = fminf(fmaxf((float)l + off, 0.f), 4095.f);
            float fpf = floorf(pos);
            int f = (int)fpf;
            float alpha = pos - fpf;
            s_fp[k][tl] = f;
            s_a0[k][tl] = (1.f - alpha) * mask;
            s_a1[k][tl] = alpha * mask;
        }
    }
    __syncthreads();

    // phase 2: gather + bf16, transpose via smem, coalesced (B,C,L) write
#pragma unroll
    for (int i = 0; i < 16; i++) {
        int idx = i * 256 + tid;          // 0..4095
        int dl = idx >> 7, c = idx & 127;
        float o = 0.f;
#pragma unroll
        for (int k = 0; k < 3; k++) {
            int f  = s_fp[k][dl];
            int cp = min(f + 1, 4095);
            o += xt[((size_t)b * 4096 + f)  * 128 + c] * s_a0[k][dl]
               + xt[((size_t)b * 4096 + cp) * 128 + c] * s_a1[k][dl];
        }
        smout[dl][c] = __float2bfloat16_rn(o);
    }
    __syncthreads();
#pragma unroll
    for (int i = 0; i < 16; i++) {
        int idx = i * 256 + tid;
        int c = idx >> 5, dl = idx & 31;
        outp[(size_t)b * 524288 + (size_t)c * 4096 + l0 + dl] = smout[dl][c];
    }
}

// ---------------- host launcher ----------------
extern "C" void kernel_launch(void* const* d_in, const int* in_sizes, int n_in,
                              void* d_out, int out_size)
{
    const float* xt    = (const float*)d_in[0];
    const float* hx    = (const float*)d_in[1];
    const float* cx    = (const float*)d_in[2];
    const float* red_w = (const float*)d_in[3];
    const float* red_b = (const float*)d_in[4];
    const float* n1g   = (const float*)d_in[5];
    const float* n1b   = (const float*)d_in[6];
    const float* qkvw  = (const float*)d_in[7];
    const float* qkvb  = (const float*)d_in[8];
    const float* rp    = (const float*)d_in[9];
    const float* pw    = (const float*)d_in[10];
    const float* pb    = (const float*)d_in[11];
    const float* n2g   = (const float*)d_in[12];
    const float* n2b   = (const float*)d_in[13];
    const float* f1w   = (const float*)d_in[14];
    const float* f1b   = (const float*)d_in[15];
    const float* f2w   = (const float*)d_in[16];
    const float* f2b   = (const float*)d_in[17];
    const float* off_w = (const float*)d_in[18];
    const float* off_b = (const float*)d_in[19];
    const float* msk_w = (const float*)d_in[20];
    const float* msk_b = (const float*)d_in[21];
    const float* lf_w  = (const float*)d_in[22];
    const float* lf_b  = (const float*)d_in[23];
    const float* gf_w  = (const float*)d_in[24];
    const float* gf_b  = (const float*)d_in[25];
    const float* ff_w  = (const float*)d_in[26];
    const float* ff_b  = (const float*)d_in[27];

    float* px;
    bf16 *pbig16, *pxw16, *patt16, *ploc16, *px16;
    bf16 *predT, *pqkvT, *ppwT, *pf1T, *pf2T, *plfT, *pgfT, *pffT;
    cudaGetSymbolAddress((void**)&px,    d_x);
    cudaGetSymbolAddress((void**)&pbig16, g_big16);
    cudaGetSymbolAddress((void**)&pxw16, g_xw16);
    cudaGetSymbolAddress((void**)&patt16, g_att16);
    cudaGetSymbolAddress((void**)&ploc16, g_loc16);
    cudaGetSymbolAddress((void**)&px16,  g_x16);
    cudaGetSymbolAddress((void**)&predT, g_redT);
    cudaGetSymbolAddress((void**)&pqkvT, g_qkvT);
    cudaGetSymbolAddress((void**)&ppwT,  g_pwT);
    cudaGetSymbolAddress((void**)&pf1T,  g_f1T);
    cudaGetSymbolAddress((void**)&pf2T,  g_f2T);
    cudaGetSymbolAddress((void**)&plfT,  g_lfT);
    cudaGetSymbolAddress((void**)&pgfT,  g_gfT);
    cudaGetSymbolAddress((void**)&pffT,  g_ffT);

    cudaFuncSetAttribute(gemm_tc<M_PLAIN>,      cudaFuncAttributeMaxDynamicSharedMemorySize, GEMM_SMEM);
    cudaFuncSetAttribute(gemm_tc<M_GELU>,       cudaFuncAttributeMaxDynamicSharedMemorySize, GEMM_SMEM);
    cudaFuncSetAttribute(gemm_tc<M_RES>,        cudaFuncAttributeMaxDynamicSharedMemorySize, GEMM_SMEM);
    cudaFuncSetAttribute(gemm_tc<M_PLAIN_LN>,   cudaFuncAttributeMaxDynamicSharedMemorySize, GEMM_SMEM);
    cudaFuncSetAttribute(gemm_tc<M_RES_LN>,     cudaFuncAttributeMaxDynamicSharedMemorySize, GEMM_SMEM);
    cudaFuncSetAttribute(gemm_tc<M_PERMRES_LN>, cudaFuncAttributeMaxDynamicSharedMemorySize, GEMM_SMEM);
    cudaFuncSetAttribute(fusion_k,              cudaFuncAttributeMaxDynamicSharedMemorySize, GEMM_SMEM);
    cudaFuncSetAttribute(attn5,                 cudaFuncAttributeMaxDynamicSharedMemorySize, ATT_SMEM);

    // weight transpose-convert (fp32 KxN -> bf16 NxK)
    WPack wp;
    wp.e[0]  = { red_w,           predT,           256, 128 };
    wp.e[1]  = { qkvw,            pqkvT,           128, 384 };
    wp.e[2]  = { qkvw + 49152,    pqkvT + 49152,   128, 384 };
    wp.e[3]  = { pw,              ppwT,            128, 128 };
    wp.e[4]  = { pw + 16384,      ppwT + 16384,    128, 128 };
    wp.e[5]  = { f1w,             pf1T,            128, 512 };
    wp.e[6]  = { f1w + 65536,     pf1T + 65536,    128, 512 };
    wp.e[7]  = { f2w,             pf2T,            512, 128 };
    wp.e[8]  = { f2w + 65536,     pf2T + 65536,    512, 128 };
    wp.e[9]  = { lf_w,            plfT,            128, 128 };
    wp.e[10] = { gf_w,            pgfT,            128, 128 };
    wp.e[11] = { ff_w,            pffT,            128, 128 };
    wconv_k<<<dim3(48, 12), 256>>>(wp);

    // local (deformable) branch — fused offsets + gather
    local_k<<<Bn * 128, 256>>>(xt, off_w, off_b, msk_w, msk_b, ploc16);

    // global branch: concat then reduce GEMM (K=256) + fused LN1(block0, shift 0)
    concat_k<<<BL * 64 / 512, 256>>>(xt, hx, pbig16);
    gemm_tc<M_PLAIN_LN><<<dim3(1, 256), 256, GEMM_SMEM>>>(
        pbig16, predT, red_b, nullptr, px, pxw16, n1g, n1b, 128, 256, 0);

    for (int i = 0; i < 2; i++) {
        int shift = i ? 4 : 0;
        gemm_tc<M_PLAIN><<<dim3(3, 256), 256, GEMM_SMEM>>>(
            pxw16, pqkvT + i * 49152, qkvb + i * 384, nullptr,
            nullptr, pbig16, nullptr, nullptr, 384, 128, 0);
        attn5<<<512, 256, ATT_SMEM>>>(pbig16, rp + i * 900, patt16, shift);
        gemm_tc<M_PERMRES_LN><<<dim3(1, 256), 256, GEMM_SMEM>>>(
            patt16, ppwT + i * 16384, pb + i * 128, px,
            px, pxw16, n2g + i * 128, n2b + i * 128, 128, 128, shift);
        gemm_tc<M_GELU><<<dim3(4, 256), 256, GEMM_SMEM>>>(
            pxw16, pf1T + i * 65536, f1b + i * 512, nullptr,
            nullptr, pbig16, nullptr, nullptr, 512, 128, 0);
        if (i == 0) {
            gemm_tc<M_RES_LN><<<dim3(1, 256), 256, GEMM_SMEM>>>(
                pbig16, pf2T, f2b, px,
                px, pxw16, n1g + 128, n1b + 128, 128, 512, 4);
        } else {
            gemm_tc<M_RES><<<dim3(1, 256), 256, GEMM_SMEM>>>(
                pbig16, pf2T + 65536, f2b + 128, px,
                px, px16, nullptr, nullptr, 128, 512, 0);
        }
    }

    // fused fusion + LSTM gate (lf, gf, mulrelu, ff, gate in one kernel)
    fusion_k<<<256, 256, GEMM_SMEM>>>(px16, ploc16, pgfT, plfT, pffT,
                                      gf_b, lf_b, ff_b, cx, (float*)d_out);
}

// round 11
// speedup vs baseline: 4.4651x; 1.0706x over previous
#include <cuda_runtime.h>
#include <cuda_bf16.h>
#include <math.h>

// Problem constants
#define Bn   8
#define Ln   4096
#define Cn   128
#define BL   32768            // B*L rows

typedef unsigned int u32;
typedef unsigned long long u64;
typedef __nv_bfloat16 bf16;

// ---------------- helpers ----------------
__device__ __forceinline__ u32 smem_u32(const void* p) {
    u32 a;
    asm("{ .reg .u64 t; cvta.to.shared.u64 t, %1; cvt.u32.u64 %0, t; }" : "=r"(a) : "l"(p));
    return a;
}
__device__ __forceinline__ void cp16(u32 dst, const void* src) {
    size_t g = __cvta_generic_to_global(src);
    asm volatile("cp.async.cg.shared.global [%0], [%1], 16;" :: "r"(dst), "l"(g));
}
__device__ __forceinline__ void ldm_x4(u32& r0, u32& r1, u32& r2, u32& r3, u32 addr) {
    asm volatile("ldmatrix.sync.aligned.m8n8.x4.shared.b16 {%0,%1,%2,%3}, [%4];"
                 : "=r"(r0), "=r"(r1), "=r"(r2), "=r"(r3) : "r"(addr));
}
__device__ __forceinline__ void ldmt_x4(u32& r0, u32& r1, u32& r2, u32& r3, u32 addr) {
    asm volatile("ldmatrix.sync.aligned.m8n8.x4.trans.shared.b16 {%0,%1,%2,%3}, [%4];"
                 : "=r"(r0), "=r"(r1), "=r"(r2), "=r"(r3) : "r"(addr));
}
__device__ __forceinline__ u32 bf2(float a, float b) {
    __nv_bfloat162 h;
    h.x = __float2bfloat16_rn(a);
    h.y = __float2bfloat16_rn(b);
    return *(u32*)&h;
}
__device__ __forceinline__ void mma_bf(float* c, const u32* a, u32 b0, u32 b1) {
    asm volatile(
        "mma.sync.aligned.m16n8k16.row.col.f32.bf16.bf16.f32 "
        "{%0,%1,%2,%3},{%4,%5,%6,%7},{%8,%9},{%0,%1,%2,%3};"
        : "+f"(c[0]), "+f"(c[1]), "+f"(c[2]), "+f"(c[3])
        : "r"(a[0]), "r"(a[1]), "r"(a[2]), "r"(a[3]), "r"(b0), "r"(b1));
}

// ---------------- scratch (device globals; no allocs allowed) ----------------
__device__ float d_x   [BL * Cn];      // running stream (fp32)
__device__ bf16  g_big16[BL * 512];    // concat input / qkv / MLP hidden (bf16)
__device__ bf16  g_xw16 [BL * Cn];     // LN output (bf16)
__device__ bf16  g_att16[BL * Cn];     // attention out (bf16)
__device__ bf16  g_loc16[BL * Cn];     // deform out (bf16, (B,C,L) flat)
__device__ bf16  g_x16  [BL * Cn];     // final g (bf16)
// transposed bf16 weights (N x K row-major)
__device__ bf16  g_redT[128 * 256];
__device__ bf16  g_qkvT[2 * 384 * 128];
__device__ bf16  g_pwT [2 * 128 * 128];
__device__ bf16  g_f1T [2 * 512 * 128];
__device__ bf16  g_f2T [2 * 128 * 512];
__device__ bf16  g_lfT [128 * 128];
__device__ bf16  g_gfT [128 * 128];
__device__ bf16  g_ffT [128 * 128];

// window-layout row m  ->  token index (b*L + ho*64 + wo)
__device__ __forceinline__ int win_to_token(int m, int shift) {
    int n    = m & 63;
    int bw   = m >> 6;
    int widx = bw & 63;
    int b    = bw >> 6;
    int wh = widx >> 3, ww = widx & 7;
    int r = n >> 3, s = n & 7;
    int ho = (wh * 8 + r + shift) & 63;
    int wo = (ww * 8 + s + shift) & 63;
    return (b << 12) + (ho << 6) + wo;
}
// token index -> window-layout row (exact inverse)
__device__ __forceinline__ int token_to_win(int t, int shift) {
    int b = t >> 12, rem = t & 4095;
    int ho = rem >> 6, wo = rem & 63;
    int u = (ho - shift) & 63, v = (wo - shift) & 63;
    int wh = u >> 3, r = u & 7;
    int ww = v >> 3, s = v & 7;
    return (((b << 6) + (wh << 3) + ww) << 6) + (r << 3) + s;
}

// ---------------- weight transpose-convert: (K x N fp32) -> (N x K bf16) ----------------
struct WEnt { const float* src; bf16* dst; int K; int N; };
struct WPack { WEnt e[12]; };

__global__ void __launch_bounds__(256) wconv_k(WPack p) {
    WEnt w = p.e[blockIdx.y];
    int total = w.K * w.N;
    for (int i = blockIdx.x * 256 + threadIdx.x; i < total; i += gridDim.x * 256) {
        int n = i / w.K, k = i - n * w.K;
        w.dst[i] = __float2bfloat16_rn(w.src[(size_t)k * w.N + n]);
    }
}

// ---------------- bf16 tensor-core GEMM: 128x128 tile, 16 warps (32x32/warp) ---------------
enum { M_PLAIN = 0, M_GELU, M_RES, M_PERMRES,
       M_PLAIN_LN, M_RES_LN, M_PERMRES_LN };

#define TSTRIDE 40            // 32 k halfs + 8 pad (80 B rows)
#define STG_HALFS 10240       // per stage: A 5120 halfs + B 5120 halfs (20480 B)
#define GEMM_SMEM (4 * STG_HALFS * 2)   // 81920 B

template <int MODE>
__global__ void __launch_bounds__(512, 2) gemm_tc(
    const bf16* __restrict__ A, const bf16* __restrict__ BT,
    const float* __restrict__ bias, const float* __restrict__ extra,
    float* __restrict__ C, bf16* __restrict__ C16,
    const float* __restrict__ lng, const float* __restrict__ lnb,
    int N, int K, int shift)
{
    extern __shared__ bf16 smg[];
    int tid = threadIdx.x;
    int lane = tid & 31, warp = tid >> 5;       // warp 0..15
    int warp_m = warp & 3, warp_n = warp >> 2;  // 4 (M) x 4 (N), 32x32 tiles
    int m0 = blockIdx.y << 7, n0 = blockIdx.x << 7;
    int r = lane >> 2, c = lane & 3;

    const bool LN = (MODE == M_PLAIN_LN || MODE == M_RES_LN || MODE == M_PERMRES_LN);

    float acc[2][4][4];
#pragma unroll
    for (int i = 0; i < 2; i++)
#pragma unroll
        for (int j = 0; j < 4; j++)
#pragma unroll
            for (int q = 0; q < 4; q++) acc[i][j][q] = 0.f;

    const int prr = tid >> 2;                    // 0..127
    const int pcc = (tid & 3) << 3;              // 0,8,16,24
    auto prefetch = [&](int k0, int s) {
        u32 abase = smem_u32(smg + s * STG_HALFS);
        u32 bbase = abase + 5120 * 2;
        cp16(abase + (u32)(prr * TSTRIDE + pcc) * 2,
             A + (size_t)(m0 + prr) * K + k0 + pcc);
        cp16(bbase + (u32)(prr * TSTRIDE + pcc) * 2,
             BT + (size_t)(n0 + prr) * K + k0 + pcc);
        asm volatile("cp.async.commit_group;");
    };

    int lrow = lane & 15;
    int lcol = (lane >> 4) << 3;                 // 0 or 8 halfs

    int ntk = K >> 5;
    prefetch(0, 0);
    if (ntk > 1) prefetch(32, 1);
    for (int t = 0; t < ntk; t++) {
        if (t + 2 < ntk) prefetch((t + 2) << 5, (t + 2) & 3);
        if (t < ntk - 2)       asm volatile("cp.async.wait_group 2;");
        else if (t == ntk - 2) asm volatile("cp.async.wait_group 1;");
        else                   asm volatile("cp.async.wait_group 0;");
        __syncthreads();

        u32 abase = smem_u32(smg + (t & 3) * STG_HALFS);
        u32 bbase = abase + 5120 * 2;
#pragma unroll
        for (int ks = 0; ks < 2; ks++) {
            u32 af[2][4];
#pragma unroll
            for (int mt = 0; mt < 2; mt++)
                ldm_x4(af[mt][0], af[mt][1], af[mt][2], af[mt][3],
                       abase + (u32)((warp_m * 32 + mt * 16 + lrow) * TSTRIDE + ks * 16 + lcol) * 2);
            u32 bfr[2][4];
#pragma unroll
            for (int p = 0; p < 2; p++)
                ldm_x4(bfr[p][0], bfr[p][1], bfr[p][2], bfr[p][3],
                       bbase + (u32)((warp_n * 32 + p * 16 + lrow) * TSTRIDE + ks * 16 + lcol) * 2);
#pragma unroll
            for (int p = 0; p < 2; p++)
#pragma unroll
                for (int q = 0; q < 2; q++) {
                    int nt2 = p * 2 + q;
                    u32 b0 = bfr[p][q], b1 = bfr[p][q + 2];
#pragma unroll
                    for (int mt = 0; mt < 2; mt++)
                        mma_bf(acc[mt][nt2], af[mt], b0, b1);
                }
        }
    }

    if (!LN) {
#pragma unroll
        for (int mt = 0; mt < 2; mt++) {
            int row0 = m0 + warp_m * 32 + mt * 16 + r;
#pragma unroll
            for (int half = 0; half < 2; half++) {
                int row = row0 + half * 8;
                int dst = (MODE == M_PERMRES) ? win_to_token(row, shift) : row;
#pragma unroll
                for (int nt2 = 0; nt2 < 4; nt2++) {
                    int col = n0 + warp_n * 32 + nt2 * 8 + c * 2;
                    float v0 = acc[mt][nt2][half * 2 + 0] + bias[col];
                    float v1 = acc[mt][nt2][half * 2 + 1] + bias[col + 1];
                    size_t off = (size_t)dst * N + col;
                    if (MODE == M_GELU) {
                        v0 = 0.5f * v0 * (1.f + erff(v0 * 0.70710678118654752f));
                        v1 = 0.5f * v1 * (1.f + erff(v1 * 0.70710678118654752f));
                    } else if (MODE == M_RES || MODE == M_PERMRES) {
                        float2 e = *(const float2*)&extra[off];
                        v0 += e.x; v1 += e.y;
                    }
                    if (C)   *(float2*)&C[off] = make_float2(v0, v1);
                    if (C16) *(u32*)&C16[off]  = bf2(v0, v1);
                }
            }
        }
        return;
    }

    // ---- fused-LN epilogue (N == 128) ----
    float rsum[2][2], rsq[2][2];
#pragma unroll
    for (int mt = 0; mt < 2; mt++) {
        int row0 = m0 + warp_m * 32 + mt * 16 + r;
#pragma unroll
        for (int half = 0; half < 2; half++) {
            int row = row0 + half * 8;
            int dst = (MODE == M_PERMRES_LN) ? win_to_token(row, shift) : row;
            float s = 0.f, sq = 0.f;
#pragma unroll
            for (int nt2 = 0; nt2 < 4; nt2++) {
                int col = n0 + warp_n * 32 + nt2 * 8 + c * 2;
                float v0 = acc[mt][nt2][half * 2 + 0] + bias[col];
                float v1 = acc[mt][nt2][half * 2 + 1] + bias[col + 1];
                if (MODE == M_RES_LN || MODE == M_PERMRES_LN) {
                    float2 e = *(const float2*)&extra[(size_t)dst * 128 + col];
                    v0 += e.x; v1 += e.y;
                }
                acc[mt][nt2][half * 2 + 0] = v0;
                acc[mt][nt2][half * 2 + 1] = v1;
                s += v0 + v1; sq += v0 * v0 + v1 * v1;
            }
            s  += __shfl_xor_sync(0xffffffffu, s, 1);
            s  += __shfl_xor_sync(0xffffffffu, s, 2);
            sq += __shfl_xor_sync(0xffffffffu, sq, 1);
            sq += __shfl_xor_sync(0xffffffffu, sq, 2);
            rsum[mt][half] = s; rsq[mt][half] = sq;
        }
    }
    __syncthreads();
    float* part = (float*)smg;             // [128 rows][4 warp_n][2]
    if ((lane & 3) == 0) {
#pragma unroll
        for (int mt = 0; mt < 2; mt++)
#pragma unroll
            for (int half = 0; half < 2; half++) {
                int rowloc = warp_m * 32 + mt * 16 + (lane >> 2) + half * 8;
                part[rowloc * 8 + warp_n * 2 + 0] = rsum[mt][half];
                part[rowloc * 8 + warp_n * 2 + 1] = rsq[mt][half];
            }
    }
    __syncthreads();
#pragma unroll
    for (int mt = 0; mt < 2; mt++) {
#pragma unroll
        for (int half = 0; half < 2; half++) {
            int rowloc = warp_m * 32 + mt * 16 + r + half * 8;
            float s  = part[rowloc * 8] + part[rowloc * 8 + 2]
                     + part[rowloc * 8 + 4] + part[rowloc * 8 + 6];
            float sq = part[rowloc * 8 + 1] + part[rowloc * 8 + 3]
                     + part[rowloc * 8 + 5] + part[rowloc * 8 + 7];
            float mu = s * 0.0078125f;
            float var = sq * 0.0078125f - mu * mu;
            float rstd = rsqrtf(var + 1e-5f);
            int row = m0 + rowloc;
            int xdst, wdst;
            if (MODE == M_PERMRES_LN) { xdst = win_to_token(row, shift); wdst = xdst; }
            else                      { xdst = row; wdst = token_to_win(row, shift); }
#pragma unroll
            for (int nt2 = 0; nt2 < 4; nt2++) {
                int col = n0 + warp_n * 32 + nt2 * 8 + c * 2;
                float v0 = acc[mt][nt2][half * 2 + 0];
                float v1 = acc[mt][nt2][half * 2 + 1];
                *(float2*)&C[(size_t)xdst * 128 + col] = make_float2(v0, v1);
                float w0 = (v0 - mu) * rstd * lng[col]     + lnb[col];
                float w1 = (v1 - mu) * rstd * lng[col + 1] + lnb[col + 1];
                *(u32*)&C16[(size_t)wdst * 128 + col] = bf2(w0, w1);
            }
        }
    }
}

// ---------------- fused fusion + LSTM gate kernel (16 warps, 32x32 tiles) ----------------
__device__ __forceinline__ void ml_k128(
    bf16* smg, const bf16* A, const bf16* BT, int m0,
    int tid, int warp_m, int warp_n, int lrow, int lcol,
    float (&acc)[2][4][4])
{
    __syncthreads();   // previous smem users done
    int prr = tid >> 2, pcc = (tid & 3) << 3;
#pragma unroll
    for (int s = 0; s < 4; s++) {
        u32 abase = smem_u32(smg + s * STG_HALFS);
        u32 bbase = abase + 5120 * 2;
        cp16(abase + (u32)(prr * TSTRIDE + pcc) * 2,
             A + (size_t)(m0 + prr) * 128 + s * 32 + pcc);
        cp16(bbase + (u32)(prr * TSTRIDE + pcc) * 2,
             BT + (size_t)prr * 128 + s * 32 + pcc);
    }
    asm volatile("cp.async.commit_group;");
    asm volatile("cp.async.wait_group 0;");
    __syncthreads();
#pragma unroll
    for (int t = 0; t < 4; t++) {
        u32 abase = smem_u32(smg + t * STG_HALFS);
        u32 bbase = abase + 5120 * 2;
#pragma unroll
        for (int ks = 0; ks < 2; ks++) {
            u32 af[2][4];
#pragma unroll
            for (int mt = 0; mt < 2; mt++)
                ldm_x4(af[mt][0], af[mt][1], af[mt][2], af[mt][3],
                       abase + (u32)((warp_m * 32 + mt * 16 + lrow) * TSTRIDE + ks * 16 + lcol) * 2);
            u32 bfr[2][4];
#pragma unroll
            for (int p = 0; p < 2; p++)
                ldm_x4(bfr[p][0], bfr[p][1], bfr[p][2], bfr[p][3],
                       bbase + (u32)((warp_n * 32 + p * 16 + lrow) * TSTRIDE + ks * 16 + lcol) * 2);
#pragma unroll
            for (int p = 0; p < 2; p++)
#pragma unroll
                for (int q = 0; q < 2; q++) {
                    int nt2 = p * 2 + q;
#pragma unroll
                    for (int mt = 0; mt < 2; mt++)
                        mma_bf(acc[mt][nt2], af[mt], bfr[p][q], bfr[p][q + 2]);
                }
        }
    }
}

__global__ void __launch_bounds__(512, 2) fusion_k(
    const bf16* __restrict__ g16, const bf16* __restrict__ loc16,
    const bf16* __restrict__ gfT, const bf16* __restrict__ lfT,
    const bf16* __restrict__ ffT,
    const float* __restrict__ gf_b, const float* __restrict__ lf_b,
    const float* __restrict__ ff_b,
    const float* __restrict__ cx, float* __restrict__ outp)
{
    extern __shared__ bf16 smg[];
    int tid = threadIdx.x;
    int lane = tid & 31, warp = tid >> 5;
    int warp_m = warp & 3, warp_n = warp >> 2;
    int m0 = blockIdx.x << 7;
    int r = lane >> 2, c = lane & 3;
    int lrow = lane & 15;
    int lcol = (lane >> 4) << 3;

    float acc1[2][4][4], acc2[2][4][4];
#pragma unroll
    for (int i = 0; i < 2; i++)
#pragma unroll
        for (int j = 0; j < 4; j++)
#pragma unroll
            for (int q = 0; q < 4; q++) { acc1[i][j][q] = 0.f; acc2[i][j][q] = 0.f; }

    // ML1: g @ gfT ; ML2: loc @ lfT
    ml_k128(smg, g16, gfT, m0, tid, warp_m, warp_n, lrow, lcol, acc1);
    ml_k128(smg, loc16, lfT, m0, tid, warp_m, warp_n, lrow, lcol, acc2);

    __syncthreads();   // all ML2 smem reads done before t overwrites stages
    // t = relu((acc2+lf_b)*(acc1+gf_b)) -> stage A regions (k-tile = warp_n), ldmatrix layout
    {
        u32 abase = smem_u32(smg + warp_n * STG_HALFS);
#pragma unroll
        for (int mt = 0; mt < 2; mt++)
#pragma unroll
            for (int half = 0; half < 2; half++) {
                int row = warp_m * 32 + mt * 16 + r + half * 8;
#pragma unroll
                for (int nt2 = 0; nt2 < 4; nt2++) {
                    int cc = nt2 * 8 + c * 2;          // 0..31 within this k-tile
                    int col = warp_n * 32 + cc;
                    float a0 = acc1[mt][nt2][half * 2 + 0] + gf_b[col];
                    float a1 = acc1[mt][nt2][half * 2 + 1] + gf_b[col + 1];
                    float b0 = acc2[mt][nt2][half * 2 + 0] + lf_b[col];
                    float b1 = acc2[mt][nt2][half * 2 + 1] + lf_b[col + 1];
                    float t0 = a0 * b0, t1 = a1 * b1;
                    t0 = t0 > 0.f ? t0 : 0.f;
                    t1 = t1 > 0.f ? t1 : 0.f;
                    u32 pkv = bf2(t0, t1);
                    asm volatile("st.shared.b32 [%0], %1;"
                                 :: "r"(abase + (u32)(row * TSTRIDE + cc) * 2), "r"(pkv));
                }
            }
    }
    // prefetch ffT into stage B regions
    {
        int prr = tid >> 2, pcc = (tid & 3) << 3;
#pragma unroll
        for (int s = 0; s < 4; s++) {
            u32 bbase = smem_u32(smg + s * STG_HALFS) + 5120 * 2;
            cp16(bbase + (u32)(prr * TSTRIDE + pcc) * 2,
                 ffT + (size_t)prr * 128 + s * 32 + pcc);
        }
    }
    asm volatile("cp.async.commit_group;");
    asm volatile("cp.async.wait_group 0;");
    __syncthreads();

    // ML3: t @ ffT (both resident in smem)
#pragma unroll
    for (int i = 0; i < 2; i++)
#pragma unroll
        for (int j = 0; j < 4; j++)
#pragma unroll
            for (int q = 0; q < 4; q++) acc1[i][j][q] = 0.f;
#pragma unroll
    for (int t = 0; t < 4; t++) {
        u32 abase = smem_u32(smg + t * STG_HALFS);
        u32 bbase = abase + 5120 * 2;
#pragma unroll
        for (int ks = 0; ks < 2; ks++) {
            u32 af[2][4];
#pragma unroll
            for (int mt = 0; mt < 2; mt++)
                ldm_x4(af[mt][0], af[mt][1], af[mt][2], af[mt][3],
                       abase + (u32)((warp_m * 32 + mt * 16 + lrow) * TSTRIDE + ks * 16 + lcol) * 2);
            u32 bfr[2][4];
#pragma unroll
            for (int p = 0; p < 2; p++)
                ldm_x4(bfr[p][0], bfr[p][1], bfr[p][2], bfr[p][3],
                       bbase + (u32)((warp_n * 32 + p * 16 + lrow) * TSTRIDE + ks * 16 + lcol) * 2);
#pragma unroll
            for (int p = 0; p < 2; p++)
#pragma unroll
                for (int q = 0; q < 2; q++) {
                    int nt2 = p * 2 + q;
#pragma unroll
                    for (int mt = 0; mt < 2; mt++)
                        mma_bf(acc1[mt][nt2], af[mt], bfr[p][q], bfr[p][q + 2]);
                }
        }
    }

    // gate epilogue -> d_out (fp32)
#pragma unroll
    for (int mt = 0; mt < 2; mt++) {
        int row0 = m0 + warp_m * 32 + mt * 16 + r;
#pragma unroll
        for (int half = 0; half < 2; half++) {
            int row = row0 + half * 8;
#pragma unroll
            for (int nt2 = 0; nt2 < 4; nt2++) {
                int col = warp_n * 32 + nt2 * 8 + c * 2;
                float v0 = acc1[mt][nt2][half * 2 + 0] + ff_b[col];
                float v1 = acc1[mt][nt2][half * 2 + 1] + ff_b[col + 1];
                size_t off = (size_t)row * 128 + col;
                float2 e = *(const float2*)&cx[off];
                float g0 = 1.f / (1.f + expf(-v0));
                float g1 = 1.f / (1.f + expf(-v1));
                float cy0 = g0 * (e.x + tanhf(v0));
                float cy1 = g1 * (e.y + tanhf(v1));
                *(float2*)&outp[off] = make_float2(g0 * tanhf(cy0), g1 * tanhf(cy1));
            }
        }
    }
}

// ---------------- concat + bf16 (reduce GEMM input) ----------------
__global__ void __launch_bounds__(256) concat_k(
    const float* __restrict__ xt, const float* __restrict__ hx, bf16* __restrict__ dst)
{
#pragma unroll
    for (int it = 0; it < 2; it++) {
        int g = (blockIdx.x * 256 + threadIdx.x) * 2 + it;
        int row = g >> 6, q = g & 63;
        const float* src = (q < 32) ? xt + (size_t)row * 128 + (q << 2)
                                    : hx + (size_t)row * 128 + ((q - 32) << 2);
        float4 v = *(const float4*)src;
        uint2 o = make_uint2(bf2(v.x, v.y), bf2(v.z, v.w));
        *(uint2*)(dst + (size_t)row * 256 + (q << 2)) = o;
    }
}

// ---------------- tensor-core window attention ----------------
#define ATT_STRIDE 136    // 128 d halfs + 8 pad (272 B rows)
#define ATT_SMEM   (3 * 64 * ATT_STRIDE * 2 + 900 * 4)

__global__ void __launch_bounds__(256) attn5(
    const bf16* __restrict__ qkv, const float* __restrict__ rp,
    bf16* __restrict__ out, int shift)
{
    extern __shared__ char smr[];
    bf16* qs = (bf16*)smr;
    bf16* ks = qs + 64 * ATT_STRIDE;
    bf16* vs = ks + 64 * ATT_STRIDE;
    float* rps = (float*)(vs + 64 * ATT_STRIDE);
    int tid = threadIdx.x;
    int lane = tid & 31, warp = tid >> 5;
    int bw = blockIdx.x;
    const float SCALE = 0.17677669529663687f;

    const bf16* base = qkv + (size_t)bw * 64 * 384;
#pragma unroll
    for (int i = 0; i < 12; i++) {
        int idx = tid + i * 256;
        int n = idx / 48, part = idx % 48;
        uint4 val = *(const uint4*)(base + (size_t)n * 384 + part * 8);
        bf16* dstp = (part < 16) ? qs : (part < 32) ? ks : vs;
        *(uint4*)&dstp[n * ATT_STRIDE + (part & 15) * 8] = val;
    }
    for (int i = tid; i < 900; i += 256) rps[i] = rp[i];
    __syncthreads();

    int h = warp >> 1;
    int m0 = (warp & 1) * 32;
    int cb = h * 32;
    int lrow = lane & 15;
    int lcol = (lane >> 4) << 3;

    u32 aq[2][2][4];
#pragma unroll
    for (int mt = 0; mt < 2; mt++)
#pragma unroll
        for (int kt = 0; kt < 2; kt++)
            ldm_x4(aq[mt][kt][0], aq[mt][kt][1], aq[mt][kt][2], aq[mt][kt][3],
                   smem_u32(&qs[(m0 + 16 * mt + lrow) * ATT_STRIDE + cb + 16 * kt + lcol]));

    float sacc[2][8][4];
#pragma unroll
    for (int mt = 0; mt < 2; mt++)
#pragma unroll
        for (int nt = 0; nt < 8; nt++)
#pragma unroll
            for (int q = 0; q < 4; q++) sacc[mt][nt][q] = 0.f;

#pragma unroll
    for (int ntp = 0; ntp < 4; ntp++)
#pragma unroll
        for (int kt = 0; kt < 2; kt++) {
            u32 b0, b1, b2, b3;
            ldm_x4(b0, b1, b2, b3,
                   smem_u32(&ks[(16 * ntp + lrow) * ATT_STRIDE + cb + 16 * kt + lcol]));
#pragma unroll
            for (int mt = 0; mt < 2; mt++) {
                mma_bf(sacc[mt][2 * ntp],     aq[mt][kt], b0, b2);
                mma_bf(sacc[mt][2 * ntp + 1], aq[mt][kt], b1, b3);
            }
        }

    int widx = bw & 63;
    int wh = widx >> 3, ww = widx & 7;
#pragma unroll
    for (int mt = 0; mt < 2; mt++)
#pragma unroll
        for (int q = 0; q < 4; q++) {
            int t1 = m0 + 16 * mt + (lane >> 2) + ((q >> 1) << 3);
            int r1 = t1 >> 3, s1 = t1 & 7;
            int h1 = wh * 8 + r1, w1 = ww * 8 + s1;
            int img1 = (h1 < 56 ? 0 : (h1 < 60 ? 1 : 2)) * 3 + (w1 < 56 ? 0 : (w1 < 60 ? 1 : 2));
#pragma unroll
            for (int nt = 0; nt < 8; nt++) {
                int t2 = nt * 8 + 2 * (lane & 3) + (q & 1);
                int r2 = t2 >> 3, s2 = t2 & 7;
                float v = sacc[mt][nt][q] * SCALE
                        + rps[((r1 - r2 + 7) * 15 + (s1 - s2 + 7)) * 4 + h];
                if (shift) {
                    int h2 = wh * 8 + r2, w2 = ww * 8 + s2;
                    int img2 = (h2 < 56 ? 0 : (h2 < 60 ? 1 : 2)) * 3 + (w2 < 56 ? 0 : (w2 < 60 ? 1 : 2));
                    if (img1 != img2) v -= 100.f;
                }
                sacc[mt][nt][q] = v;
            }
        }

#pragma unroll
    for (int mt = 0; mt < 2; mt++)
#pragma unroll
        for (int half = 0; half < 2; half++) {
            float mx = -1e30f;
#pragma unroll
            for (int nt = 0; nt < 8; nt++) {
                mx = fmaxf(mx, sacc[mt][nt][2 * half]);
                mx = fmaxf(mx, sacc[mt][nt][2 * half + 1]);
            }
            mx = fmaxf(mx, __shfl_xor_sync(0xffffffffu, mx, 1));
            mx = fmaxf(mx, __shfl_xor_sync(0xffffffffu, mx, 2));
            float sum = 0.f;
#pragma unroll
            for (int nt = 0; nt < 8; nt++) {
#pragma unroll
                for (int qq = 0; qq < 2; qq++) {
                    float e = __expf(sacc[mt][nt][2 * half + qq] - mx);
                    sacc[mt][nt][2 * half + qq] = e;
                    sum += e;
                }
            }
            sum += __shfl_xor_sync(0xffffffffu, sum, 1);
            sum += __shfl_xor_sync(0xffffffffu, sum, 2);
            float inv = 1.f / sum;
#pragma unroll
            for (int nt = 0; nt < 8; nt++) {
                sacc[mt][nt][2 * half] *= inv;
                sacc[mt][nt][2 * half + 1] *= inv;
            }
        }

    u32 pa[2][4][4];
#pragma unroll
    for (int mt = 0; mt < 2; mt++)
#pragma unroll
        for (int j = 0; j < 4; j++) {
            pa[mt][j][0] = bf2(sacc[mt][2 * j][0],     sacc[mt][2 * j][1]);
            pa[mt][j][1] = bf2(sacc[mt][2 * j][2],     sacc[mt][2 * j][3]);
            pa[mt][j][2] = bf2(sacc[mt][2 * j + 1][0], sacc[mt][2 * j + 1][1]);
            pa[mt][j][3] = bf2(sacc[mt][2 * j + 1][2], sacc[mt][2 * j + 1][3]);
        }

    float oacc[2][4][4];
#pragma unroll
    for (int mt = 0; mt < 2; mt++)
#pragma unroll
        for (int nt2 = 0; nt2 < 4; nt2++)
#pragma unroll
            for (int q = 0; q < 4; q++) oacc[mt][nt2][q] = 0.f;

#pragma unroll
    for (int j = 0; j < 4; j++)
#pragma unroll
        for (int ntp = 0; ntp < 2; ntp++) {
            u32 b0, b1, b2, b3;
            ldmt_x4(b0, b1, b2, b3,
                    smem_u32(&vs[(16 * j + lrow) * ATT_STRIDE + cb + 16 * ntp + lcol]));
#pragma unroll
            for (int mt = 0; mt < 2; mt++) {
                mma_bf(oacc[mt][2 * ntp],     pa[mt][j], b0, b1);
                mma_bf(oacc[mt][2 * ntp + 1], pa[mt][j], b2, b3);
            }
        }

#pragma unroll
    for (int mt = 0; mt < 2; mt++) {
        int row0 = bw * 64 + m0 + 16 * mt + (lane >> 2);
        int col  = cb + 2 * (lane & 3);
#pragma unroll
        for (int nt2 = 0; nt2 < 4; nt2++) {
            *(u32*)&out[(size_t)row0 * 128 + col + nt2 * 8]       = bf2(oacc[mt][nt2][0], oacc[mt][nt2][1]);
            *(u32*)&out[(size_t)(row0 + 8) * 128 + col + nt2 * 8] = bf2(oacc[mt][nt2][2], oacc[mt][nt2][3]);
        }
    }
}

// ---------------- fused deformable-conv branch (offset/mask conv + gather) ----------------
__global__ void __launch_bounds__(256) local_k(
    const float* __restrict__ xt,
    const float* __restrict__ ow, const float* __restrict__ ob,
    const float* __restrict__ mw, const float* __restrict__ mb,
    bf16* __restrict__ outp)
{
    __shared__ float rows[34][128];
    __shared__ float wo_s[1152], wm_s[1152];
    __shared__ int   s_fp[3][32];
    __shared__ float s_a0[3][32], s_a1[3][32];
    __shared__ bf16  smout[32][130];
    int b  = blockIdx.x >> 7;
    int l0 = (blockIdx.x & 127) << 5;
    int tid = threadIdx.x;
    int warp = tid >> 5, lane = tid & 31;

    for (int i = tid; i < 1152; i += 256) { wo_s[i] = ow[i]; wm_s[i] = mw[i]; }
#pragma unroll
    for (int i = 0; i < 5; i++) {
        int idx = i * 256 + tid;             // float4 ids, need 34*32 = 1088
        if (idx < 1088) {
            int rr = idx >> 5, c4 = (idx & 31) << 2;
            int l = l0 - 1 + rr;
            if (l >= 0 && l < 4096)
                *(float4*)&rows[rr][c4] = *(const float4*)(xt + ((size_t)b * 4096 + l) * 128 + c4);
        }
    }
    __syncthreads();

    int c0 = lane << 2;
#pragma unroll
    for (int it = 0; it < 4; it++) {
        int tl = warp * 4 + it;              // local token 0..31
        int l = l0 + tl;
        float so[3] = {0.f, 0.f, 0.f}, sm[3] = {0.f, 0.f, 0.f};
#pragma unroll
        for (int j = 0; j < 3; j++) {
            int ll = l + j - 1;
            if (ll < 0 || ll > 4095) continue;
            float4 xv = *(const float4*)&rows[tl + j][c0];
#pragma unroll
            for (int k = 0; k < 3; k++) {
                const float* owp = wo_s + k * 384 + j;
                const float* mwp = wm_s + k * 384 + j;
                so[k] += xv.x * owp[(c0 + 0) * 3] + xv.y * owp[(c0 + 1) * 3]
                       + xv.z * owp[(c0 + 2) * 3] + xv.w * owp[(c0 + 3) * 3];
                sm[k] += xv.x * mwp[(c0 + 0) * 3] + xv.y * mwp[(c0 + 1) * 3]
                       + xv.z * mwp[(c0 + 2) * 3] + xv.w * mwp[(c0 + 3) * 3];
            }
        }
#pragma unroll
        for (int o = 16; o > 0; o >>= 1) {
#pragma unroll
            for (int k = 0; k < 3; k++) {
                so[k] += __shfl_xor_sync(0xffffffffu, so[k], o);
                sm[k] += __shfl_xor_sync(0xffffffffu, sm[k], o);
            }
        }
        if (lane < 3) {
            int k = lane;
            float off = ob[k] + so[k];
            float mk  = mb[k] + sm[k];
            float mask = 1.f / (1.f + expf(-mk));
            float pos = fminf(fmaxf((float)l + off, 0.f), 4095.f);
            float fpf = floorf(pos);
            int f = (int)fpf;
            float alpha = pos - fpf;
            s_fp[k][tl] = f;
            s_a0[k][tl] = (1.f - alpha) * mask;
            s_a1[k][tl] = alpha * mask;
        }
    }
    __syncthreads();

    // phase 2: gather + bf16, transpose via smem, coalesced (B,C,L) write
#pragma unroll
    for (int i = 0; i < 16; i++) {
        int idx = i * 256 + tid;          // 0..4095
        int dl = idx >> 7, c = idx & 127;
        float o = 0.f;
#pragma unroll
        for (int k = 0; k < 3; k++) {
            int f  = s_fp[k][dl];
            int cp = min(f + 1, 4095);
            o += xt[((size_t)b * 4096 + f)  * 128 + c] * s_a0[k][dl]
               + xt[((size_t)b * 4096 + cp) * 128 + c] * s_a1[k][dl];
        }
        smout[dl][c] = __float2bfloat16_rn(o);
    }
    __syncthreads();
#pragma unroll
    for (int i = 0; i < 16; i++) {
        int idx = i * 256 + tid;
        int c = idx >> 5, dl = idx & 31;
        outp[(size_t)b * 524288 + (size_t)c * 4096 + l0 + dl] = smout[dl][c];
    }
}

// ---------------- host launcher ----------------
extern "C" void kernel_launch(void* const* d_in, const int* in_sizes, int n_in,
                              void* d_out, int out_size)
{
    const float* xt    = (const float*)d_in[0];
    const float* hx    = (const float*)d_in[1];
    const float* cx    = (const float*)d_in[2];
    const float* red_w = (const float*)d_in[3];
    const float* red_b = (const float*)d_in[4];
    const float* n1g   = (const float*)d_in[5];
    const float* n1b   = (const float*)d_in[6];
    const float* qkvw  = (const float*)d_in[7];
    const float* qkvb  = (const float*)d_in[8];
    const float* rp    = (const float*)d_in[9];
    const float* pw    = (const float*)d_in[10];
    const float* pb    = (const float*)d_in[11];
    const float* n2g   = (const float*)d_in[12];
    const float* n2b   = (const float*)d_in[13];
    const float* f1w   = (const float*)d_in[14];
    const float* f1b   = (const float*)d_in[15];
    const float* f2w   = (const float*)d_in[16];
    const float* f2b   = (const float*)d_in[17];
    const float* off_w = (const float*)d_in[18];
    const float* off_b = (const float*)d_in[19];
    const float* msk_w = (const float*)d_in[20];
    const float* msk_b = (const float*)d_in[21];
    const float* lf_w  = (const float*)d_in[22];
    const float* lf_b  = (const float*)d_in[23];
    const float* gf_w  = (const float*)d_in[24];
    const float* gf_b  = (const float*)d_in[25];
    const float* ff_w  = (const float*)d_in[26];
    const float* ff_b  = (const float*)d_in[27];

    float* px;
    bf16 *pbig16, *pxw16, *patt16, *ploc16, *px16;
    bf16 *predT, *pqkvT, *ppwT, *pf1T, *pf2T, *plfT, *pgfT, *pffT;
    cudaGetSymbolAddress((void**)&px,    d_x);
    cudaGetSymbolAddress((void**)&pbig16, g_big16);
    cudaGetSymbolAddress((void**)&pxw16, g_xw16);
    cudaGetSymbolAddress((void**)&patt16, g_att16);
    cudaGetSymbolAddress((void**)&ploc16, g_loc16);
    cudaGetSymbolAddress((void**)&px16,  g_x16);
    cudaGetSymbolAddress((void**)&predT, g_redT);
    cudaGetSymbolAddress((void**)&pqkvT, g_qkvT);
    cudaGetSymbolAddress((void**)&ppwT,  g_pwT);
    cudaGetSymbolAddress((void**)&pf1T,  g_f1T);
    cudaGetSymbolAddress((void**)&pf2T,  g_f2T);
    cudaGetSymbolAddress((void**)&plfT,  g_lfT);
    cudaGetSymbolAddress((void**)&pgfT,  g_gfT);
    cudaGetSymbolAddress((void**)&pffT,  g_ffT);

    cudaFuncSetAttribute(gemm_tc<M_PLAIN>,      cudaFuncAttributeMaxDynamicSharedMemorySize, GEMM_SMEM);
    cudaFuncSetAttribute(gemm_tc<M_GELU>,       cudaFuncAttributeMaxDynamicSharedMemorySize, GEMM_SMEM);
    cudaFuncSetAttribute(gemm_tc<M_RES>,        cudaFuncAttributeMaxDynamicSharedMemorySize, GEMM_SMEM);
    cudaFuncSetAttribute(gemm_tc<M_PLAIN_LN>,   cudaFuncAttributeMaxDynamicSharedMemorySize, GEMM_SMEM);
    cudaFuncSetAttribute(gemm_tc<M_RES_LN>,     cudaFuncAttributeMaxDynamicSharedMemorySize, GEMM_SMEM);
    cudaFuncSetAttribute(gemm_tc<M_PERMRES_LN>, cudaFuncAttributeMaxDynamicSharedMemorySize, GEMM_SMEM);
    cudaFuncSetAttribute(fusion_k,              cudaFuncAttributeMaxDynamicSharedMemorySize, GEMM_SMEM);
    cudaFuncSetAttribute(attn5,                 cudaFuncAttributeMaxDynamicSharedMemorySize, ATT_SMEM);

    // weight transpose-convert (fp32 KxN -> bf16 NxK)
    WPack wp;
    wp.e[0]  = { red_w,           predT,           256, 128 };
    wp.e[1]  = { qkvw,            pqkvT,           128, 384 };
    wp.e[2]  = { qkvw + 49152,    pqkvT + 49152,   128, 384 };
    wp.e[3]  = { pw,              ppwT,            128, 128 };
    wp.e[4]  = { pw + 16384,      ppwT + 16384,    128, 128 };
    wp.e[5]  = { f1w,             pf1T,            128, 512 };
    wp.e[6]  = { f1w + 65536,     pf1T + 65536,    128, 512 };
    wp.e[7]  = { f2w,             pf2T,            512, 128 };
    wp.e[8]  = { f2w + 65536,     pf2T + 65536,    512, 128 };
    wp.e[9]  = { lf_w,            plfT,            128, 128 };
    wp.e[10] = { gf_w,            pgfT,            128, 128 };
    wp.e[11] = { ff_w,            pffT,            128, 128 };
    wconv_k<<<dim3(48, 12), 256>>>(wp);

    // local (deformable) branch — fused offsets + gather
    local_k<<<Bn * 128, 256>>>(xt, off_w, off_b, msk_w, msk_b, ploc16);

    // global branch: concat then reduce GEMM (K=256) + fused LN1(block0, shift 0)
    concat_k<<<BL * 64 / 512, 256>>>(xt, hx, pbig16);
    gemm_tc<M_PLAIN_LN><<<dim3(1, 256), 512, GEMM_SMEM>>>(
        pbig16, predT, red_b, nullptr, px, pxw16, n1g, n1b, 128, 256, 0);

    for (int i = 0; i < 2; i++) {
        int shift = i ? 4 : 0;
        gemm_tc<M_PLAIN><<<dim3(3, 256), 512, GEMM_SMEM>>>(
            pxw16, pqkvT + i * 49152, qkvb + i * 384, nullptr,
            nullptr, pbig16, nullptr, nullptr, 384, 128, 0);
        attn5<<<512, 256, ATT_SMEM>>>(pbig16, rp + i * 900, patt16, shift);
        gemm_tc<M_PERMRES_LN><<<dim3(1, 256), 512, GEMM_SMEM>>>(
            patt16, ppwT + i * 16384, pb + i * 128, px,
            px, pxw16, n2g + i * 128, n2b + i * 128, 128, 128, shift);
        gemm_tc<M_GELU><<<dim3(4, 256), 512, GEMM_SMEM>>>(
            pxw16, pf1T + i * 65536, f1b + i * 512, nullptr,
            nullptr, pbig16, nullptr, nullptr, 512, 128, 0);
        if (i == 0) {
            gemm_tc<M_RES_LN><<<dim3(1, 256), 512, GEMM_SMEM>>>(
                pbig16, pf2T, f2b, px,
                px, pxw16, n1g + 128, n1b + 128, 128, 512, 4);
        } else {
            gemm_tc<M_RES><<<dim3(1, 256), 512, GEMM_SMEM>>>(
                pbig16, pf2T + 65536, f2b + 128, px,
                px, px16, nullptr, nullptr, 128, 512, 0);
        }
    }

    // fused fusion + LSTM gate
    fusion_k<<<256, 512, GEMM_SMEM>>>(px16, ploc16, pgfT, plfT, pffT,
                                      gf_b, lf_b, ff_b, cx, (float*)d_out);
}